// round 1
// baseline (speedup 1.0000x reference)
#include <cuda_runtime.h>
#include <cuda_bf16.h>
#include <math.h>

// Problem constants
#define BB    64
#define SS    128
#define EMB_  512
#define ENC2_ 1024
#define ATTN_ 512
#define DECH_ 1024
#define VOCAB_ 32000
#define XK    (EMB_ + ENC2_)          // 1536
#define OUTK  (DECH_ + ENC2_ + EMB_)  // 2560
#define G4    (4 * DECH_)             // 4096

// Output layout: concat(output[64,32000], new_hidden[64,1024], new_cell[64,1024], attn_w[64,128])
#define OFF_OUT 0
#define OFF_NH  (BB * VOCAB_)                 // 2048000
#define OFF_NC  (OFF_NH + BB * DECH_)         // 2113536
#define OFF_AW  (OFF_NC + BB * DECH_)         // 2179072
#define OUT_TOTAL (OFF_AW + BB * SS)          // 2187264

// Scratch (device globals: no allocations allowed)
__device__ __align__(16) float g_enc_proj[(size_t)SS * BB * ATTN_]; // 16.8 MB
__device__ __align__(16) float g_dec_proj[BB * ATTN_];
__device__ __align__(16) float g_xcat[BB * XK];
__device__ __align__(16) float g_outin[BB * OUTK];
__device__ __align__(16) float g_gates[BB * G4];
__device__ __align__(16) float g_aux[BB * DECH_ * 2 + BB * SS];     // fallback sink if out_size is small

// ---------------------------------------------------------------------------
// Embedding gather (padding_idx = 0) -> xcat[:, :512] and out_in[:, 2048:2560]
// ---------------------------------------------------------------------------
__global__ void embed_k(const int* __restrict__ tok, const float* __restrict__ emb)
{
    int b = blockIdx.x;
    int t = tok[b];
    const float* src = emb + (size_t)t * EMB_;
    for (int j = threadIdx.x; j < EMB_; j += blockDim.x) {
        float v = (t == 0) ? 0.f : src[j];
        g_xcat[b * XK + j] = v;
        g_outin[b * OUTK + (DECH_ + ENC2_) + j] = v;
    }
}

// ---------------------------------------------------------------------------
// SGEMM: C[M,N] = A[M,K] * B[N,K]^T (+ C if accumulate) (+ bias[n] if bias)
// Tiles: BM=BN=64, BK=16, 256 threads, 4x4 microtile, float4 smem paths.
// Requires M%64==0 (or M==64), N%64==0, K%16==0, all pointers 16B aligned.
// ---------------------------------------------------------------------------
__global__ void __launch_bounds__(256)
sgemm_tn(const float* __restrict__ A, const float* __restrict__ Bm,
         float* __restrict__ C, int M, int N, int K,
         const float* __restrict__ bias, int accumulate)
{
    const int LDS = 68;  // pad: keeps 16B alignment, reduces store conflicts
    __shared__ float As[16][LDS];
    __shared__ float Bs[16][LDS];

    int tid = threadIdx.x;
    int lr = tid >> 2;            // 0..63 (tile row)
    int lc = (tid & 3) << 2;      // 0,4,8,12 (k group)
    int tx = tid & 15, ty = tid >> 4;

    int bm = blockIdx.y * 64, bn = blockIdx.x * 64;

    const float* Ap = A + (size_t)(bm + lr) * K + lc;
    const float* Bp = Bm + (size_t)(bn + lr) * K + lc;

    float acc[4][4] = {};

    for (int k0 = 0; k0 < K; k0 += 16) {
        float4 av = *(const float4*)(Ap + k0);
        float4 bv = *(const float4*)(Bp + k0);
        As[lc + 0][lr] = av.x; As[lc + 1][lr] = av.y;
        As[lc + 2][lr] = av.z; As[lc + 3][lr] = av.w;
        Bs[lc + 0][lr] = bv.x; Bs[lc + 1][lr] = bv.y;
        Bs[lc + 2][lr] = bv.z; Bs[lc + 3][lr] = bv.w;
        __syncthreads();

        #pragma unroll
        for (int k = 0; k < 16; k++) {
            float4 ra = *(const float4*)&As[k][ty * 4];
            float4 rb = *(const float4*)&Bs[k][tx * 4];
            float a0[4] = {ra.x, ra.y, ra.z, ra.w};
            float b0[4] = {rb.x, rb.y, rb.z, rb.w};
            #pragma unroll
            for (int i = 0; i < 4; i++)
                #pragma unroll
                for (int j = 0; j < 4; j++)
                    acc[i][j] = fmaf(a0[i], b0[j], acc[i][j]);
        }
        __syncthreads();
    }

    float4 bsv = make_float4(0.f, 0.f, 0.f, 0.f);
    if (bias) bsv = *(const float4*)(bias + bn + tx * 4);

    #pragma unroll
    for (int i = 0; i < 4; i++) {
        int m = bm + ty * 4 + i;
        float* cp = C + (size_t)m * N + bn + tx * 4;
        float4 cv = make_float4(acc[i][0] + bsv.x, acc[i][1] + bsv.y,
                                acc[i][2] + bsv.z, acc[i][3] + bsv.w);
        if (accumulate) {
            float4 old = *(const float4*)cp;
            cv.x += old.x; cv.y += old.y; cv.z += old.z; cv.w += old.w;
        }
        *(float4*)cp = cv;
    }
}

// ---------------------------------------------------------------------------
// Fused attention: scores = v . tanh(enc_proj + dec_proj); mask; softmax over S;
// context = sum_s w[s] * enc_out[s,b,:]. One block per b, 256 threads.
// ---------------------------------------------------------------------------
__global__ void __launch_bounds__(256)
attn_k(const float* __restrict__ v, const int* __restrict__ mask,
       const float* __restrict__ enc_out, float* __restrict__ aw_out)
{
    int b = blockIdx.x;
    int tid = threadIdx.x;
    int wid = tid >> 5, lane = tid & 31;

    __shared__ float sc[SS];
    __shared__ float red[8];
    __shared__ float red2[8];

    // scores
    for (int s = wid; s < SS; s += 8) {
        const float* pe = g_enc_proj + ((size_t)(s * BB + b)) * ATTN_;
        const float* pd = g_dec_proj + (size_t)b * ATTN_;
        float sum = 0.f;
        for (int a = lane; a < ATTN_; a += 32)
            sum += tanhf(pe[a] + pd[a]) * v[a];
        #pragma unroll
        for (int o = 16; o; o >>= 1) sum += __shfl_xor_sync(0xffffffffu, sum, o);
        if (lane == 0)
            sc[s] = (mask[b * SS + s] == 0) ? -INFINITY : sum;
    }
    __syncthreads();

    // softmax over 128 (threads >=128 carry -inf / 0)
    float val = (tid < SS) ? sc[tid] : -INFINITY;
    float m = val;
    #pragma unroll
    for (int o = 16; o; o >>= 1) m = fmaxf(m, __shfl_xor_sync(0xffffffffu, m, o));
    if (lane == 0) red[wid] = m;
    __syncthreads();
    if (tid == 0) {
        float mm = red[0];
        #pragma unroll
        for (int i = 1; i < 8; i++) mm = fmaxf(mm, red[i]);
        red[0] = mm;
    }
    __syncthreads();
    float mx = red[0];

    float e = (tid < SS) ? expf(val - mx) : 0.f;
    float ssum = e;
    #pragma unroll
    for (int o = 16; o; o >>= 1) ssum += __shfl_xor_sync(0xffffffffu, ssum, o);
    if (lane == 0) red2[wid] = ssum;
    __syncthreads();
    if (tid == 0) {
        float tot = 0.f;
        #pragma unroll
        for (int i = 0; i < 8; i++) tot += red2[i];
        red2[0] = tot;
    }
    __syncthreads();
    float denom = red2[0];

    if (tid < SS) {
        float w = e / denom;
        sc[tid] = w;
        aw_out[b * SS + tid] = w;
    }
    __syncthreads();

    // context: each thread owns e = tid, tid+256, tid+512, tid+768
    float a0 = 0.f, a1 = 0.f, a2 = 0.f, a3 = 0.f;
    for (int s = 0; s < SS; s++) {
        float w = sc[s];
        const float* pe = enc_out + ((size_t)(s * BB + b)) * ENC2_;
        a0 = fmaf(w, pe[tid + 0],   a0);
        a1 = fmaf(w, pe[tid + 256], a1);
        a2 = fmaf(w, pe[tid + 512], a2);
        a3 = fmaf(w, pe[tid + 768], a3);
    }
    g_xcat[b * XK + EMB_ + tid + 0]   = a0;
    g_xcat[b * XK + EMB_ + tid + 256] = a1;
    g_xcat[b * XK + EMB_ + tid + 512] = a2;
    g_xcat[b * XK + EMB_ + tid + 768] = a3;
    g_outin[b * OUTK + DECH_ + tid + 0]   = a0;
    g_outin[b * OUTK + DECH_ + tid + 256] = a1;
    g_outin[b * OUTK + DECH_ + tid + 512] = a2;
    g_outin[b * OUTK + DECH_ + tid + 768] = a3;
}

// ---------------------------------------------------------------------------
// LSTM pointwise: torch gate order i,f,g,o
// ---------------------------------------------------------------------------
__global__ void __launch_bounds__(1024)
lstm_k(const float* __restrict__ b_ih, const float* __restrict__ b_hh,
       const float* __restrict__ cell,
       float* __restrict__ nh_out, float* __restrict__ nc_out)
{
    int b = blockIdx.x, j = threadIdx.x;
    const float* g = g_gates + (size_t)b * G4;
    float iv = g[j]            + b_ih[j]            + b_hh[j];
    float fv = g[j + DECH_]    + b_ih[j + DECH_]    + b_hh[j + DECH_];
    float gv = g[j + 2*DECH_]  + b_ih[j + 2*DECH_]  + b_hh[j + 2*DECH_];
    float ov = g[j + 3*DECH_]  + b_ih[j + 3*DECH_]  + b_hh[j + 3*DECH_];
    float i_ = 1.f / (1.f + expf(-iv));
    float f_ = 1.f / (1.f + expf(-fv));
    float o_ = 1.f / (1.f + expf(-ov));
    float gt = tanhf(gv);
    float nc = f_ * cell[b * DECH_ + j] + i_ * gt;
    float nh = o_ * tanhf(nc);
    nc_out[b * DECH_ + j] = nc;
    nh_out[b * DECH_ + j] = nh;
    g_outin[b * OUTK + j] = nh;
}

// ---------------------------------------------------------------------------
extern "C" void kernel_launch(void* const* d_in, const int* in_sizes, int n_in,
                              void* d_out, int out_size)
{
    const int*   input_token = (const int*)  d_in[0];
    const float* hidden      = (const float*)d_in[1];
    const float* cell        = (const float*)d_in[2];
    const float* enc_out     = (const float*)d_in[3];
    const int*   mask        = (const int*)  d_in[4];
    const float* embedding   = (const float*)d_in[5];
    const float* W_enc       = (const float*)d_in[6];
    const float* W_dec       = (const float*)d_in[7];
    const float* v_attn      = (const float*)d_in[8];
    const float* W_ih        = (const float*)d_in[9];
    const float* W_hh        = (const float*)d_in[10];
    const float* b_ih        = (const float*)d_in[11];
    const float* b_hh        = (const float*)d_in[12];
    const float* W_out       = (const float*)d_in[13];
    const float* b_out       = (const float*)d_in[14];

    float* out = (float*)d_out;

    // Scratch symbol addresses (capture-safe; no allocation)
    void *p_encp, *p_decp, *p_xcat, *p_outin, *p_gates, *p_aux;
    cudaGetSymbolAddress(&p_encp,  g_enc_proj);
    cudaGetSymbolAddress(&p_decp,  g_dec_proj);
    cudaGetSymbolAddress(&p_xcat,  g_xcat);
    cudaGetSymbolAddress(&p_outin, g_outin);
    cudaGetSymbolAddress(&p_gates, g_gates);
    cudaGetSymbolAddress(&p_aux,   g_aux);

    // If the harness buffer only holds the primary output, sink aux outputs to scratch.
    bool full = (out_size >= OUT_TOTAL);
    float* nh_dst = full ? out + OFF_NH : (float*)p_aux;
    float* nc_dst = full ? out + OFF_NC : (float*)p_aux + BB * DECH_;
    float* aw_dst = full ? out + OFF_AW : (float*)p_aux + 2 * BB * DECH_;

    // 1) embedding gather
    embed_k<<<BB, 128>>>(input_token, embedding);

    // 2) enc_proj[SB, ATTN] = enc_out[SB, ENC2] @ W_enc^T
    sgemm_tn<<<dim3(ATTN_ / 64, (SS * BB) / 64), 256>>>(
        enc_out, W_enc, (float*)p_encp, SS * BB, ATTN_, ENC2_, nullptr, 0);

    // 3) dec_proj[B, ATTN] = hidden @ W_dec^T
    sgemm_tn<<<dim3(ATTN_ / 64, 1), 256>>>(
        hidden, W_dec, (float*)p_decp, BB, ATTN_, DECH_, nullptr, 0);

    // 4) attention: scores -> softmax -> context (+ attn_w out)
    attn_k<<<BB, 256>>>(v_attn, mask, enc_out, aw_dst);

    // 5) gates = xcat @ W_ih^T
    sgemm_tn<<<dim3(G4 / 64, 1), 256>>>(
        (const float*)p_xcat, W_ih, (float*)p_gates, BB, G4, XK, nullptr, 0);

    // 6) gates += hidden @ W_hh^T
    sgemm_tn<<<dim3(G4 / 64, 1), 256>>>(
        hidden, W_hh, (float*)p_gates, BB, G4, DECH_, nullptr, 1);

    // 7) LSTM pointwise
    lstm_k<<<BB, DECH_>>>(b_ih, b_hh, cell, nh_dst, nc_dst);

    // 8) output = out_in @ W_out^T + b_out
    sgemm_tn<<<dim3(VOCAB_ / 64, 1), 256>>>(
        (const float*)p_outin, W_out, out + OFF_OUT, BB, VOCAB_, OUTK, b_out, 0);
}

// round 3
// speedup vs baseline: 1.6525x; 1.6525x over previous
#include <cuda_runtime.h>
#include <cuda_bf16.h>
#include <math.h>
#include <stdint.h>

// Problem constants
#define BB    64
#define SS    128
#define EMB_  512
#define ENC2_ 1024
#define ATTN_ 512
#define DECH_ 1024
#define VOCAB_ 32000
#define XKC   2560                     // [emb|ctx|hidden] concat K for gates
#define OUTK  2560                     // [nh|ctx|emb] concat K for output
#define G4    (4 * DECH_)              // 4096

// Output layout: concat(output[64,32000], new_hidden, new_cell, attn_w)
#define OFF_OUT 0
#define OFF_NH  (BB * VOCAB_)
#define OFF_NC  (OFF_NH + BB * DECH_)
#define OFF_AW  (OFF_NC + BB * DECH_)
#define OUT_TOTAL (OFF_AW + BB * SS)

// Scratch
__device__ __align__(16) float g_decp[BB * ATTN_];
__device__ __align__(16) float g_scores[BB * SS];
__device__ __align__(16) float g_xbuf[BB * XKC];   // [emb(512)|ctx(1024)|hidden(1024)]
__device__ __align__(16) float g_obuf[BB * OUTK];  // [nh(1024)|ctx(1024)|emb(512)]
__device__ __align__(16) float g_gates[BB * G4];
__device__ __align__(16) float g_aux[BB * DECH_ * 2 + BB * SS];

// ---------------------------------------------------------------------------
// Embedding gather + hidden copy + scores zero
// ---------------------------------------------------------------------------
__global__ void __launch_bounds__(256)
embed_copy_k(const int* __restrict__ tok, const float* __restrict__ emb,
             const float* __restrict__ hidden)
{
    int b = blockIdx.x, tid = threadIdx.x;
    int t = tok[b];
    const float* src = emb + (size_t)t * EMB_;
    for (int j = tid; j < EMB_; j += 256) {
        float v = (t == 0) ? 0.f : src[j];
        g_xbuf[b * XKC + j] = v;
        g_obuf[b * OUTK + (DECH_ + ENC2_) + j] = v;
    }
    for (int j = tid; j < DECH_; j += 256)
        g_xbuf[b * XKC + (EMB_ + ENC2_) + j] = hidden[b * DECH_ + j];
    if (tid < SS) g_scores[b * SS + tid] = 0.f;
}

// ---------------------------------------------------------------------------
// bf16 split-GEMM: C[M,N] = A[M,K] @ B[N,K]^T (+bias), computed as
//   Ah*Bh + Ah*Bl + Al*Bh with bf16 hi/lo split done in the SMEM loader.
// BM=64, BN=128, BK=32, 256 threads, 8 warps in 2(m)x4(n), warp tile 32x32.
// EPI=0: write C (+bias).  EPI=1: attention score epilogue (no C write):
//   scores[b,s] += sum_n tanh(c + decp[b,n]) * v[n]   (atomic partial)
// B can be a concat of two matrices along K (ksplit boundary).
// ---------------------------------------------------------------------------
#define BKK 32
#define LDK 40   // padded row length (bf16 elems): conflict-free frag loads

#define MMA16816(c, a, b) \
    asm volatile("mma.sync.aligned.m16n8k16.row.col.f32.bf16.bf16.f32 " \
        "{%0,%1,%2,%3},{%4,%5,%6,%7},{%8,%9},{%0,%1,%2,%3};" \
        : "+f"(c[0]), "+f"(c[1]), "+f"(c[2]), "+f"(c[3]) \
        : "r"(a[0]), "r"(a[1]), "r"(a[2]), "r"(a[3]), "r"(b[0]), "r"(b[1]))

__device__ __forceinline__ void cvt_split4(__nv_bfloat16* ph, __nv_bfloat16* pl, float4 v)
{
    float xs[4] = {v.x, v.y, v.z, v.w};
    #pragma unroll
    for (int i = 0; i < 4; i++) {
        __nv_bfloat16 h = __float2bfloat16_rn(xs[i]);
        float r = xs[i] - __bfloat162float(h);
        ph[i] = h;
        pl[i] = __float2bfloat16_rn(r);
    }
}

template<int EPI>
__global__ void __launch_bounds__(256)
gemm_k(const float* __restrict__ A, int lda,
       const float* __restrict__ B1, int ldb1, int ksplit,
       const float* __restrict__ B2, int ldb2,
       float* __restrict__ C, int N, int K,
       const float* __restrict__ bias,
       const float* __restrict__ decp,
       const float* __restrict__ vat)
{
    __shared__ __nv_bfloat16 Ah[64][LDK], Al[64][LDK];
    __shared__ __nv_bfloat16 Bh[128][LDK], Bl[128][LDK];

    int tid = threadIdx.x;
    int wid = tid >> 5, lane = tid & 31;
    int g = lane >> 2, tig = lane & 3;
    int wm = wid >> 2, wn = wid & 3;
    int bm = blockIdx.y * 64, bn = blockIdx.x * 128;

    int lrow = tid >> 3;   // 0..31
    int lkq  = tid & 7;    // float4 slot within BK=32

    float4 pa0, pa1, pb[4];
    int nk = K / BKK;

    // prefetch kt = 0
    {
        int gk = lkq * 4;
        pa0 = *(const float4*)(A + (size_t)(bm + lrow) * lda + gk);
        pa1 = *(const float4*)(A + (size_t)(bm + lrow + 32) * lda + gk);
        #pragma unroll
        for (int r = 0; r < 4; r++) {
            int n = bn + lrow + r * 32;
            const float* Bp = (gk < ksplit)
                ? (B1 + (size_t)n * ldb1 + gk)
                : (B2 + (size_t)n * ldb2 + (gk - ksplit));
            pb[r] = *(const float4*)Bp;
        }
    }

    float acc[2][4][4];
    #pragma unroll
    for (int mt = 0; mt < 2; mt++)
        #pragma unroll
        for (int nt = 0; nt < 4; nt++)
            #pragma unroll
            for (int q = 0; q < 4; q++) acc[mt][nt][q] = 0.f;

    for (int kt = 0; kt < nk; kt++) {
        // store prefetched tile (convert to hi/lo)
        cvt_split4(&Ah[lrow][lkq * 4],      &Al[lrow][lkq * 4],      pa0);
        cvt_split4(&Ah[lrow + 32][lkq * 4], &Al[lrow + 32][lkq * 4], pa1);
        #pragma unroll
        for (int r = 0; r < 4; r++)
            cvt_split4(&Bh[lrow + r * 32][lkq * 4], &Bl[lrow + r * 32][lkq * 4], pb[r]);
        __syncthreads();

        // prefetch next tile (loads in flight during MMAs below)
        if (kt + 1 < nk) {
            int gk = (kt + 1) * BKK + lkq * 4;
            pa0 = *(const float4*)(A + (size_t)(bm + lrow) * lda + gk);
            pa1 = *(const float4*)(A + (size_t)(bm + lrow + 32) * lda + gk);
            #pragma unroll
            for (int r = 0; r < 4; r++) {
                int n = bn + lrow + r * 32;
                const float* Bp = (gk < ksplit)
                    ? (B1 + (size_t)n * ldb1 + gk)
                    : (B2 + (size_t)n * ldb2 + (gk - ksplit));
                pb[r] = *(const float4*)Bp;
            }
        }

        #pragma unroll
        for (int ks = 0; ks < 2; ks++) {
            int ko = ks * 16 + tig * 2;
            uint32_t ah[2][4], al[2][4], bh[4][2], bl[4][2];
            #pragma unroll
            for (int mt = 0; mt < 2; mt++) {
                int r = wm * 32 + mt * 16;
                ah[mt][0] = *(const uint32_t*)&Ah[r + g][ko];
                ah[mt][1] = *(const uint32_t*)&Ah[r + g + 8][ko];
                ah[mt][2] = *(const uint32_t*)&Ah[r + g][ko + 8];
                ah[mt][3] = *(const uint32_t*)&Ah[r + g + 8][ko + 8];
                al[mt][0] = *(const uint32_t*)&Al[r + g][ko];
                al[mt][1] = *(const uint32_t*)&Al[r + g + 8][ko];
                al[mt][2] = *(const uint32_t*)&Al[r + g][ko + 8];
                al[mt][3] = *(const uint32_t*)&Al[r + g + 8][ko + 8];
            }
            #pragma unroll
            for (int nt = 0; nt < 4; nt++) {
                int n = wn * 32 + nt * 8 + g;
                bh[nt][0] = *(const uint32_t*)&Bh[n][ko];
                bh[nt][1] = *(const uint32_t*)&Bh[n][ko + 8];
                bl[nt][0] = *(const uint32_t*)&Bl[n][ko];
                bl[nt][1] = *(const uint32_t*)&Bl[n][ko + 8];
            }
            #pragma unroll
            for (int mt = 0; mt < 2; mt++)
                #pragma unroll
                for (int nt = 0; nt < 4; nt++) {
                    MMA16816(acc[mt][nt], ah[mt], bh[nt]);
                    MMA16816(acc[mt][nt], ah[mt], bl[nt]);
                    MMA16816(acc[mt][nt], al[mt], bh[nt]);
                }
        }
        __syncthreads();
    }

    if (EPI == 0) {
        #pragma unroll
        for (int mt = 0; mt < 2; mt++) {
            int gm = bm + wm * 32 + mt * 16 + g;
            #pragma unroll
            for (int nt = 0; nt < 4; nt++) {
                int gn = bn + wn * 32 + nt * 8 + tig * 2;
                float b0 = bias ? bias[gn] : 0.f;
                float b1 = bias ? bias[gn + 1] : 0.f;
                float2 v0 = make_float2(acc[mt][nt][0] + b0, acc[mt][nt][1] + b1);
                float2 v1 = make_float2(acc[mt][nt][2] + b0, acc[mt][nt][3] + b1);
                *(float2*)(C + (size_t)gm * N + gn) = v0;
                *(float2*)(C + (size_t)(gm + 8) * N + gn) = v1;
            }
        }
    } else {
        // attention score epilogue: rows are (s*64 + b).
        // NOTE: acc[..][2],acc[..][3] belong to row gm+8 -> batch (gm+8)&63.
        #pragma unroll
        for (int mt = 0; mt < 2; mt++) {
            int gm = bm + wm * 32 + mt * 16 + g;
            int bA = gm & 63;
            int bB = (gm + 8) & 63;
            float p0 = 0.f, p8 = 0.f;
            #pragma unroll
            for (int nt = 0; nt < 4; nt++) {
                int gn = bn + wn * 32 + nt * 8 + tig * 2;
                float d0a = decp[bA * ATTN_ + gn], d1a = decp[bA * ATTN_ + gn + 1];
                float d0b = decp[bB * ATTN_ + gn], d1b = decp[bB * ATTN_ + gn + 1];
                float v0 = vat[gn], v1 = vat[gn + 1];
                p0 += tanhf(acc[mt][nt][0] + d0a) * v0 + tanhf(acc[mt][nt][1] + d1a) * v1;
                p8 += tanhf(acc[mt][nt][2] + d0b) * v0 + tanhf(acc[mt][nt][3] + d1b) * v1;
            }
            p0 += __shfl_xor_sync(0xffffffffu, p0, 1);
            p0 += __shfl_xor_sync(0xffffffffu, p0, 2);
            p8 += __shfl_xor_sync(0xffffffffu, p8, 1);
            p8 += __shfl_xor_sync(0xffffffffu, p8, 2);
            if (tig == 0) {
                atomicAdd(&g_scores[bA * SS + (gm >> 6)], p0);
                int gm8 = gm + 8;
                atomicAdd(&g_scores[bB * SS + (gm8 >> 6)], p8);
            }
        }
    }
}

// ---------------------------------------------------------------------------
// softmax (per b over S) + context (float4 over ENC2) fused
// ---------------------------------------------------------------------------
__global__ void __launch_bounds__(256)
smctx_k(const int* __restrict__ mask, const float* __restrict__ enc_out,
        float* __restrict__ aw_dst)
{
    int b = blockIdx.x, tid = threadIdx.x;
    int wid = tid >> 5, lane = tid & 31;

    __shared__ float w[SS];
    __shared__ float red[8];

    float val = -INFINITY;
    if (tid < SS)
        val = (mask[b * SS + tid] == 0) ? -INFINITY : g_scores[b * SS + tid];

    float m = val;
    #pragma unroll
    for (int o = 16; o; o >>= 1) m = fmaxf(m, __shfl_xor_sync(0xffffffffu, m, o));
    if (lane == 0) red[wid] = m;
    __syncthreads();
    if (tid == 0) {
        float mm = red[0];
        #pragma unroll
        for (int i = 1; i < 8; i++) mm = fmaxf(mm, red[i]);
        red[0] = mm;
    }
    __syncthreads();
    float mx = red[0];
    __syncthreads();

    float e = (tid < SS) ? __expf(val - mx) : 0.f;
    float ssum = e;
    #pragma unroll
    for (int o = 16; o; o >>= 1) ssum += __shfl_xor_sync(0xffffffffu, ssum, o);
    if (lane == 0) red[wid] = ssum;
    __syncthreads();
    if (tid == 0) {
        float tot = 0.f;
        #pragma unroll
        for (int i = 0; i < 8; i++) tot += red[i];
        red[0] = tot;
    }
    __syncthreads();
    float denom = red[0];

    if (tid < SS) {
        float ww = e / denom;
        w[tid] = ww;
        aw_dst[b * SS + tid] = ww;
    }
    __syncthreads();

    // context: 256 threads x float4 = 1024 elems
    const float* base = enc_out + (size_t)b * ENC2_ + tid * 4;
    float4 a = make_float4(0.f, 0.f, 0.f, 0.f);
    #pragma unroll 8
    for (int s = 0; s < SS; s++) {
        float ws = w[s];
        float4 v = *(const float4*)(base + (size_t)s * BB * ENC2_);
        a.x = fmaf(ws, v.x, a.x); a.y = fmaf(ws, v.y, a.y);
        a.z = fmaf(ws, v.z, a.z); a.w = fmaf(ws, v.w, a.w);
    }
    *(float4*)(&g_xbuf[b * XKC + EMB_ + tid * 4]) = a;
    *(float4*)(&g_obuf[b * OUTK + DECH_ + tid * 4]) = a;
}

// ---------------------------------------------------------------------------
// LSTM pointwise (torch gate order i,f,g,o)
// ---------------------------------------------------------------------------
__global__ void __launch_bounds__(1024)
lstm_k(const float* __restrict__ b_ih, const float* __restrict__ b_hh,
       const float* __restrict__ cell,
       float* __restrict__ nh_out, float* __restrict__ nc_out)
{
    int b = blockIdx.x, j = threadIdx.x;
    const float* gg = g_gates + (size_t)b * G4;
    float iv = gg[j]             + b_ih[j]             + b_hh[j];
    float fv = gg[j + DECH_]     + b_ih[j + DECH_]     + b_hh[j + DECH_];
    float gv = gg[j + 2 * DECH_] + b_ih[j + 2 * DECH_] + b_hh[j + 2 * DECH_];
    float ov = gg[j + 3 * DECH_] + b_ih[j + 3 * DECH_] + b_hh[j + 3 * DECH_];
    float i_ = 1.f / (1.f + __expf(-iv));
    float f_ = 1.f / (1.f + __expf(-fv));
    float o_ = 1.f / (1.f + __expf(-ov));
    float gt = tanhf(gv);
    float nc = f_ * cell[b * DECH_ + j] + i_ * gt;
    float nh = o_ * tanhf(nc);
    nc_out[b * DECH_ + j] = nc;
    nh_out[b * DECH_ + j] = nh;
    g_obuf[b * OUTK + j] = nh;
}

// ---------------------------------------------------------------------------
extern "C" void kernel_launch(void* const* d_in, const int* in_sizes, int n_in,
                              void* d_out, int out_size)
{
    const int*   input_token = (const int*)  d_in[0];
    const float* hidden      = (const float*)d_in[1];
    const float* cell        = (const float*)d_in[2];
    const float* enc_out     = (const float*)d_in[3];
    const int*   mask        = (const int*)  d_in[4];
    const float* embedding   = (const float*)d_in[5];
    const float* W_enc       = (const float*)d_in[6];
    const float* W_dec       = (const float*)d_in[7];
    const float* v_attn      = (const float*)d_in[8];
    const float* W_ih        = (const float*)d_in[9];
    const float* W_hh        = (const float*)d_in[10];
    const float* b_ih        = (const float*)d_in[11];
    const float* b_hh        = (const float*)d_in[12];
    const float* W_out       = (const float*)d_in[13];
    const float* b_out       = (const float*)d_in[14];

    float* out = (float*)d_out;

    void *p_decp, *p_xbuf, *p_obuf, *p_gates, *p_aux;
    cudaGetSymbolAddress(&p_decp,  g_decp);
    cudaGetSymbolAddress(&p_xbuf,  g_xbuf);
    cudaGetSymbolAddress(&p_obuf,  g_obuf);
    cudaGetSymbolAddress(&p_gates, g_gates);
    cudaGetSymbolAddress(&p_aux,   g_aux);

    bool full = (out_size >= OUT_TOTAL);
    float* nh_dst = full ? out + OFF_NH : (float*)p_aux;
    float* nc_dst = full ? out + OFF_NC : (float*)p_aux + BB * DECH_;
    float* aw_dst = full ? out + OFF_AW : (float*)p_aux + 2 * BB * DECH_;

    // 1) embedding + hidden copy + scores zero
    embed_copy_k<<<BB, 256>>>(input_token, embedding, hidden);

    // 2) dec_proj[64,512] = hidden @ W_dec^T
    gemm_k<0><<<dim3(ATTN_ / 128, 1), 256>>>(
        hidden, DECH_, W_dec, DECH_, DECH_, W_dec, DECH_,
        (float*)p_decp, ATTN_, DECH_, nullptr, nullptr, nullptr);

    // 3) enc_proj GEMM fused with score reduction (no C materialization)
    gemm_k<1><<<dim3(ATTN_ / 128, (SS * BB) / 64), 256>>>(
        enc_out, ENC2_, W_enc, ENC2_, ENC2_, W_enc, ENC2_,
        nullptr, ATTN_, ENC2_, nullptr, (const float*)p_decp, v_attn);

    // 4) softmax + context
    smctx_k<<<BB, 256>>>(mask, enc_out, aw_dst);

    // 5) gates[64,4096] = [emb|ctx] @ W_ih^T + hidden @ W_hh^T  (concat K=2560)
    gemm_k<0><<<dim3(G4 / 128, 1), 256>>>(
        (const float*)p_xbuf, XKC, W_ih, EMB_ + ENC2_, EMB_ + ENC2_, W_hh, DECH_,
        (float*)p_gates, G4, XKC, nullptr, nullptr, nullptr);

    // 6) LSTM pointwise
    lstm_k<<<BB, DECH_>>>(b_ih, b_hh, cell, nh_dst, nc_dst);

    // 7) output[64,32000] = [nh|ctx|emb] @ W_out^T + b_out
    gemm_k<0><<<dim3(VOCAB_ / 128, 1), 256>>>(
        (const float*)p_obuf, OUTK, W_out, OUTK, OUTK, W_out, OUTK,
        out + OFF_OUT, VOCAB_, OUTK, b_out, nullptr, nullptr);
}

// round 5
// speedup vs baseline: 3.0383x; 1.8386x over previous
#include <cuda_runtime.h>
#include <cuda_bf16.h>
#include <math.h>
#include <stdint.h>

// ---------------------------------------------------------------- constants
#define BB    64
#define SS    128
#define EMB_  512
#define ENC2_ 1024
#define ATTN_ 512
#define DECH_ 1024
#define VOCAB_ 32000
#define XKC   2560
#define OUTK  2560
#define G4    (4 * DECH_)

#define OFF_OUT 0
#define OFF_NH  (BB * VOCAB_)
#define OFF_NC  (OFF_NH + BB * DECH_)
#define OFF_AW  (OFF_NC + BB * DECH_)
#define OUT_TOTAL (OFF_AW + BB * SS)

// scratch (no allocations allowed)
__device__ __align__(16) float g_decp[BB * ATTN_];
__device__ __align__(16) float g_scores[BB * SS];
__device__ __align__(16) float g_xbuf[BB * XKC];   // [emb|ctx|hidden]
__device__ __align__(16) float g_obuf[BB * OUTK];  // [nh|ctx|emb]
__device__ __align__(16) float g_gates[BB * G4];
__device__ __align__(16) float g_aux[BB * DECH_ * 2 + BB * SS];

// ---------------------------------------------------------------- helpers
#define MMA16816(c, a, b) \
    asm volatile("mma.sync.aligned.m16n8k16.row.col.f32.bf16.bf16.f32 " \
        "{%0,%1,%2,%3},{%4,%5,%6,%7},{%8,%9},{%0,%1,%2,%3};" \
        : "+f"(c[0]), "+f"(c[1]), "+f"(c[2]), "+f"(c[3]) \
        : "r"(a[0]), "r"(a[1]), "r"(a[2]), "r"(a[3]), "r"(b[0]), "r"(b[1]))

__device__ __forceinline__ void split4(float4 v, uint2& h, uint2& l)
{
    __nv_bfloat162 h01 = __floats2bfloat162_rn(v.x, v.y);
    __nv_bfloat162 h23 = __floats2bfloat162_rn(v.z, v.w);
    float2 f01 = __bfloat1622float2(h01);
    float2 f23 = __bfloat1622float2(h23);
    __nv_bfloat162 l01 = __floats2bfloat162_rn(v.x - f01.x, v.y - f01.y);
    __nv_bfloat162 l23 = __floats2bfloat162_rn(v.z - f23.x, v.w - f23.y);
    h.x = *(uint32_t*)&h01; h.y = *(uint32_t*)&h23;
    l.x = *(uint32_t*)&l01; l.y = *(uint32_t*)&l23;
}

// ---------------------------------------------------------------- GEMM
// C[M,N] (M%64==0 tiles of 64) = A[M,K] @ concatK(B1,B2)[N,K]^T (+bias)
// 3-product bf16 split (Ah*Bh + Ah*Bl + Al*Bh), fp32 accum.
// BM=64, BN=128, BK=32, 256 thr, 8 warps 2(m)x4(n), warp tile 32x32.
// Split-K via blockIdx.z (kslice elems each); ATOM=1 -> atomicAdd epilogue.
// EPI=1: Bahdanau score epilogue (atomicAdd partial tanh-dot into g_scores).
#define BKK 32
#define LDK 40
#define STAGE_A  0
#define STAGE_AL 2560
#define STAGE_B  5120
#define STAGE_BL 10240
#define STAGE_SZ 15360          // bf16 elems per stage
#define SMEM_BYTES (2 * STAGE_SZ * 2)  // 61440

template<int EPI, int ATOM>
__global__ void __launch_bounds__(256, 2)
gemm_k(const float* __restrict__ A, int lda,
       const float* __restrict__ B1, int ldb1, int ksplit,
       const float* __restrict__ B2, int ldb2,
       float* __restrict__ C, int N, int kslice,
       const float* __restrict__ bias,
       const float* __restrict__ decp,
       const float* __restrict__ vat)
{
    extern __shared__ __nv_bfloat16 sm[];

    const int tid = threadIdx.x;
    const int wid = tid >> 5, lane = tid & 31;
    const int g = lane >> 2, tig = lane & 3;
    const int wm = wid >> 2, wn = wid & 3;
    const int bm = blockIdx.y * 64, bn = blockIdx.x * 128;
    const int k0 = blockIdx.z * kslice;
    const int nk = kslice / BKK;

    const int lrow = tid >> 3;   // 0..31
    const int lkq  = tid & 7;    // float4 slot in BK=32

    float4 pa0, pa1, pb[4];

    // prefetch kt=0
    {
        const int gk = k0 + lkq * 4;
        pa0 = *(const float4*)(A + (size_t)(bm + lrow) * lda + gk);
        pa1 = *(const float4*)(A + (size_t)(bm + lrow + 32) * lda + gk);
        #pragma unroll
        for (int r = 0; r < 4; r++) {
            const int n = bn + lrow + r * 32;
            const float* Bp = (gk < ksplit)
                ? (B1 + (size_t)n * ldb1 + gk)
                : (B2 + (size_t)n * ldb2 + (gk - ksplit));
            pb[r] = *(const float4*)Bp;
        }
    }
    // store stage 0
    {
        __nv_bfloat16* st = sm;
        uint2 h, l;
        split4(pa0, h, l);
        *(uint2*)&st[STAGE_A  + lrow * LDK + lkq * 4] = h;
        *(uint2*)&st[STAGE_AL + lrow * LDK + lkq * 4] = l;
        split4(pa1, h, l);
        *(uint2*)&st[STAGE_A  + (lrow + 32) * LDK + lkq * 4] = h;
        *(uint2*)&st[STAGE_AL + (lrow + 32) * LDK + lkq * 4] = l;
        #pragma unroll
        for (int r = 0; r < 4; r++) {
            split4(pb[r], h, l);
            *(uint2*)&st[STAGE_B  + (lrow + r * 32) * LDK + lkq * 4] = h;
            *(uint2*)&st[STAGE_BL + (lrow + r * 32) * LDK + lkq * 4] = l;
        }
    }
    __syncthreads();

    float acc[2][4][4];
    #pragma unroll
    for (int mt = 0; mt < 2; mt++)
        #pragma unroll
        for (int nt = 0; nt < 4; nt++)
            #pragma unroll
            for (int q = 0; q < 4; q++) acc[mt][nt][q] = 0.f;

    for (int kt = 0; kt < nk; kt++) {
        const __nv_bfloat16* cur = sm + (kt & 1) * STAGE_SZ;
        __nv_bfloat16* nxt = sm + ((kt + 1) & 1) * STAGE_SZ;

        // LDG for kt+1 (in flight during MMAs)
        if (kt + 1 < nk) {
            const int gk = k0 + (kt + 1) * BKK + lkq * 4;
            pa0 = *(const float4*)(A + (size_t)(bm + lrow) * lda + gk);
            pa1 = *(const float4*)(A + (size_t)(bm + lrow + 32) * lda + gk);
            #pragma unroll
            for (int r = 0; r < 4; r++) {
                const int n = bn + lrow + r * 32;
                const float* Bp = (gk < ksplit)
                    ? (B1 + (size_t)n * ldb1 + gk)
                    : (B2 + (size_t)n * ldb2 + (gk - ksplit));
                pb[r] = *(const float4*)Bp;
            }
        }

        // MMAs on current stage
        #pragma unroll
        for (int ks = 0; ks < 2; ks++) {
            const int ko = ks * 16 + tig * 2;
            uint32_t ah[2][4], al[2][4], bh[4][2], bl[4][2];
            #pragma unroll
            for (int mt = 0; mt < 2; mt++) {
                const int r = wm * 32 + mt * 16;
                ah[mt][0] = *(const uint32_t*)&cur[STAGE_A + (r + g) * LDK + ko];
                ah[mt][1] = *(const uint32_t*)&cur[STAGE_A + (r + g + 8) * LDK + ko];
                ah[mt][2] = *(const uint32_t*)&cur[STAGE_A + (r + g) * LDK + ko + 8];
                ah[mt][3] = *(const uint32_t*)&cur[STAGE_A + (r + g + 8) * LDK + ko + 8];
                al[mt][0] = *(const uint32_t*)&cur[STAGE_AL + (r + g) * LDK + ko];
                al[mt][1] = *(const uint32_t*)&cur[STAGE_AL + (r + g + 8) * LDK + ko];
                al[mt][2] = *(const uint32_t*)&cur[STAGE_AL + (r + g) * LDK + ko + 8];
                al[mt][3] = *(const uint32_t*)&cur[STAGE_AL + (r + g + 8) * LDK + ko + 8];
            }
            #pragma unroll
            for (int nt = 0; nt < 4; nt++) {
                const int n = wn * 32 + nt * 8 + g;
                bh[nt][0] = *(const uint32_t*)&cur[STAGE_B + n * LDK + ko];
                bh[nt][1] = *(const uint32_t*)&cur[STAGE_B + n * LDK + ko + 8];
                bl[nt][0] = *(const uint32_t*)&cur[STAGE_BL + n * LDK + ko];
                bl[nt][1] = *(const uint32_t*)&cur[STAGE_BL + n * LDK + ko + 8];
            }
            #pragma unroll
            for (int mt = 0; mt < 2; mt++)
                #pragma unroll
                for (int nt = 0; nt < 4; nt++) {
                    MMA16816(acc[mt][nt], ah[mt], bh[nt]);
                    MMA16816(acc[mt][nt], ah[mt], bl[nt]);
                    MMA16816(acc[mt][nt], al[mt], bh[nt]);
                }
        }

        // convert + STS into other stage
        if (kt + 1 < nk) {
            uint2 h, l;
            split4(pa0, h, l);
            *(uint2*)&nxt[STAGE_A  + lrow * LDK + lkq * 4] = h;
            *(uint2*)&nxt[STAGE_AL + lrow * LDK + lkq * 4] = l;
            split4(pa1, h, l);
            *(uint2*)&nxt[STAGE_A  + (lrow + 32) * LDK + lkq * 4] = h;
            *(uint2*)&nxt[STAGE_AL + (lrow + 32) * LDK + lkq * 4] = l;
            #pragma unroll
            for (int r = 0; r < 4; r++) {
                split4(pb[r], h, l);
                *(uint2*)&nxt[STAGE_B  + (lrow + r * 32) * LDK + lkq * 4] = h;
                *(uint2*)&nxt[STAGE_BL + (lrow + r * 32) * LDK + lkq * 4] = l;
            }
        }
        __syncthreads();
    }

    if (EPI == 0) {
        #pragma unroll
        for (int mt = 0; mt < 2; mt++) {
            const int gm = bm + wm * 32 + mt * 16 + g;
            #pragma unroll
            for (int nt = 0; nt < 4; nt++) {
                const int gn = bn + wn * 32 + nt * 8 + tig * 2;
                if (ATOM) {
                    atomicAdd(C + (size_t)gm * N + gn,       acc[mt][nt][0]);
                    atomicAdd(C + (size_t)gm * N + gn + 1,   acc[mt][nt][1]);
                    atomicAdd(C + (size_t)(gm + 8) * N + gn,     acc[mt][nt][2]);
                    atomicAdd(C + (size_t)(gm + 8) * N + gn + 1, acc[mt][nt][3]);
                } else {
                    const float b0 = bias ? bias[gn] : 0.f;
                    const float b1 = bias ? bias[gn + 1] : 0.f;
                    *(float2*)(C + (size_t)gm * N + gn) =
                        make_float2(acc[mt][nt][0] + b0, acc[mt][nt][1] + b1);
                    *(float2*)(C + (size_t)(gm + 8) * N + gn) =
                        make_float2(acc[mt][nt][2] + b0, acc[mt][nt][3] + b1);
                }
            }
        }
    } else {
        // score epilogue: row gm -> (b = gm&63, s = gm>>6); c2/c3 are row gm+8
        #pragma unroll
        for (int mt = 0; mt < 2; mt++) {
            const int gm = bm + wm * 32 + mt * 16 + g;
            const int bA = gm & 63;
            const int bBt = (gm + 8) & 63;
            float p0 = 0.f, p8 = 0.f;
            #pragma unroll
            for (int nt = 0; nt < 4; nt++) {
                const int gn = bn + wn * 32 + nt * 8 + tig * 2;
                const float d0a = decp[bA * ATTN_ + gn],  d1a = decp[bA * ATTN_ + gn + 1];
                const float d0b = decp[bBt * ATTN_ + gn], d1b = decp[bBt * ATTN_ + gn + 1];
                const float v0 = vat[gn], v1 = vat[gn + 1];
                p0 += tanhf(acc[mt][nt][0] + d0a) * v0 + tanhf(acc[mt][nt][1] + d1a) * v1;
                p8 += tanhf(acc[mt][nt][2] + d0b) * v0 + tanhf(acc[mt][nt][3] + d1b) * v1;
            }
            p0 += __shfl_xor_sync(0xffffffffu, p0, 1);
            p0 += __shfl_xor_sync(0xffffffffu, p0, 2);
            p8 += __shfl_xor_sync(0xffffffffu, p8, 1);
            p8 += __shfl_xor_sync(0xffffffffu, p8, 2);
            if (tig == 0) {
                atomicAdd(&g_scores[bA * SS + (gm >> 6)], p0);
                atomicAdd(&g_scores[bBt * SS + ((gm + 8) >> 6)], p8);
            }
        }
    }
}

// ---------------------------------------------------------------- embed etc.
__global__ void __launch_bounds__(256)
embed_copy_k(const int* __restrict__ tok, const float* __restrict__ emb,
             const float* __restrict__ hidden)
{
    int b = blockIdx.x, tid = threadIdx.x;
    int t = tok[b];
    const float* src = emb + (size_t)t * EMB_;
    for (int j = tid; j < EMB_; j += 256) {
        float v = (t == 0) ? 0.f : src[j];
        g_xbuf[b * XKC + j] = v;
        g_obuf[b * OUTK + (DECH_ + ENC2_) + j] = v;
    }
    for (int j = tid; j < DECH_; j += 256)
        g_xbuf[b * XKC + (EMB_ + ENC2_) + j] = hidden[b * DECH_ + j];
    if (tid < SS) g_scores[b * SS + tid] = 0.f;
}

// softmax + context; grid (2 col-halves, 64 b), 128 threads
__global__ void __launch_bounds__(128)
smctx_k(const int* __restrict__ mask, const float* __restrict__ enc_out,
        float* __restrict__ aw_dst)
{
    int b = blockIdx.y, half = blockIdx.x, tid = threadIdx.x;
    int wid = tid >> 5, lane = tid & 31;
    __shared__ float w[SS];
    __shared__ float red[4];

    float val = (mask[b * SS + tid] == 0) ? -INFINITY : g_scores[b * SS + tid];
    float m = val;
    #pragma unroll
    for (int o = 16; o; o >>= 1) m = fmaxf(m, __shfl_xor_sync(0xffffffffu, m, o));
    if (lane == 0) red[wid] = m;
    __syncthreads();
    if (tid == 0) red[0] = fmaxf(fmaxf(red[0], red[1]), fmaxf(red[2], red[3]));
    __syncthreads();
    float mx = red[0];
    __syncthreads();

    float e = __expf(val - mx);
    float ssum = e;
    #pragma unroll
    for (int o = 16; o; o >>= 1) ssum += __shfl_xor_sync(0xffffffffu, ssum, o);
    if (lane == 0) red[wid] = ssum;
    __syncthreads();
    if (tid == 0) red[0] = red[0] + red[1] + red[2] + red[3];
    __syncthreads();
    float ww = e / red[0];
    w[tid] = ww;
    if (half == 0) aw_dst[b * SS + tid] = ww;
    __syncthreads();

    const int col = half * 512 + tid * 4;
    const float* base = enc_out + (size_t)b * ENC2_ + col;
    float4 a = make_float4(0.f, 0.f, 0.f, 0.f);
    #pragma unroll 8
    for (int s = 0; s < SS; s++) {
        float ws = w[s];
        float4 v = *(const float4*)(base + (size_t)s * BB * ENC2_);
        a.x = fmaf(ws, v.x, a.x); a.y = fmaf(ws, v.y, a.y);
        a.z = fmaf(ws, v.z, a.z); a.w = fmaf(ws, v.w, a.w);
    }
    *(float4*)(&g_xbuf[b * XKC + EMB_ + col]) = a;
    *(float4*)(&g_obuf[b * OUTK + DECH_ + col]) = a;
}

__global__ void __launch_bounds__(1024)
lstm_k(const float* __restrict__ b_ih, const float* __restrict__ b_hh,
       const float* __restrict__ cell,
       float* __restrict__ nh_out, float* __restrict__ nc_out)
{
    int b = blockIdx.x, j = threadIdx.x;
    const float* gg = g_gates + (size_t)b * G4;
    float iv = gg[j]             + b_ih[j]             + b_hh[j];
    float fv = gg[j + DECH_]     + b_ih[j + DECH_]     + b_hh[j + DECH_];
    float gv = gg[j + 2 * DECH_] + b_ih[j + 2 * DECH_] + b_hh[j + 2 * DECH_];
    float ov = gg[j + 3 * DECH_] + b_ih[j + 3 * DECH_] + b_hh[j + 3 * DECH_];
    float i_ = 1.f / (1.f + __expf(-iv));
    float f_ = 1.f / (1.f + __expf(-fv));
    float o_ = 1.f / (1.f + __expf(-ov));
    float gt = tanhf(gv);
    float nc = f_ * cell[b * DECH_ + j] + i_ * gt;
    float nh = o_ * tanhf(nc);
    nc_out[b * DECH_ + j] = nc;
    nh_out[b * DECH_ + j] = nh;
    g_obuf[b * OUTK + j] = nh;
}

// ---------------------------------------------------------------- launcher
extern "C" void kernel_launch(void* const* d_in, const int* in_sizes, int n_in,
                              void* d_out, int out_size)
{
    const int*   input_token = (const int*)  d_in[0];
    const float* hidden      = (const float*)d_in[1];
    const float* cell        = (const float*)d_in[2];
    const float* enc_out     = (const float*)d_in[3];
    const int*   mask        = (const int*)  d_in[4];
    const float* embedding   = (const float*)d_in[5];
    const float* W_enc       = (const float*)d_in[6];
    const float* W_dec       = (const float*)d_in[7];
    const float* v_attn      = (const float*)d_in[8];
    const float* W_ih        = (const float*)d_in[9];
    const float* W_hh        = (const float*)d_in[10];
    const float* b_ih        = (const float*)d_in[11];
    const float* b_hh        = (const float*)d_in[12];
    const float* W_out       = (const float*)d_in[13];
    const float* b_out       = (const float*)d_in[14];

    float* out = (float*)d_out;

    void *p_decp, *p_xbuf, *p_obuf, *p_gates, *p_aux;
    cudaGetSymbolAddress(&p_decp,  g_decp);
    cudaGetSymbolAddress(&p_xbuf,  g_xbuf);
    cudaGetSymbolAddress(&p_obuf,  g_obuf);
    cudaGetSymbolAddress(&p_gates, g_gates);
    cudaGetSymbolAddress(&p_aux,   g_aux);

    cudaFuncSetAttribute(gemm_k<0,0>, cudaFuncAttributeMaxDynamicSharedMemorySize, SMEM_BYTES);
    cudaFuncSetAttribute(gemm_k<0,1>, cudaFuncAttributeMaxDynamicSharedMemorySize, SMEM_BYTES);
    cudaFuncSetAttribute(gemm_k<1,0>, cudaFuncAttributeMaxDynamicSharedMemorySize, SMEM_BYTES);

    bool full = (out_size >= OUT_TOTAL);
    float* nh_dst = full ? out + OFF_NH : (float*)p_aux;
    float* nc_dst = full ? out + OFF_NC : (float*)p_aux + BB * DECH_;
    float* aw_dst = full ? out + OFF_AW : (float*)p_aux + 2 * BB * DECH_;

    // zero split-K accumulators (memset nodes are graph-capturable)
    cudaMemsetAsync(p_decp,  0, BB * ATTN_ * sizeof(float));
    cudaMemsetAsync(p_gates, 0, BB * G4 * sizeof(float));

    // 1) embedding + hidden copy + scores zero
    embed_copy_k<<<BB, 256>>>(input_token, embedding, hidden);

    // 2) dec_proj[64,512] = hidden @ W_dec^T (split-K x8, atomic)
    gemm_k<0,1><<<dim3(ATTN_ / 128, 1, 8), 256, SMEM_BYTES>>>(
        hidden, DECH_, W_dec, DECH_, DECH_, W_dec, DECH_,
        (float*)p_decp, ATTN_, DECH_ / 8, nullptr, nullptr, nullptr);

    // 3) enc_proj GEMM fused with score reduction
    gemm_k<1,0><<<dim3(ATTN_ / 128, (SS * BB) / 64, 1), 256, SMEM_BYTES>>>(
        enc_out, ENC2_, W_enc, ENC2_, ENC2_, W_enc, ENC2_,
        nullptr, ATTN_, ENC2_, nullptr, (const float*)p_decp, v_attn);

    // 4) softmax + context
    smctx_k<<<dim3(2, BB), 128>>>(mask, enc_out, aw_dst);

    // 5) gates = [emb|ctx]@W_ih^T + hidden@W_hh^T (concat K=2560, split-K x4)
    gemm_k<0,1><<<dim3(G4 / 128, 1, 4), 256, SMEM_BYTES>>>(
        (const float*)p_xbuf, XKC, W_ih, EMB_ + ENC2_, EMB_ + ENC2_, W_hh, DECH_,
        (float*)p_gates, G4, XKC / 4, nullptr, nullptr, nullptr);

    // 6) LSTM pointwise
    lstm_k<<<BB, DECH_>>>(b_ih, b_hh, cell, nh_dst, nc_dst);

    // 7) output[64,32000] = [nh|ctx|emb] @ W_out^T + b_out
    gemm_k<0,0><<<dim3(VOCAB_ / 128, 1, 1), 256, SMEM_BYTES>>>(
        (const float*)p_obuf, OUTK, W_out, OUTK, OUTK, W_out, OUTK,
        out + OFF_OUT, VOCAB_, OUTK, b_out, nullptr, nullptr);
}

// round 6
// speedup vs baseline: 3.3641x; 1.1072x over previous
#include <cuda_runtime.h>
#include <cuda_bf16.h>
#include <math.h>
#include <stdint.h>

// ---------------------------------------------------------------- constants
#define BB    64
#define SS    128
#define EMB_  512
#define ENC2_ 1024
#define ATTN_ 512
#define DECH_ 1024
#define VOCAB_ 32000
#define XKC   2560
#define OUTK  2560
#define G4    (4 * DECH_)

#define OFF_OUT 0
#define OFF_NH  (BB * VOCAB_)
#define OFF_NC  (OFF_NH + BB * DECH_)
#define OFF_AW  (OFF_NC + BB * DECH_)
#define OUT_TOTAL (OFF_AW + BB * SS)

// scratch (no allocations allowed)
__device__ __align__(16) float g_decp[BB * ATTN_];
__device__ __align__(16) float g_scores[BB * SS];
__device__ __align__(16) float g_xbuf[BB * XKC];   // [emb|ctx|hidden]
__device__ __align__(16) float g_obuf[BB * OUTK];  // [nh|ctx|emb]
__device__ __align__(16) float g_gates[BB * G4];
__device__ __align__(16) float g_aux[BB * DECH_ * 2 + BB * SS];

// ---------------------------------------------------------------- helpers
#define MMA16816(c, a, b) \
    asm volatile("mma.sync.aligned.m16n8k16.row.col.f32.bf16.bf16.f32 " \
        "{%0,%1,%2,%3},{%4,%5,%6,%7},{%8,%9},{%0,%1,%2,%3};" \
        : "+f"(c[0]), "+f"(c[1]), "+f"(c[2]), "+f"(c[3]) \
        : "r"(a[0]), "r"(a[1]), "r"(a[2]), "r"(a[3]), "r"(b[0]), "r"(b[1]))

__device__ __forceinline__ void split4(float4 v, uint2& h, uint2& l)
{
    __nv_bfloat162 h01 = __floats2bfloat162_rn(v.x, v.y);
    __nv_bfloat162 h23 = __floats2bfloat162_rn(v.z, v.w);
    float2 f01 = __bfloat1622float2(h01);
    float2 f23 = __bfloat1622float2(h23);
    __nv_bfloat162 l01 = __floats2bfloat162_rn(v.x - f01.x, v.y - f01.y);
    __nv_bfloat162 l23 = __floats2bfloat162_rn(v.z - f23.x, v.w - f23.y);
    h.x = *(uint32_t*)&h01; h.y = *(uint32_t*)&h23;
    l.x = *(uint32_t*)&l01; l.y = *(uint32_t*)&l23;
}
__device__ __forceinline__ void hi4(float4 v, uint2& h)
{
    __nv_bfloat162 h01 = __floats2bfloat162_rn(v.x, v.y);
    __nv_bfloat162 h23 = __floats2bfloat162_rn(v.z, v.w);
    h.x = *(uint32_t*)&h01; h.y = *(uint32_t*)&h23;
}

// ---------------------------------------------------------------- GEMM
// C[M,N] = A[M,K] @ concatK(B1,B2)[N,K]^T (+bias)
// NPROD=3: Ah*Bh + Ah*Bl + Al*Bh.  NPROD=2: (Ah+Al)*Bh (B truncated to bf16).
// BM=64, BN=128, BK=32, 256 thr, 8 warps 2(m)x4(n), warp tile 32x32.
// Split-K via blockIdx.z; ATOM=1 -> atomicAdd epilogue.
// EPI=1: Bahdanau score epilogue (atomicAdd partial tanh-dot into g_scores).
#define BKK 32
#define LDK 40
#define STAGE_A  0
#define STAGE_AL 2560
#define STAGE_B  5120
#define STAGE_BL 10240
#define STAGE_SZ 15360          // bf16 elems per stage
#define SMEM_BYTES (2 * STAGE_SZ * 2)  // 61440

template<int EPI, int ATOM, int NPROD>
__global__ void __launch_bounds__(256, 2)
gemm_k(const float* __restrict__ A, int lda,
       const float* __restrict__ B1, int ldb1, int ksplit,
       const float* __restrict__ B2, int ldb2,
       float* __restrict__ C, int N, int kslice,
       const float* __restrict__ bias,
       const float* __restrict__ decp,
       const float* __restrict__ vat)
{
    extern __shared__ __nv_bfloat16 sm[];

    const int tid = threadIdx.x;
    const int wid = tid >> 5, lane = tid & 31;
    const int g = lane >> 2, tig = lane & 3;
    const int wm = wid >> 2, wn = wid & 3;
    const int bm = blockIdx.y * 64, bn = blockIdx.x * 128;
    const int k0 = blockIdx.z * kslice;
    const int nk = kslice / BKK;

    const int lrow = tid >> 3;   // 0..31
    const int lkq  = tid & 7;    // float4 slot in BK=32

    float4 pa0, pa1, pb[4];

    // prefetch kt=0
    {
        const int gk = k0 + lkq * 4;
        pa0 = *(const float4*)(A + (size_t)(bm + lrow) * lda + gk);
        pa1 = *(const float4*)(A + (size_t)(bm + lrow + 32) * lda + gk);
        #pragma unroll
        for (int r = 0; r < 4; r++) {
            const int n = bn + lrow + r * 32;
            const float* Bp = (gk < ksplit)
                ? (B1 + (size_t)n * ldb1 + gk)
                : (B2 + (size_t)n * ldb2 + (gk - ksplit));
            pb[r] = *(const float4*)Bp;
        }
    }
    // store stage 0
    {
        __nv_bfloat16* st = sm;
        uint2 h, l;
        split4(pa0, h, l);
        *(uint2*)&st[STAGE_A  + lrow * LDK + lkq * 4] = h;
        *(uint2*)&st[STAGE_AL + lrow * LDK + lkq * 4] = l;
        split4(pa1, h, l);
        *(uint2*)&st[STAGE_A  + (lrow + 32) * LDK + lkq * 4] = h;
        *(uint2*)&st[STAGE_AL + (lrow + 32) * LDK + lkq * 4] = l;
        #pragma unroll
        for (int r = 0; r < 4; r++) {
            if (NPROD == 3) {
                split4(pb[r], h, l);
                *(uint2*)&st[STAGE_B  + (lrow + r * 32) * LDK + lkq * 4] = h;
                *(uint2*)&st[STAGE_BL + (lrow + r * 32) * LDK + lkq * 4] = l;
            } else {
                hi4(pb[r], h);
                *(uint2*)&st[STAGE_B  + (lrow + r * 32) * LDK + lkq * 4] = h;
            }
        }
    }
    __syncthreads();

    float acc[2][4][4];
    #pragma unroll
    for (int mt = 0; mt < 2; mt++)
        #pragma unroll
        for (int nt = 0; nt < 4; nt++)
            #pragma unroll
            for (int q = 0; q < 4; q++) acc[mt][nt][q] = 0.f;

    for (int kt = 0; kt < nk; kt++) {
        const __nv_bfloat16* cur = sm + (kt & 1) * STAGE_SZ;
        __nv_bfloat16* nxt = sm + ((kt + 1) & 1) * STAGE_SZ;

        // LDG for kt+1
        if (kt + 1 < nk) {
            const int gk = k0 + (kt + 1) * BKK + lkq * 4;
            pa0 = *(const float4*)(A + (size_t)(bm + lrow) * lda + gk);
            pa1 = *(const float4*)(A + (size_t)(bm + lrow + 32) * lda + gk);
            #pragma unroll
            for (int r = 0; r < 4; r++) {
                const int n = bn + lrow + r * 32;
                const float* Bp = (gk < ksplit)
                    ? (B1 + (size_t)n * ldb1 + gk)
                    : (B2 + (size_t)n * ldb2 + (gk - ksplit));
                pb[r] = *(const float4*)Bp;
            }
        }

        // MMAs on current stage
        #pragma unroll
        for (int ks = 0; ks < 2; ks++) {
            const int ko = ks * 16 + tig * 2;
            uint32_t ah[2][4], al[2][4], bh[4][2], bl[4][2];
            #pragma unroll
            for (int mt = 0; mt < 2; mt++) {
                const int r = wm * 32 + mt * 16;
                ah[mt][0] = *(const uint32_t*)&cur[STAGE_A + (r + g) * LDK + ko];
                ah[mt][1] = *(const uint32_t*)&cur[STAGE_A + (r + g + 8) * LDK + ko];
                ah[mt][2] = *(const uint32_t*)&cur[STAGE_A + (r + g) * LDK + ko + 8];
                ah[mt][3] = *(const uint32_t*)&cur[STAGE_A + (r + g + 8) * LDK + ko + 8];
                al[mt][0] = *(const uint32_t*)&cur[STAGE_AL + (r + g) * LDK + ko];
                al[mt][1] = *(const uint32_t*)&cur[STAGE_AL + (r + g + 8) * LDK + ko];
                al[mt][2] = *(const uint32_t*)&cur[STAGE_AL + (r + g) * LDK + ko + 8];
                al[mt][3] = *(const uint32_t*)&cur[STAGE_AL + (r + g + 8) * LDK + ko + 8];
            }
            #pragma unroll
            for (int nt = 0; nt < 4; nt++) {
                const int n = wn * 32 + nt * 8 + g;
                bh[nt][0] = *(const uint32_t*)&cur[STAGE_B + n * LDK + ko];
                bh[nt][1] = *(const uint32_t*)&cur[STAGE_B + n * LDK + ko + 8];
                if (NPROD == 3) {
                    bl[nt][0] = *(const uint32_t*)&cur[STAGE_BL + n * LDK + ko];
                    bl[nt][1] = *(const uint32_t*)&cur[STAGE_BL + n * LDK + ko + 8];
                }
            }
            #pragma unroll
            for (int mt = 0; mt < 2; mt++)
                #pragma unroll
                for (int nt = 0; nt < 4; nt++) {
                    MMA16816(acc[mt][nt], ah[mt], bh[nt]);
                    if (NPROD == 3) MMA16816(acc[mt][nt], ah[mt], bl[nt]);
                    MMA16816(acc[mt][nt], al[mt], bh[nt]);
                }
        }

        // convert + STS into other stage
        if (kt + 1 < nk) {
            uint2 h, l;
            split4(pa0, h, l);
            *(uint2*)&nxt[STAGE_A  + lrow * LDK + lkq * 4] = h;
            *(uint2*)&nxt[STAGE_AL + lrow * LDK + lkq * 4] = l;
            split4(pa1, h, l);
            *(uint2*)&nxt[STAGE_A  + (lrow + 32) * LDK + lkq * 4] = h;
            *(uint2*)&nxt[STAGE_AL + (lrow + 32) * LDK + lkq * 4] = l;
            #pragma unroll
            for (int r = 0; r < 4; r++) {
                if (NPROD == 3) {
                    split4(pb[r], h, l);
                    *(uint2*)&nxt[STAGE_B  + (lrow + r * 32) * LDK + lkq * 4] = h;
                    *(uint2*)&nxt[STAGE_BL + (lrow + r * 32) * LDK + lkq * 4] = l;
                } else {
                    hi4(pb[r], h);
                    *(uint2*)&nxt[STAGE_B  + (lrow + r * 32) * LDK + lkq * 4] = h;
                }
            }
        }
        __syncthreads();
    }

    if (EPI == 0) {
        #pragma unroll
        for (int mt = 0; mt < 2; mt++) {
            const int gm = bm + wm * 32 + mt * 16 + g;
            #pragma unroll
            for (int nt = 0; nt < 4; nt++) {
                const int gn = bn + wn * 32 + nt * 8 + tig * 2;
                if (ATOM) {
                    atomicAdd(C + (size_t)gm * N + gn,       acc[mt][nt][0]);
                    atomicAdd(C + (size_t)gm * N + gn + 1,   acc[mt][nt][1]);
                    atomicAdd(C + (size_t)(gm + 8) * N + gn,     acc[mt][nt][2]);
                    atomicAdd(C + (size_t)(gm + 8) * N + gn + 1, acc[mt][nt][3]);
                } else {
                    const float b0 = bias ? bias[gn] : 0.f;
                    const float b1 = bias ? bias[gn + 1] : 0.f;
                    *(float2*)(C + (size_t)gm * N + gn) =
                        make_float2(acc[mt][nt][0] + b0, acc[mt][nt][1] + b1);
                    *(float2*)(C + (size_t)(gm + 8) * N + gn) =
                        make_float2(acc[mt][nt][2] + b0, acc[mt][nt][3] + b1);
                }
            }
        }
    } else {
        // score epilogue: row gm -> (b = gm&63, s = gm>>6); c2/c3 are row gm+8
        #pragma unroll
        for (int mt = 0; mt < 2; mt++) {
            const int gm = bm + wm * 32 + mt * 16 + g;
            const int bA = gm & 63;
            const int bBt = (gm + 8) & 63;
            float p0 = 0.f, p8 = 0.f;
            #pragma unroll
            for (int nt = 0; nt < 4; nt++) {
                const int gn = bn + wn * 32 + nt * 8 + tig * 2;
                const float d0a = decp[bA * ATTN_ + gn],  d1a = decp[bA * ATTN_ + gn + 1];
                const float d0b = decp[bBt * ATTN_ + gn], d1b = decp[bBt * ATTN_ + gn + 1];
                const float v0 = vat[gn], v1 = vat[gn + 1];
                p0 += tanhf(acc[mt][nt][0] + d0a) * v0 + tanhf(acc[mt][nt][1] + d1a) * v1;
                p8 += tanhf(acc[mt][nt][2] + d0b) * v0 + tanhf(acc[mt][nt][3] + d1b) * v1;
            }
            p0 += __shfl_xor_sync(0xffffffffu, p0, 1);
            p0 += __shfl_xor_sync(0xffffffffu, p0, 2);
            p8 += __shfl_xor_sync(0xffffffffu, p8, 1);
            p8 += __shfl_xor_sync(0xffffffffu, p8, 2);
            if (tig == 0) {
                atomicAdd(&g_scores[bA * SS + (gm >> 6)], p0);
                atomicAdd(&g_scores[bBt * SS + ((gm + 8) >> 6)], p8);
            }
        }
    }
}

// ---------------------------------------------------------------- embed etc.
// also zeroes the ctx slice of g_xbuf (accumulated atomically by smctx)
__global__ void __launch_bounds__(256)
embed_copy_k(const int* __restrict__ tok, const float* __restrict__ emb,
             const float* __restrict__ hidden)
{
    int b = blockIdx.x, tid = threadIdx.x;
    int t = tok[b];
    const float* src = emb + (size_t)t * EMB_;
    for (int j = tid; j < EMB_; j += 256) {
        float v = (t == 0) ? 0.f : src[j];
        g_xbuf[b * XKC + j] = v;
        g_obuf[b * OUTK + (DECH_ + ENC2_) + j] = v;
    }
    for (int j = tid; j < DECH_; j += 256) {
        g_xbuf[b * XKC + (EMB_ + ENC2_) + j] = hidden[b * DECH_ + j];
        g_xbuf[b * XKC + EMB_ + j] = 0.f;   // ctx accumulator
    }
    if (tid < SS) g_scores[b * SS + tid] = 0.f;
}

// softmax + partial context; grid (8, 64): x = half*4 + schunk; 128 threads.
// Each CTA accumulates 32 s-rows for its 512-col half via atomicAdd.
__global__ void __launch_bounds__(128)
smctx_k(const int* __restrict__ mask, const float* __restrict__ enc_out,
        float* __restrict__ aw_dst)
{
    int b = blockIdx.y, half = blockIdx.x >> 2, sc = blockIdx.x & 3;
    int tid = threadIdx.x;
    int wid = tid >> 5, lane = tid & 31;
    __shared__ float w[SS];
    __shared__ float red[4];

    float val = (mask[b * SS + tid] == 0) ? -INFINITY : g_scores[b * SS + tid];
    float m = val;
    #pragma unroll
    for (int o = 16; o; o >>= 1) m = fmaxf(m, __shfl_xor_sync(0xffffffffu, m, o));
    if (lane == 0) red[wid] = m;
    __syncthreads();
    if (tid == 0) red[0] = fmaxf(fmaxf(red[0], red[1]), fmaxf(red[2], red[3]));
    __syncthreads();
    float mx = red[0];
    __syncthreads();

    float e = __expf(val - mx);
    float ssum = e;
    #pragma unroll
    for (int o = 16; o; o >>= 1) ssum += __shfl_xor_sync(0xffffffffu, ssum, o);
    if (lane == 0) red[wid] = ssum;
    __syncthreads();
    if (tid == 0) red[0] = red[0] + red[1] + red[2] + red[3];
    __syncthreads();
    float ww = e / red[0];
    w[tid] = ww;
    if (blockIdx.x == 0) aw_dst[b * SS + tid] = ww;
    __syncthreads();

    const int col = half * 512 + tid * 4;
    const float* base = enc_out + (size_t)b * ENC2_ + col;
    float4 a = make_float4(0.f, 0.f, 0.f, 0.f);
    const int s0 = sc * 32;
    #pragma unroll 8
    for (int s = s0; s < s0 + 32; s++) {
        float ws = w[s];
        float4 v = *(const float4*)(base + (size_t)s * BB * ENC2_);
        a.x = fmaf(ws, v.x, a.x); a.y = fmaf(ws, v.y, a.y);
        a.z = fmaf(ws, v.z, a.z); a.w = fmaf(ws, v.w, a.w);
    }
    float* dst = &g_xbuf[b * XKC + EMB_ + col];
    atomicAdd(dst + 0, a.x);
    atomicAdd(dst + 1, a.y);
    atomicAdd(dst + 2, a.z);
    atomicAdd(dst + 3, a.w);
}

// LSTM pointwise; also copies ctx g_xbuf -> g_obuf (needed by out GEMM)
__global__ void __launch_bounds__(1024)
lstm_k(const float* __restrict__ b_ih, const float* __restrict__ b_hh,
       const float* __restrict__ cell,
       float* __restrict__ nh_out, float* __restrict__ nc_out)
{
    int b = blockIdx.x, j = threadIdx.x;
    const float* gg = g_gates + (size_t)b * G4;
    float iv = gg[j]             + b_ih[j]             + b_hh[j];
    float fv = gg[j + DECH_]     + b_ih[j + DECH_]     + b_hh[j + DECH_];
    float gv = gg[j + 2 * DECH_] + b_ih[j + 2 * DECH_] + b_hh[j + 2 * DECH_];
    float ov = gg[j + 3 * DECH_] + b_ih[j + 3 * DECH_] + b_hh[j + 3 * DECH_];
    float i_ = 1.f / (1.f + __expf(-iv));
    float f_ = 1.f / (1.f + __expf(-fv));
    float o_ = 1.f / (1.f + __expf(-ov));
    float gt = tanhf(gv);
    float nc = f_ * cell[b * DECH_ + j] + i_ * gt;
    float nh = o_ * tanhf(nc);
    nc_out[b * DECH_ + j] = nc;
    nh_out[b * DECH_ + j] = nh;
    g_obuf[b * OUTK + j] = nh;
    g_obuf[b * OUTK + DECH_ + j] = g_xbuf[b * XKC + EMB_ + j];  // ctx copy
}

// ---------------------------------------------------------------- launcher
extern "C" void kernel_launch(void* const* d_in, const int* in_sizes, int n_in,
                              void* d_out, int out_size)
{
    const int*   input_token = (const int*)  d_in[0];
    const float* hidden      = (const float*)d_in[1];
    const float* cell        = (const float*)d_in[2];
    const float* enc_out     = (const float*)d_in[3];
    const int*   mask        = (const int*)  d_in[4];
    const float* embedding   = (const float*)d_in[5];
    const float* W_enc       = (const float*)d_in[6];
    const float* W_dec       = (const float*)d_in[7];
    const float* v_attn      = (const float*)d_in[8];
    const float* W_ih        = (const float*)d_in[9];
    const float* W_hh        = (const float*)d_in[10];
    const float* b_ih        = (const float*)d_in[11];
    const float* b_hh        = (const float*)d_in[12];
    const float* W_out       = (const float*)d_in[13];
    const float* b_out       = (const float*)d_in[14];

    float* out = (float*)d_out;

    void *p_decp, *p_xbuf, *p_obuf, *p_gates, *p_aux;
    cudaGetSymbolAddress(&p_decp,  g_decp);
    cudaGetSymbolAddress(&p_xbuf,  g_xbuf);
    cudaGetSymbolAddress(&p_obuf,  g_obuf);
    cudaGetSymbolAddress(&p_gates, g_gates);
    cudaGetSymbolAddress(&p_aux,   g_aux);

    cudaFuncSetAttribute(gemm_k<0,0,3>, cudaFuncAttributeMaxDynamicSharedMemorySize, SMEM_BYTES);
    cudaFuncSetAttribute(gemm_k<0,1,3>, cudaFuncAttributeMaxDynamicSharedMemorySize, SMEM_BYTES);
    cudaFuncSetAttribute(gemm_k<1,0,2>, cudaFuncAttributeMaxDynamicSharedMemorySize, SMEM_BYTES);

    bool full = (out_size >= OUT_TOTAL);
    float* nh_dst = full ? out + OFF_NH : (float*)p_aux;
    float* nc_dst = full ? out + OFF_NC : (float*)p_aux + BB * DECH_;
    float* aw_dst = full ? out + OFF_AW : (float*)p_aux + 2 * BB * DECH_;

    // zero split-K accumulators
    cudaMemsetAsync(p_decp,  0, BB * ATTN_ * sizeof(float));
    cudaMemsetAsync(p_gates, 0, BB * G4 * sizeof(float));

    // 1) embedding + hidden copy + zero scores/ctx
    embed_copy_k<<<BB, 256>>>(input_token, embedding, hidden);

    // 2) dec_proj[64,512] = hidden @ W_dec^T (split-K x8, atomic, 3-product)
    gemm_k<0,1,3><<<dim3(ATTN_ / 128, 1, 8), 256, SMEM_BYTES>>>(
        hidden, DECH_, W_dec, DECH_, DECH_, W_dec, DECH_,
        (float*)p_decp, ATTN_, DECH_ / 8, nullptr, nullptr, nullptr);

    // 3) enc_proj GEMM fused with score reduction (2-product: B bf16-truncated)
    gemm_k<1,0,2><<<dim3(ATTN_ / 128, (SS * BB) / 64, 1), 256, SMEM_BYTES>>>(
        enc_out, ENC2_, W_enc, ENC2_, ENC2_, W_enc, ENC2_,
        nullptr, ATTN_, ENC2_, nullptr, (const float*)p_decp, v_attn);

    // 4) softmax + context (s-split x4, col-half x2, atomic ctx accumulate)
    smctx_k<<<dim3(8, BB), 128>>>(mask, enc_out, aw_dst);

    // 5) gates = [emb|ctx]@W_ih^T + hidden@W_hh^T (concat K=2560, split-K x4)
    gemm_k<0,1,3><<<dim3(G4 / 128, 1, 4), 256, SMEM_BYTES>>>(
        (const float*)p_xbuf, XKC, W_ih, EMB_ + ENC2_, EMB_ + ENC2_, W_hh, DECH_,
        (float*)p_gates, G4, XKC / 4, nullptr, nullptr, nullptr);

    // 6) LSTM pointwise + ctx copy into obuf
    lstm_k<<<BB, DECH_>>>(b_ih, b_hh, cell, nh_dst, nc_dst);

    // 7) output[64,32000] = [nh|ctx|emb] @ W_out^T + b_out (3-product)
    gemm_k<0,0,3><<<dim3(VOCAB_ / 128, 1, 1), 256, SMEM_BYTES>>>(
        (const float*)p_obuf, OUTK, W_out, OUTK, OUTK, W_out, OUTK,
        out + OFF_OUT, VOCAB_, OUTK, b_out, nullptr, nullptr);
}

// round 7
// speedup vs baseline: 3.7520x; 1.1153x over previous
#include <cuda_runtime.h>
#include <cuda_fp16.h>
#include <math.h>
#include <stdint.h>

// ---------------------------------------------------------------- constants
#define BB    64
#define SS    128
#define EMB_  512
#define ENC2_ 1024
#define ATTN_ 512
#define DECH_ 1024
#define VOCAB_ 32000
#define XKC   2560
#define OUTK  2560
#define G4    (4 * DECH_)

#define OFF_OUT 0
#define OFF_NH  (BB * VOCAB_)
#define OFF_NC  (OFF_NH + BB * DECH_)
#define OFF_AW  (OFF_NC + BB * DECH_)
#define OUT_TOTAL (OFF_AW + BB * SS)

// scratch (no allocations allowed)
__device__ __align__(16) float g_decp[BB * ATTN_];
__device__ __align__(16) float g_scores[BB * SS];
__device__ __align__(16) float g_xbuf[BB * XKC];   // [emb|ctx|hidden]
__device__ __align__(16) float g_obuf[BB * OUTK];  // [nh|ctx|emb]
__device__ __align__(16) float g_gates[BB * G4];
__device__ __align__(16) float g_aux[BB * DECH_ * 2 + BB * SS];

// ---------------------------------------------------------------- helpers
#define MMA16816(c, a, b) \
    asm volatile("mma.sync.aligned.m16n8k16.row.col.f32.f16.f16.f32 " \
        "{%0,%1,%2,%3},{%4,%5,%6,%7},{%8,%9},{%0,%1,%2,%3};" \
        : "+f"(c[0]), "+f"(c[1]), "+f"(c[2]), "+f"(c[3]) \
        : "r"(a[0]), "r"(a[1]), "r"(a[2]), "r"(a[3]), "r"(b[0]), "r"(b[1]))

__device__ __forceinline__ void split4(float4 v, uint2& h, uint2& l)
{
    __half2 h01 = __floats2half2_rn(v.x, v.y);
    __half2 h23 = __floats2half2_rn(v.z, v.w);
    float2 f01 = __half22float2(h01);
    float2 f23 = __half22float2(h23);
    __half2 l01 = __floats2half2_rn(v.x - f01.x, v.y - f01.y);
    __half2 l23 = __floats2half2_rn(v.z - f23.x, v.w - f23.y);
    h.x = *(uint32_t*)&h01; h.y = *(uint32_t*)&h23;
    l.x = *(uint32_t*)&l01; l.y = *(uint32_t*)&l23;
}
__device__ __forceinline__ void hi4(float4 v, uint2& h)
{
    __half2 h01 = __floats2half2_rn(v.x, v.y);
    __half2 h23 = __floats2half2_rn(v.z, v.w);
    h.x = *(uint32_t*)&h01; h.y = *(uint32_t*)&h23;
}

// ---------------------------------------------------------------- GEMM
// C[M,N] = A[M,K] @ concatK(B1,B2)[N,K]^T (+bias), fp16 split, fp32 accum.
// NPROD=3: Ah*Bh + Ah*Bl + Al*Bh (A,B both ~2^-22 accurate).
// NPROD=2: (Ah+Al)*Bh (A ~2^-22, B truncated to 2^-11).
// BM=64, BN=128, BK=32, 256 thr, 8 warps 2(m)x4(n), warp tile 32x32.
// Split-K via blockIdx.z; ATOM=1 -> atomicAdd epilogue.
// EPI=1: Bahdanau score epilogue (atomicAdd partial tanh-dot into g_scores).
#define BKK 32
#define LDK 40
#define STAGE_A  0
#define STAGE_AL 2560
#define STAGE_B  5120
#define STAGE_BL 10240
#define STAGE_SZ 15360          // fp16 elems per stage
#define SMEM_BYTES (2 * STAGE_SZ * 2)  // 61440

template<int EPI, int ATOM, int NPROD>
__global__ void __launch_bounds__(256, 2)
gemm_k(const float* __restrict__ A, int lda,
       const float* __restrict__ B1, int ldb1, int ksplit,
       const float* __restrict__ B2, int ldb2,
       float* __restrict__ C, int N, int kslice,
       const float* __restrict__ bias,
       const float* __restrict__ decp,
       const float* __restrict__ vat)
{
    extern __shared__ __half sm[];

    const int tid = threadIdx.x;
    const int wid = tid >> 5, lane = tid & 31;
    const int g = lane >> 2, tig = lane & 3;
    const int wm = wid >> 2, wn = wid & 3;
    const int bm = blockIdx.y * 64, bn = blockIdx.x * 128;
    const int k0 = blockIdx.z * kslice;
    const int nk = kslice / BKK;

    const int lrow = tid >> 3;   // 0..31
    const int lkq  = tid & 7;    // float4 slot in BK=32

    float4 pa0, pa1, pb[4];

    // prefetch kt=0
    {
        const int gk = k0 + lkq * 4;
        pa0 = *(const float4*)(A + (size_t)(bm + lrow) * lda + gk);
        pa1 = *(const float4*)(A + (size_t)(bm + lrow + 32) * lda + gk);
        #pragma unroll
        for (int r = 0; r < 4; r++) {
            const int n = bn + lrow + r * 32;
            const float* Bp = (gk < ksplit)
                ? (B1 + (size_t)n * ldb1 + gk)
                : (B2 + (size_t)n * ldb2 + (gk - ksplit));
            pb[r] = *(const float4*)Bp;
        }
    }
    // store stage 0
    {
        __half* st = sm;
        uint2 h, l;
        split4(pa0, h, l);
        *(uint2*)&st[STAGE_A  + lrow * LDK + lkq * 4] = h;
        *(uint2*)&st[STAGE_AL + lrow * LDK + lkq * 4] = l;
        split4(pa1, h, l);
        *(uint2*)&st[STAGE_A  + (lrow + 32) * LDK + lkq * 4] = h;
        *(uint2*)&st[STAGE_AL + (lrow + 32) * LDK + lkq * 4] = l;
        #pragma unroll
        for (int r = 0; r < 4; r++) {
            if (NPROD == 3) {
                split4(pb[r], h, l);
                *(uint2*)&st[STAGE_B  + (lrow + r * 32) * LDK + lkq * 4] = h;
                *(uint2*)&st[STAGE_BL + (lrow + r * 32) * LDK + lkq * 4] = l;
            } else {
                hi4(pb[r], h);
                *(uint2*)&st[STAGE_B  + (lrow + r * 32) * LDK + lkq * 4] = h;
            }
        }
    }
    __syncthreads();

    float acc[2][4][4];
    #pragma unroll
    for (int mt = 0; mt < 2; mt++)
        #pragma unroll
        for (int nt = 0; nt < 4; nt++)
            #pragma unroll
            for (int q = 0; q < 4; q++) acc[mt][nt][q] = 0.f;

    for (int kt = 0; kt < nk; kt++) {
        const __half* cur = sm + (kt & 1) * STAGE_SZ;
        __half* nxt = sm + ((kt + 1) & 1) * STAGE_SZ;

        // LDG for kt+1
        if (kt + 1 < nk) {
            const int gk = k0 + (kt + 1) * BKK + lkq * 4;
            pa0 = *(const float4*)(A + (size_t)(bm + lrow) * lda + gk);
            pa1 = *(const float4*)(A + (size_t)(bm + lrow + 32) * lda + gk);
            #pragma unroll
            for (int r = 0; r < 4; r++) {
                const int n = bn + lrow + r * 32;
                const float* Bp = (gk < ksplit)
                    ? (B1 + (size_t)n * ldb1 + gk)
                    : (B2 + (size_t)n * ldb2 + (gk - ksplit));
                pb[r] = *(const float4*)Bp;
            }
        }

        // MMAs on current stage
        #pragma unroll
        for (int ks = 0; ks < 2; ks++) {
            const int ko = ks * 16 + tig * 2;
            uint32_t ah[2][4], al[2][4], bh[4][2], bl[4][2];
            #pragma unroll
            for (int mt = 0; mt < 2; mt++) {
                const int r = wm * 32 + mt * 16;
                ah[mt][0] = *(const uint32_t*)&cur[STAGE_A + (r + g) * LDK + ko];
                ah[mt][1] = *(const uint32_t*)&cur[STAGE_A + (r + g + 8) * LDK + ko];
                ah[mt][2] = *(const uint32_t*)&cur[STAGE_A + (r + g) * LDK + ko + 8];
                ah[mt][3] = *(const uint32_t*)&cur[STAGE_A + (r + g + 8) * LDK + ko + 8];
                al[mt][0] = *(const uint32_t*)&cur[STAGE_AL + (r + g) * LDK + ko];
                al[mt][1] = *(const uint32_t*)&cur[STAGE_AL + (r + g + 8) * LDK + ko];
                al[mt][2] = *(const uint32_t*)&cur[STAGE_AL + (r + g) * LDK + ko + 8];
                al[mt][3] = *(const uint32_t*)&cur[STAGE_AL + (r + g + 8) * LDK + ko + 8];
            }
            #pragma unroll
            for (int nt = 0; nt < 4; nt++) {
                const int n = wn * 32 + nt * 8 + g;
                bh[nt][0] = *(const uint32_t*)&cur[STAGE_B + n * LDK + ko];
                bh[nt][1] = *(const uint32_t*)&cur[STAGE_B + n * LDK + ko + 8];
                if (NPROD == 3) {
                    bl[nt][0] = *(const uint32_t*)&cur[STAGE_BL + n * LDK + ko];
                    bl[nt][1] = *(const uint32_t*)&cur[STAGE_BL + n * LDK + ko + 8];
                }
            }
            #pragma unroll
            for (int mt = 0; mt < 2; mt++)
                #pragma unroll
                for (int nt = 0; nt < 4; nt++) {
                    MMA16816(acc[mt][nt], ah[mt], bh[nt]);
                    if (NPROD == 3) MMA16816(acc[mt][nt], ah[mt], bl[nt]);
                    MMA16816(acc[mt][nt], al[mt], bh[nt]);
                }
        }

        // convert + STS into other stage
        if (kt + 1 < nk) {
            uint2 h, l;
            split4(pa0, h, l);
            *(uint2*)&nxt[STAGE_A  + lrow * LDK + lkq * 4] = h;
            *(uint2*)&nxt[STAGE_AL + lrow * LDK + lkq * 4] = l;
            split4(pa1, h, l);
            *(uint2*)&nxt[STAGE_A  + (lrow + 32) * LDK + lkq * 4] = h;
            *(uint2*)&nxt[STAGE_AL + (lrow + 32) * LDK + lkq * 4] = l;
            #pragma unroll
            for (int r = 0; r < 4; r++) {
                if (NPROD == 3) {
                    split4(pb[r], h, l);
                    *(uint2*)&nxt[STAGE_B  + (lrow + r * 32) * LDK + lkq * 4] = h;
                    *(uint2*)&nxt[STAGE_BL + (lrow + r * 32) * LDK + lkq * 4] = l;
                } else {
                    hi4(pb[r], h);
                    *(uint2*)&nxt[STAGE_B  + (lrow + r * 32) * LDK + lkq * 4] = h;
                }
            }
        }
        __syncthreads();
    }

    if (EPI == 0) {
        #pragma unroll
        for (int mt = 0; mt < 2; mt++) {
            const int gm = bm + wm * 32 + mt * 16 + g;
            #pragma unroll
            for (int nt = 0; nt < 4; nt++) {
                const int gn = bn + wn * 32 + nt * 8 + tig * 2;
                if (ATOM) {
                    atomicAdd(C + (size_t)gm * N + gn,       acc[mt][nt][0]);
                    atomicAdd(C + (size_t)gm * N + gn + 1,   acc[mt][nt][1]);
                    atomicAdd(C + (size_t)(gm + 8) * N + gn,     acc[mt][nt][2]);
                    atomicAdd(C + (size_t)(gm + 8) * N + gn + 1, acc[mt][nt][3]);
                } else {
                    const float b0 = bias ? bias[gn] : 0.f;
                    const float b1 = bias ? bias[gn + 1] : 0.f;
                    *(float2*)(C + (size_t)gm * N + gn) =
                        make_float2(acc[mt][nt][0] + b0, acc[mt][nt][1] + b1);
                    *(float2*)(C + (size_t)(gm + 8) * N + gn) =
                        make_float2(acc[mt][nt][2] + b0, acc[mt][nt][3] + b1);
                }
            }
        }
    } else {
        // score epilogue: row gm -> (b = gm&63, s = gm>>6); c2/c3 are row gm+8
        #pragma unroll
        for (int mt = 0; mt < 2; mt++) {
            const int gm = bm + wm * 32 + mt * 16 + g;
            const int bA = gm & 63;
            const int bBt = (gm + 8) & 63;
            float p0 = 0.f, p8 = 0.f;
            #pragma unroll
            for (int nt = 0; nt < 4; nt++) {
                const int gn = bn + wn * 32 + nt * 8 + tig * 2;
                const float d0a = decp[bA * ATTN_ + gn],  d1a = decp[bA * ATTN_ + gn + 1];
                const float d0b = decp[bBt * ATTN_ + gn], d1b = decp[bBt * ATTN_ + gn + 1];
                const float v0 = vat[gn], v1 = vat[gn + 1];
                p0 += tanhf(acc[mt][nt][0] + d0a) * v0 + tanhf(acc[mt][nt][1] + d1a) * v1;
                p8 += tanhf(acc[mt][nt][2] + d0b) * v0 + tanhf(acc[mt][nt][3] + d1b) * v1;
            }
            p0 += __shfl_xor_sync(0xffffffffu, p0, 1);
            p0 += __shfl_xor_sync(0xffffffffu, p0, 2);
            p8 += __shfl_xor_sync(0xffffffffu, p8, 1);
            p8 += __shfl_xor_sync(0xffffffffu, p8, 2);
            if (tig == 0) {
                atomicAdd(&g_scores[bA * SS + (gm >> 6)], p0);
                atomicAdd(&g_scores[bBt * SS + ((gm + 8) >> 6)], p8);
            }
        }
    }
}

// ---------------------------------------------------------------- embed etc.
__global__ void __launch_bounds__(256)
embed_copy_k(const int* __restrict__ tok, const float* __restrict__ emb,
             const float* __restrict__ hidden)
{
    int b = blockIdx.x, tid = threadIdx.x;
    int t = tok[b];
    const float* src = emb + (size_t)t * EMB_;
    for (int j = tid; j < EMB_; j += 256) {
        float v = (t == 0) ? 0.f : src[j];
        g_xbuf[b * XKC + j] = v;
        g_obuf[b * OUTK + (DECH_ + ENC2_) + j] = v;
    }
    for (int j = tid; j < DECH_; j += 256) {
        g_xbuf[b * XKC + (EMB_ + ENC2_) + j] = hidden[b * DECH_ + j];
        g_xbuf[b * XKC + EMB_ + j] = 0.f;   // ctx accumulator
    }
    if (tid < SS) g_scores[b * SS + tid] = 0.f;
}

// softmax + partial context; grid (8, 64): x = half*4 + schunk; 128 threads.
__global__ void __launch_bounds__(128)
smctx_k(const int* __restrict__ mask, const float* __restrict__ enc_out,
        float* __restrict__ aw_dst)
{
    int b = blockIdx.y, half = blockIdx.x >> 2, sc = blockIdx.x & 3;
    int tid = threadIdx.x;
    int wid = tid >> 5, lane = tid & 31;
    __shared__ float w[SS];
    __shared__ float red[4];

    float val = (mask[b * SS + tid] == 0) ? -INFINITY : g_scores[b * SS + tid];
    float m = val;
    #pragma unroll
    for (int o = 16; o; o >>= 1) m = fmaxf(m, __shfl_xor_sync(0xffffffffu, m, o));
    if (lane == 0) red[wid] = m;
    __syncthreads();
    if (tid == 0) red[0] = fmaxf(fmaxf(red[0], red[1]), fmaxf(red[2], red[3]));
    __syncthreads();
    float mx = red[0];
    __syncthreads();

    float e = __expf(val - mx);
    float ssum = e;
    #pragma unroll
    for (int o = 16; o; o >>= 1) ssum += __shfl_xor_sync(0xffffffffu, ssum, o);
    if (lane == 0) red[wid] = ssum;
    __syncthreads();
    if (tid == 0) red[0] = red[0] + red[1] + red[2] + red[3];
    __syncthreads();
    float ww = e / red[0];
    w[tid] = ww;
    if (blockIdx.x == 0) aw_dst[b * SS + tid] = ww;
    __syncthreads();

    const int col = half * 512 + tid * 4;
    const float* base = enc_out + (size_t)b * ENC2_ + col;
    float4 a = make_float4(0.f, 0.f, 0.f, 0.f);
    const int s0 = sc * 32;
    #pragma unroll 8
    for (int s = s0; s < s0 + 32; s++) {
        float ws = w[s];
        float4 v = *(const float4*)(base + (size_t)s * BB * ENC2_);
        a.x = fmaf(ws, v.x, a.x); a.y = fmaf(ws, v.y, a.y);
        a.z = fmaf(ws, v.z, a.z); a.w = fmaf(ws, v.w, a.w);
    }
    float* dst = &g_xbuf[b * XKC + EMB_ + col];
    atomicAdd(dst + 0, a.x);
    atomicAdd(dst + 1, a.y);
    atomicAdd(dst + 2, a.z);
    atomicAdd(dst + 3, a.w);
}

// LSTM pointwise; also copies ctx g_xbuf -> g_obuf
__global__ void __launch_bounds__(1024)
lstm_k(const float* __restrict__ b_ih, const float* __restrict__ b_hh,
       const float* __restrict__ cell,
       float* __restrict__ nh_out, float* __restrict__ nc_out)
{
    int b = blockIdx.x, j = threadIdx.x;
    const float* gg = g_gates + (size_t)b * G4;
    float iv = gg[j]             + b_ih[j]             + b_hh[j];
    float fv = gg[j + DECH_]     + b_ih[j + DECH_]     + b_hh[j + DECH_];
    float gv = gg[j + 2 * DECH_] + b_ih[j + 2 * DECH_] + b_hh[j + 2 * DECH_];
    float ov = gg[j + 3 * DECH_] + b_ih[j + 3 * DECH_] + b_hh[j + 3 * DECH_];
    float i_ = 1.f / (1.f + __expf(-iv));
    float f_ = 1.f / (1.f + __expf(-fv));
    float o_ = 1.f / (1.f + __expf(-ov));
    float gt = tanhf(gv);
    float nc = f_ * cell[b * DECH_ + j] + i_ * gt;
    float nh = o_ * tanhf(nc);
    nc_out[b * DECH_ + j] = nc;
    nh_out[b * DECH_ + j] = nh;
    g_obuf[b * OUTK + j] = nh;
    g_obuf[b * OUTK + DECH_ + j] = g_xbuf[b * XKC + EMB_ + j];  // ctx copy
}

// ---------------------------------------------------------------- launcher
extern "C" void kernel_launch(void* const* d_in, const int* in_sizes, int n_in,
                              void* d_out, int out_size)
{
    const int*   input_token = (const int*)  d_in[0];
    const float* hidden      = (const float*)d_in[1];
    const float* cell        = (const float*)d_in[2];
    const float* enc_out     = (const float*)d_in[3];
    const int*   mask        = (const int*)  d_in[4];
    const float* embedding   = (const float*)d_in[5];
    const float* W_enc       = (const float*)d_in[6];
    const float* W_dec       = (const float*)d_in[7];
    const float* v_attn      = (const float*)d_in[8];
    const float* W_ih        = (const float*)d_in[9];
    const float* W_hh        = (const float*)d_in[10];
    const float* b_ih        = (const float*)d_in[11];
    const float* b_hh        = (const float*)d_in[12];
    const float* W_out       = (const float*)d_in[13];
    const float* b_out       = (const float*)d_in[14];

    float* out = (float*)d_out;

    void *p_decp, *p_xbuf, *p_obuf, *p_gates, *p_aux;
    cudaGetSymbolAddress(&p_decp,  g_decp);
    cudaGetSymbolAddress(&p_xbuf,  g_xbuf);
    cudaGetSymbolAddress(&p_obuf,  g_obuf);
    cudaGetSymbolAddress(&p_gates, g_gates);
    cudaGetSymbolAddress(&p_aux,   g_aux);

    cudaFuncSetAttribute(gemm_k<0,0,2>, cudaFuncAttributeMaxDynamicSharedMemorySize, SMEM_BYTES);
    cudaFuncSetAttribute(gemm_k<0,1,3>, cudaFuncAttributeMaxDynamicSharedMemorySize, SMEM_BYTES);
    cudaFuncSetAttribute(gemm_k<1,0,2>, cudaFuncAttributeMaxDynamicSharedMemorySize, SMEM_BYTES);

    bool full = (out_size >= OUT_TOTAL);
    float* nh_dst = full ? out + OFF_NH : (float*)p_aux;
    float* nc_dst = full ? out + OFF_NC : (float*)p_aux + BB * DECH_;
    float* aw_dst = full ? out + OFF_AW : (float*)p_aux + 2 * BB * DECH_;

    // zero split-K accumulators
    cudaMemsetAsync(p_decp,  0, BB * ATTN_ * sizeof(float));
    cudaMemsetAsync(p_gates, 0, BB * G4 * sizeof(float));

    // 1) embedding + hidden copy + zero scores/ctx
    embed_copy_k<<<BB, 256>>>(input_token, embedding, hidden);

    // 2) dec_proj[64,512] = hidden @ W_dec^T (split-K x8, atomic, 3-product fp16)
    gemm_k<0,1,3><<<dim3(ATTN_ / 128, 1, 8), 256, SMEM_BYTES>>>(
        hidden, DECH_, W_dec, DECH_, DECH_, W_dec, DECH_,
        (float*)p_decp, ATTN_, DECH_ / 8, nullptr, nullptr, nullptr);

    // 3) enc_proj GEMM + fused score reduction (2-product fp16)
    gemm_k<1,0,2><<<dim3(ATTN_ / 128, (SS * BB) / 64, 1), 256, SMEM_BYTES>>>(
        enc_out, ENC2_, W_enc, ENC2_, ENC2_, W_enc, ENC2_,
        nullptr, ATTN_, ENC2_, nullptr, (const float*)p_decp, v_attn);

    // 4) softmax + context (s-split x4, col-half x2)
    smctx_k<<<dim3(8, BB), 128>>>(mask, enc_out, aw_dst);

    // 5) gates = [emb|ctx]@W_ih^T + hidden@W_hh^T (split-K x4, 3-product fp16)
    gemm_k<0,1,3><<<dim3(G4 / 128, 1, 4), 256, SMEM_BYTES>>>(
        (const float*)p_xbuf, XKC, W_ih, EMB_ + ENC2_, EMB_ + ENC2_, W_hh, DECH_,
        (float*)p_gates, G4, XKC / 4, nullptr, nullptr, nullptr);

    // 6) LSTM pointwise + ctx copy
    lstm_k<<<BB, DECH_>>>(b_ih, b_hh, cell, nh_dst, nc_dst);

    // 7) output = [nh|ctx|emb] @ W_out^T + b_out (2-product fp16)
    gemm_k<0,0,2><<<dim3(VOCAB_ / 128, 1, 1), 256, SMEM_BYTES>>>(
        (const float*)p_obuf, OUTK, W_out, OUTK, OUTK, W_out, OUTK,
        out + OFF_OUT, VOCAB_, OUTK, b_out, nullptr, nullptr);
}

// round 8
// speedup vs baseline: 3.9702x; 1.0582x over previous
#include <cuda_runtime.h>
#include <cuda_fp16.h>
#include <math.h>
#include <stdint.h>

// ---------------------------------------------------------------- constants
#define BB    64
#define SS    128
#define EMB_  512
#define ENC2_ 1024
#define ATTN_ 512
#define DECH_ 1024
#define VOCAB_ 32000
#define XKC   2560
#define OUTK  2560
#define G4    (4 * DECH_)

#define OFF_OUT 0
#define OFF_NH  (BB * VOCAB_)
#define OFF_NC  (OFF_NH + BB * DECH_)
#define OFF_AW  (OFF_NC + BB * DECH_)
#define OUT_TOTAL (OFF_AW + BB * SS)

// scratch (no allocations allowed)
__device__ __align__(16) float g_decp[BB * ATTN_];
__device__ __align__(16) float g_scores[BB * SS];
__device__ __align__(16) float g_xbuf[BB * XKC];   // [emb|ctx|hidden]
__device__ __align__(16) float g_obuf[BB * OUTK];  // [nh|ctx|emb]
__device__ __align__(16) float g_gates[BB * G4];
__device__ __align__(16) float g_aux[BB * DECH_ * 2 + BB * SS];

// ---------------------------------------------------------------- helpers
#define MMA16816(c, a, b) \
    asm volatile("mma.sync.aligned.m16n8k16.row.col.f32.f16.f16.f32 " \
        "{%0,%1,%2,%3},{%4,%5,%6,%7},{%8,%9},{%0,%1,%2,%3};" \
        : "+f"(c[0]), "+f"(c[1]), "+f"(c[2]), "+f"(c[3]) \
        : "r"(a[0]), "r"(a[1]), "r"(a[2]), "r"(a[3]), "r"(b[0]), "r"(b[1]))

__device__ __forceinline__ void split4(float4 v, uint2& h, uint2& l)
{
    __half2 h01 = __floats2half2_rn(v.x, v.y);
    __half2 h23 = __floats2half2_rn(v.z, v.w);
    float2 f01 = __half22float2(h01);
    float2 f23 = __half22float2(h23);
    __half2 l01 = __floats2half2_rn(v.x - f01.x, v.y - f01.y);
    __half2 l23 = __floats2half2_rn(v.z - f23.x, v.w - f23.y);
    h.x = *(uint32_t*)&h01; h.y = *(uint32_t*)&h23;
    l.x = *(uint32_t*)&l01; l.y = *(uint32_t*)&l23;
}
__device__ __forceinline__ void hi4(float4 v, uint2& h)
{
    __half2 h01 = __floats2half2_rn(v.x, v.y);
    __half2 h23 = __floats2half2_rn(v.z, v.w);
    h.x = *(uint32_t*)&h01; h.y = *(uint32_t*)&h23;
}

// ---------------------------------------------------------------- GEMM
// C[M,N] = A[M,K] @ concatK(B1,B2)[N,K]^T (+bias), fp16 split, fp32 accum.
// NPROD=3: Ah*Bh + Ah*Bl + Al*Bh.  NPROD=2: (Ah+Al)*Bh.  NPROD=1: Ah*Bh.
// BM=64, BN=128, BK=32, 256 thr, 8 warps 2(m)x4(n), warp tile 32x32.
// Split-K via blockIdx.z; ATOM=1 -> atomicAdd epilogue.
// EPI=1: Bahdanau score epilogue (atomicAdd partial tanh-dot into g_scores).
#define BKK 32
#define LDK 40
#define STAGE_A  0
#define STAGE_AL 2560
#define STAGE_B  5120
#define STAGE_BL 10240
#define STAGE_SZ 15360          // fp16 elems per stage
#define SMEM_BYTES (2 * STAGE_SZ * 2)  // 61440

template<int EPI, int ATOM, int NPROD>
__global__ void __launch_bounds__(256, 2)
gemm_k(const float* __restrict__ A, int lda,
       const float* __restrict__ B1, int ldb1, int ksplit,
       const float* __restrict__ B2, int ldb2,
       float* __restrict__ C, int N, int kslice,
       const float* __restrict__ bias,
       const float* __restrict__ decp,
       const float* __restrict__ vat)
{
    extern __shared__ __half sm[];

    const int tid = threadIdx.x;
    const int wid = tid >> 5, lane = tid & 31;
    const int g = lane >> 2, tig = lane & 3;
    const int wm = wid >> 2, wn = wid & 3;
    const int bm = blockIdx.y * 64, bn = blockIdx.x * 128;
    const int k0 = blockIdx.z * kslice;
    const int nk = kslice / BKK;

    const int lrow = tid >> 3;   // 0..31
    const int lkq  = tid & 7;    // float4 slot in BK=32

    float4 pa0, pa1, pb[4];

    // prefetch kt=0
    {
        const int gk = k0 + lkq * 4;
        pa0 = *(const float4*)(A + (size_t)(bm + lrow) * lda + gk);
        pa1 = *(const float4*)(A + (size_t)(bm + lrow + 32) * lda + gk);
        #pragma unroll
        for (int r = 0; r < 4; r++) {
            const int n = bn + lrow + r * 32;
            const float* Bp = (gk < ksplit)
                ? (B1 + (size_t)n * ldb1 + gk)
                : (B2 + (size_t)n * ldb2 + (gk - ksplit));
            pb[r] = *(const float4*)Bp;
        }
    }
    // store stage 0
    {
        __half* st = sm;
        uint2 h, l;
        if (NPROD >= 2) {
            split4(pa0, h, l);
            *(uint2*)&st[STAGE_A  + lrow * LDK + lkq * 4] = h;
            *(uint2*)&st[STAGE_AL + lrow * LDK + lkq * 4] = l;
            split4(pa1, h, l);
            *(uint2*)&st[STAGE_A  + (lrow + 32) * LDK + lkq * 4] = h;
            *(uint2*)&st[STAGE_AL + (lrow + 32) * LDK + lkq * 4] = l;
        } else {
            hi4(pa0, h);
            *(uint2*)&st[STAGE_A  + lrow * LDK + lkq * 4] = h;
            hi4(pa1, h);
            *(uint2*)&st[STAGE_A  + (lrow + 32) * LDK + lkq * 4] = h;
        }
        #pragma unroll
        for (int r = 0; r < 4; r++) {
            if (NPROD == 3) {
                split4(pb[r], h, l);
                *(uint2*)&st[STAGE_B  + (lrow + r * 32) * LDK + lkq * 4] = h;
                *(uint2*)&st[STAGE_BL + (lrow + r * 32) * LDK + lkq * 4] = l;
            } else {
                hi4(pb[r], h);
                *(uint2*)&st[STAGE_B  + (lrow + r * 32) * LDK + lkq * 4] = h;
            }
        }
    }
    __syncthreads();

    float acc[2][4][4];
    #pragma unroll
    for (int mt = 0; mt < 2; mt++)
        #pragma unroll
        for (int nt = 0; nt < 4; nt++)
            #pragma unroll
            for (int q = 0; q < 4; q++) acc[mt][nt][q] = 0.f;

    for (int kt = 0; kt < nk; kt++) {
        const __half* cur = sm + (kt & 1) * STAGE_SZ;
        __half* nxt = sm + ((kt + 1) & 1) * STAGE_SZ;

        // LDG for kt+1
        if (kt + 1 < nk) {
            const int gk = k0 + (kt + 1) * BKK + lkq * 4;
            pa0 = *(const float4*)(A + (size_t)(bm + lrow) * lda + gk);
            pa1 = *(const float4*)(A + (size_t)(bm + lrow + 32) * lda + gk);
            #pragma unroll
            for (int r = 0; r < 4; r++) {
                const int n = bn + lrow + r * 32;
                const float* Bp = (gk < ksplit)
                    ? (B1 + (size_t)n * ldb1 + gk)
                    : (B2 + (size_t)n * ldb2 + (gk - ksplit));
                pb[r] = *(const float4*)Bp;
            }
        }

        // MMAs on current stage
        #pragma unroll
        for (int ks = 0; ks < 2; ks++) {
            const int ko = ks * 16 + tig * 2;
            uint32_t ah[2][4], al[2][4], bh[4][2], bl[4][2];
            #pragma unroll
            for (int mt = 0; mt < 2; mt++) {
                const int r = wm * 32 + mt * 16;
                ah[mt][0] = *(const uint32_t*)&cur[STAGE_A + (r + g) * LDK + ko];
                ah[mt][1] = *(const uint32_t*)&cur[STAGE_A + (r + g + 8) * LDK + ko];
                ah[mt][2] = *(const uint32_t*)&cur[STAGE_A + (r + g) * LDK + ko + 8];
                ah[mt][3] = *(const uint32_t*)&cur[STAGE_A + (r + g + 8) * LDK + ko + 8];
                if (NPROD >= 2) {
                    al[mt][0] = *(const uint32_t*)&cur[STAGE_AL + (r + g) * LDK + ko];
                    al[mt][1] = *(const uint32_t*)&cur[STAGE_AL + (r + g + 8) * LDK + ko];
                    al[mt][2] = *(const uint32_t*)&cur[STAGE_AL + (r + g) * LDK + ko + 8];
                    al[mt][3] = *(const uint32_t*)&cur[STAGE_AL + (r + g + 8) * LDK + ko + 8];
                }
            }
            #pragma unroll
            for (int nt = 0; nt < 4; nt++) {
                const int n = wn * 32 + nt * 8 + g;
                bh[nt][0] = *(const uint32_t*)&cur[STAGE_B + n * LDK + ko];
                bh[nt][1] = *(const uint32_t*)&cur[STAGE_B + n * LDK + ko + 8];
                if (NPROD == 3) {
                    bl[nt][0] = *(const uint32_t*)&cur[STAGE_BL + n * LDK + ko];
                    bl[nt][1] = *(const uint32_t*)&cur[STAGE_BL + n * LDK + ko + 8];
                }
            }
            #pragma unroll
            for (int mt = 0; mt < 2; mt++)
                #pragma unroll
                for (int nt = 0; nt < 4; nt++) {
                    MMA16816(acc[mt][nt], ah[mt], bh[nt]);
                    if (NPROD == 3) MMA16816(acc[mt][nt], ah[mt], bl[nt]);
                    if (NPROD >= 2) MMA16816(acc[mt][nt], al[mt], bh[nt]);
                }
        }

        // convert + STS into other stage
        if (kt + 1 < nk) {
            uint2 h, l;
            if (NPROD >= 2) {
                split4(pa0, h, l);
                *(uint2*)&nxt[STAGE_A  + lrow * LDK + lkq * 4] = h;
                *(uint2*)&nxt[STAGE_AL + lrow * LDK + lkq * 4] = l;
                split4(pa1, h, l);
                *(uint2*)&nxt[STAGE_A  + (lrow + 32) * LDK + lkq * 4] = h;
                *(uint2*)&nxt[STAGE_AL + (lrow + 32) * LDK + lkq * 4] = l;
            } else {
                hi4(pa0, h);
                *(uint2*)&nxt[STAGE_A  + lrow * LDK + lkq * 4] = h;
                hi4(pa1, h);
                *(uint2*)&nxt[STAGE_A  + (lrow + 32) * LDK + lkq * 4] = h;
            }
            #pragma unroll
            for (int r = 0; r < 4; r++) {
                if (NPROD == 3) {
                    split4(pb[r], h, l);
                    *(uint2*)&nxt[STAGE_B  + (lrow + r * 32) * LDK + lkq * 4] = h;
                    *(uint2*)&nxt[STAGE_BL + (lrow + r * 32) * LDK + lkq * 4] = l;
                } else {
                    hi4(pb[r], h);
                    *(uint2*)&nxt[STAGE_B  + (lrow + r * 32) * LDK + lkq * 4] = h;
                }
            }
        }
        __syncthreads();
    }

    if (EPI == 0) {
        #pragma unroll
        for (int mt = 0; mt < 2; mt++) {
            const int gm = bm + wm * 32 + mt * 16 + g;
            #pragma unroll
            for (int nt = 0; nt < 4; nt++) {
                const int gn = bn + wn * 32 + nt * 8 + tig * 2;
                if (ATOM) {
                    atomicAdd(C + (size_t)gm * N + gn,       acc[mt][nt][0]);
                    atomicAdd(C + (size_t)gm * N + gn + 1,   acc[mt][nt][1]);
                    atomicAdd(C + (size_t)(gm + 8) * N + gn,     acc[mt][nt][2]);
                    atomicAdd(C + (size_t)(gm + 8) * N + gn + 1, acc[mt][nt][3]);
                } else {
                    const float b0 = bias ? bias[gn] : 0.f;
                    const float b1 = bias ? bias[gn + 1] : 0.f;
                    *(float2*)(C + (size_t)gm * N + gn) =
                        make_float2(acc[mt][nt][0] + b0, acc[mt][nt][1] + b1);
                    *(float2*)(C + (size_t)(gm + 8) * N + gn) =
                        make_float2(acc[mt][nt][2] + b0, acc[mt][nt][3] + b1);
                }
            }
        }
    } else {
        // score epilogue: row gm -> (b = gm&63, s = gm>>6); c2/c3 are row gm+8
        #pragma unroll
        for (int mt = 0; mt < 2; mt++) {
            const int gm = bm + wm * 32 + mt * 16 + g;
            const int bA = gm & 63;
            const int bBt = (gm + 8) & 63;
            float p0 = 0.f, p8 = 0.f;
            #pragma unroll
            for (int nt = 0; nt < 4; nt++) {
                const int gn = bn + wn * 32 + nt * 8 + tig * 2;
                const float d0a = decp[bA * ATTN_ + gn],  d1a = decp[bA * ATTN_ + gn + 1];
                const float d0b = decp[bBt * ATTN_ + gn], d1b = decp[bBt * ATTN_ + gn + 1];
                const float v0 = vat[gn], v1 = vat[gn + 1];
                p0 += tanhf(acc[mt][nt][0] + d0a) * v0 + tanhf(acc[mt][nt][1] + d1a) * v1;
                p8 += tanhf(acc[mt][nt][2] + d0b) * v0 + tanhf(acc[mt][nt][3] + d1b) * v1;
            }
            p0 += __shfl_xor_sync(0xffffffffu, p0, 1);
            p0 += __shfl_xor_sync(0xffffffffu, p0, 2);
            p8 += __shfl_xor_sync(0xffffffffu, p8, 1);
            p8 += __shfl_xor_sync(0xffffffffu, p8, 2);
            if (tig == 0) {
                atomicAdd(&g_scores[bA * SS + (gm >> 6)], p0);
                atomicAdd(&g_scores[bBt * SS + ((gm + 8) >> 6)], p8);
            }
        }
    }
}

// ---------------------------------------------------------------- embed etc.
__global__ void __launch_bounds__(256)
embed_copy_k(const int* __restrict__ tok, const float* __restrict__ emb,
             const float* __restrict__ hidden)
{
    int b = blockIdx.x, tid = threadIdx.x;
    int t = tok[b];
    const float* src = emb + (size_t)t * EMB_;
    for (int j = tid; j < EMB_; j += 256) {
        float v = (t == 0) ? 0.f : src[j];
        g_xbuf[b * XKC + j] = v;
        g_obuf[b * OUTK + (DECH_ + ENC2_) + j] = v;
    }
    for (int j = tid; j < DECH_; j += 256) {
        g_xbuf[b * XKC + (EMB_ + ENC2_) + j] = hidden[b * DECH_ + j];
        g_xbuf[b * XKC + EMB_ + j] = 0.f;   // ctx accumulator
    }
    if (tid < SS) g_scores[b * SS + tid] = 0.f;
}

// softmax + partial context; grid (16, 64): x = half*8 + schunk; 128 threads.
// Each CTA accumulates 16 s-rows for its 512-col half via atomicAdd.
__global__ void __launch_bounds__(128)
smctx_k(const int* __restrict__ mask, const float* __restrict__ enc_out,
        float* __restrict__ aw_dst)
{
    int b = blockIdx.y, half = blockIdx.x >> 3, sc = blockIdx.x & 7;
    int tid = threadIdx.x;
    int wid = tid >> 5, lane = tid & 31;
    __shared__ float w[SS];
    __shared__ float red[4];

    float val = (mask[b * SS + tid] == 0) ? -INFINITY : g_scores[b * SS + tid];
    float m = val;
    #pragma unroll
    for (int o = 16; o; o >>= 1) m = fmaxf(m, __shfl_xor_sync(0xffffffffu, m, o));
    if (lane == 0) red[wid] = m;
    __syncthreads();
    if (tid == 0) red[0] = fmaxf(fmaxf(red[0], red[1]), fmaxf(red[2], red[3]));
    __syncthreads();
    float mx = red[0];
    __syncthreads();

    float e = __expf(val - mx);
    float ssum = e;
    #pragma unroll
    for (int o = 16; o; o >>= 1) ssum += __shfl_xor_sync(0xffffffffu, ssum, o);
    if (lane == 0) red[wid] = ssum;
    __syncthreads();
    if (tid == 0) red[0] = red[0] + red[1] + red[2] + red[3];
    __syncthreads();
    float ww = e / red[0];
    w[tid] = ww;
    if (blockIdx.x == 0) aw_dst[b * SS + tid] = ww;
    __syncthreads();

    const int col = half * 512 + tid * 4;
    const float* base = enc_out + (size_t)b * ENC2_ + col;
    float4 a = make_float4(0.f, 0.f, 0.f, 0.f);
    const int s0 = sc * 16;
    #pragma unroll 8
    for (int s = s0; s < s0 + 16; s++) {
        float ws = w[s];
        float4 v = *(const float4*)(base + (size_t)s * BB * ENC2_);
        a.x = fmaf(ws, v.x, a.x); a.y = fmaf(ws, v.y, a.y);
        a.z = fmaf(ws, v.z, a.z); a.w = fmaf(ws, v.w, a.w);
    }
    float* dst = &g_xbuf[b * XKC + EMB_ + col];
    atomicAdd(dst + 0, a.x);
    atomicAdd(dst + 1, a.y);
    atomicAdd(dst + 2, a.z);
    atomicAdd(dst + 3, a.w);
}

// LSTM pointwise; also copies ctx g_xbuf -> g_obuf
__global__ void __launch_bounds__(1024)
lstm_k(const float* __restrict__ b_ih, const float* __restrict__ b_hh,
       const float* __restrict__ cell,
       float* __restrict__ nh_out, float* __restrict__ nc_out)
{
    int b = blockIdx.x, j = threadIdx.x;
    const float* gg = g_gates + (size_t)b * G4;
    float iv = gg[j]             + b_ih[j]             + b_hh[j];
    float fv = gg[j + DECH_]     + b_ih[j + DECH_]     + b_hh[j + DECH_];
    float gv = gg[j + 2 * DECH_] + b_ih[j + 2 * DECH_] + b_hh[j + 2 * DECH_];
    float ov = gg[j + 3 * DECH_] + b_ih[j + 3 * DECH_] + b_hh[j + 3 * DECH_];
    float i_ = 1.f / (1.f + __expf(-iv));
    float f_ = 1.f / (1.f + __expf(-fv));
    float o_ = 1.f / (1.f + __expf(-ov));
    float gt = tanhf(gv);
    float nc = f_ * cell[b * DECH_ + j] + i_ * gt;
    float nh = o_ * tanhf(nc);
    nc_out[b * DECH_ + j] = nc;
    nh_out[b * DECH_ + j] = nh;
    g_obuf[b * OUTK + j] = nh;
    g_obuf[b * OUTK + DECH_ + j] = g_xbuf[b * XKC + EMB_ + j];  // ctx copy
}

// ---------------------------------------------------------------- launcher
extern "C" void kernel_launch(void* const* d_in, const int* in_sizes, int n_in,
                              void* d_out, int out_size)
{
    const int*   input_token = (const int*)  d_in[0];
    const float* hidden      = (const float*)d_in[1];
    const float* cell        = (const float*)d_in[2];
    const float* enc_out     = (const float*)d_in[3];
    const int*   mask        = (const int*)  d_in[4];
    const float* embedding   = (const float*)d_in[5];
    const float* W_enc       = (const float*)d_in[6];
    const float* W_dec       = (const float*)d_in[7];
    const float* v_attn      = (const float*)d_in[8];
    const float* W_ih        = (const float*)d_in[9];
    const float* W_hh        = (const float*)d_in[10];
    const float* b_ih        = (const float*)d_in[11];
    const float* b_hh        = (const float*)d_in[12];
    const float* W_out       = (const float*)d_in[13];
    const float* b_out       = (const float*)d_in[14];

    float* out = (float*)d_out;

    void *p_decp, *p_xbuf, *p_obuf, *p_gates, *p_aux;
    cudaGetSymbolAddress(&p_decp,  g_decp);
    cudaGetSymbolAddress(&p_xbuf,  g_xbuf);
    cudaGetSymbolAddress(&p_obuf,  g_obuf);
    cudaGetSymbolAddress(&p_gates, g_gates);
    cudaGetSymbolAddress(&p_aux,   g_aux);

    cudaFuncSetAttribute(gemm_k<0,0,2>, cudaFuncAttributeMaxDynamicSharedMemorySize, SMEM_BYTES);
    cudaFuncSetAttribute(gemm_k<0,1,3>, cudaFuncAttributeMaxDynamicSharedMemorySize, SMEM_BYTES);
    cudaFuncSetAttribute(gemm_k<1,0,1>, cudaFuncAttributeMaxDynamicSharedMemorySize, SMEM_BYTES);

    bool full = (out_size >= OUT_TOTAL);
    float* nh_dst = full ? out + OFF_NH : (float*)p_aux;
    float* nc_dst = full ? out + OFF_NC : (float*)p_aux + BB * DECH_;
    float* aw_dst = full ? out + OFF_AW : (float*)p_aux + 2 * BB * DECH_;

    // zero split-K accumulators
    cudaMemsetAsync(p_decp,  0, BB * ATTN_ * sizeof(float));
    cudaMemsetAsync(p_gates, 0, BB * G4 * sizeof(float));

    // 1) embedding + hidden copy + zero scores/ctx
    embed_copy_k<<<BB, 256>>>(input_token, embedding, hidden);

    // 2) dec_proj[64,512] = hidden @ W_dec^T (split-K x8, atomic, 3-product fp16)
    gemm_k<0,1,3><<<dim3(ATTN_ / 128, 1, 8), 256, SMEM_BYTES>>>(
        hidden, DECH_, W_dec, DECH_, DECH_, W_dec, DECH_,
        (float*)p_decp, ATTN_, DECH_ / 8, nullptr, nullptr, nullptr);

    // 3) enc_proj GEMM + fused score reduction (1-product fp16)
    gemm_k<1,0,1><<<dim3(ATTN_ / 128, (SS * BB) / 64, 1), 256, SMEM_BYTES>>>(
        enc_out, ENC2_, W_enc, ENC2_, ENC2_, W_enc, ENC2_,
        nullptr, ATTN_, ENC2_, nullptr, (const float*)p_decp, v_attn);

    // 4) softmax + context (s-split x8, col-half x2)
    smctx_k<<<dim3(16, BB), 128>>>(mask, enc_out, aw_dst);

    // 5) gates = [emb|ctx]@W_ih^T + hidden@W_hh^T (split-K x4, 3-product fp16)
    gemm_k<0,1,3><<<dim3(G4 / 128, 1, 4), 256, SMEM_BYTES>>>(
        (const float*)p_xbuf, XKC, W_ih, EMB_ + ENC2_, EMB_ + ENC2_, W_hh, DECH_,
        (float*)p_gates, G4, XKC / 4, nullptr, nullptr, nullptr);

    // 6) LSTM pointwise + ctx copy
    lstm_k<<<BB, DECH_>>>(b_ih, b_hh, cell, nh_dst, nc_dst);

    // 7) output = [nh|ctx|emb] @ W_out^T + b_out (2-product fp16)
    gemm_k<0,0,2><<<dim3(VOCAB_ / 128, 1, 1), 256, SMEM_BYTES>>>(
        (const float*)p_obuf, OUTK, W_out, OUTK, OUTK, W_out, OUTK,
        out + OFF_OUT, VOCAB_, OUTK, b_out, nullptr, nullptr);
}

// round 9
// speedup vs baseline: 4.0206x; 1.0127x over previous
#include <cuda_runtime.h>
#include <cuda_fp16.h>
#include <math.h>
#include <stdint.h>

// ---------------------------------------------------------------- constants
#define BB    64
#define SS    128
#define EMB_  512
#define ENC2_ 1024
#define ATTN_ 512
#define DECH_ 1024
#define VOCAB_ 32000
#define XKC   2560
#define OUTK  2560
#define G4    (4 * DECH_)

#define OFF_OUT 0
#define OFF_NH  (BB * VOCAB_)
#define OFF_NC  (OFF_NH + BB * DECH_)
#define OFF_AW  (OFF_NC + BB * DECH_)
#define OUT_TOTAL (OFF_AW + BB * SS)

// scratch (no allocations allowed)
__device__ __align__(16) float g_decp[BB * ATTN_];
__device__ __align__(16) float g_scores[BB * SS];
__device__ __align__(16) float g_xbuf[BB * XKC];   // [emb|ctx|hidden]
__device__ __align__(16) float g_obuf[BB * OUTK];  // [nh|ctx|emb]
__device__ __align__(16) float g_gates[BB * G4];
__device__ __align__(16) float g_aux[BB * DECH_ * 2 + BB * SS];

// ---------------------------------------------------------------- helpers
#define MMA16816(c, a, b) \
    asm volatile("mma.sync.aligned.m16n8k16.row.col.f32.f16.f16.f32 " \
        "{%0,%1,%2,%3},{%4,%5,%6,%7},{%8,%9},{%0,%1,%2,%3};" \
        : "+f"(c[0]), "+f"(c[1]), "+f"(c[2]), "+f"(c[3]) \
        : "r"(a[0]), "r"(a[1]), "r"(a[2]), "r"(a[3]), "r"(b[0]), "r"(b[1]))

#define LDSM4(d0, d1, d2, d3, addr) \
    asm volatile("ldmatrix.sync.aligned.m8n8.x4.shared.b16 {%0,%1,%2,%3}, [%4];" \
        : "=r"(d0), "=r"(d1), "=r"(d2), "=r"(d3) : "r"(addr))

__device__ __forceinline__ uint32_t smem_u32(const void* p) {
    uint32_t a;
    asm("{ .reg .u64 t; cvta.to.shared.u64 t, %1; cvt.u32.u64 %0, t; }" : "=r"(a) : "l"(p));
    return a;
}

__device__ __forceinline__ void split4(float4 v, uint2& h, uint2& l)
{
    __half2 h01 = __floats2half2_rn(v.x, v.y);
    __half2 h23 = __floats2half2_rn(v.z, v.w);
    float2 f01 = __half22float2(h01);
    float2 f23 = __half22float2(h23);
    __half2 l01 = __floats2half2_rn(v.x - f01.x, v.y - f01.y);
    __half2 l23 = __floats2half2_rn(v.z - f23.x, v.w - f23.y);
    h.x = *(uint32_t*)&h01; h.y = *(uint32_t*)&h23;
    l.x = *(uint32_t*)&l01; l.y = *(uint32_t*)&l23;
}
__device__ __forceinline__ void hi4(float4 v, uint2& h)
{
    __half2 h01 = __floats2half2_rn(v.x, v.y);
    __half2 h23 = __floats2half2_rn(v.z, v.w);
    h.x = *(uint32_t*)&h01; h.y = *(uint32_t*)&h23;
}

// ---------------------------------------------------------------- GEMM
// C[M,N] = A[M,K] @ concatK(B1,B2)[N,K]^T (+bias), fp16 split, fp32 accum.
// NPROD=3: Ah*Bh + Ah*Bl + Al*Bh.  NPROD=2: (Ah+Al)*Bh.  NPROD=1: Ah*Bh.
// BM=64, BN=128, BK=32, 256 thr, 8 warps 2(m)x4(n), warp tile 32x32.
// Fragments loaded via ldmatrix.x4 (LDK=40 padding -> conflict-free).
// Split-K via blockIdx.z; ATOM=1 -> atomicAdd epilogue.
// EPI=1: Bahdanau score epilogue (atomicAdd partial tanh-dot into g_scores).
#define BKK 32
#define LDK 40
#define STAGE_A  0
#define STAGE_AL 2560
#define STAGE_B  5120
#define STAGE_BL 10240
#define STAGE_SZ 15360          // fp16 elems per stage
#define SMEM_BYTES (2 * STAGE_SZ * 2)  // 61440

template<int EPI, int ATOM, int NPROD>
__global__ void __launch_bounds__(256, 2)
gemm_k(const float* __restrict__ A, int lda,
       const float* __restrict__ B1, int ldb1, int ksplit,
       const float* __restrict__ B2, int ldb2,
       float* __restrict__ C, int N, int kslice,
       const float* __restrict__ bias,
       const float* __restrict__ decp,
       const float* __restrict__ vat)
{
    extern __shared__ __half sm[];
    const uint32_t sb0 = smem_u32(sm);

    const int tid = threadIdx.x;
    const int wid = tid >> 5, lane = tid & 31;
    const int g = lane >> 2, tig = lane & 3;
    const int wm = wid >> 2, wn = wid & 3;
    const int bm = blockIdx.y * 64, bn = blockIdx.x * 128;
    const int k0 = blockIdx.z * kslice;
    const int nk = kslice / BKK;

    const int lrow = tid >> 3;   // 0..31
    const int lkq  = tid & 7;    // float4 slot in BK=32

    // ldmatrix per-lane addressing components
    const int rowsel = lane & 15;          // row within 16-row A tile
    const int kcsel  = (lane >> 4) * 8;    // 0 or 8 (k sub-column)

    float4 pa0, pa1, pb[4];

    // prefetch kt=0
    {
        const int gk = k0 + lkq * 4;
        pa0 = *(const float4*)(A + (size_t)(bm + lrow) * lda + gk);
        pa1 = *(const float4*)(A + (size_t)(bm + lrow + 32) * lda + gk);
        #pragma unroll
        for (int r = 0; r < 4; r++) {
            const int n = bn + lrow + r * 32;
            const float* Bp = (gk < ksplit)
                ? (B1 + (size_t)n * ldb1 + gk)
                : (B2 + (size_t)n * ldb2 + (gk - ksplit));
            pb[r] = *(const float4*)Bp;
        }
    }
    // store stage 0
    {
        __half* st = sm;
        uint2 h, l;
        if (NPROD >= 2) {
            split4(pa0, h, l);
            *(uint2*)&st[STAGE_A  + lrow * LDK + lkq * 4] = h;
            *(uint2*)&st[STAGE_AL + lrow * LDK + lkq * 4] = l;
            split4(pa1, h, l);
            *(uint2*)&st[STAGE_A  + (lrow + 32) * LDK + lkq * 4] = h;
            *(uint2*)&st[STAGE_AL + (lrow + 32) * LDK + lkq * 4] = l;
        } else {
            hi4(pa0, h);
            *(uint2*)&st[STAGE_A  + lrow * LDK + lkq * 4] = h;
            hi4(pa1, h);
            *(uint2*)&st[STAGE_A  + (lrow + 32) * LDK + lkq * 4] = h;
        }
        #pragma unroll
        for (int r = 0; r < 4; r++) {
            if (NPROD == 3) {
                split4(pb[r], h, l);
                *(uint2*)&st[STAGE_B  + (lrow + r * 32) * LDK + lkq * 4] = h;
                *(uint2*)&st[STAGE_BL + (lrow + r * 32) * LDK + lkq * 4] = l;
            } else {
                hi4(pb[r], h);
                *(uint2*)&st[STAGE_B  + (lrow + r * 32) * LDK + lkq * 4] = h;
            }
        }
    }
    __syncthreads();

    float acc[2][4][4];
    #pragma unroll
    for (int mt = 0; mt < 2; mt++)
        #pragma unroll
        for (int nt = 0; nt < 4; nt++)
            #pragma unroll
            for (int q = 0; q < 4; q++) acc[mt][nt][q] = 0.f;

    for (int kt = 0; kt < nk; kt++) {
        const uint32_t cu = sb0 + (uint32_t)(kt & 1) * (STAGE_SZ * 2);
        __half* nxt = sm + ((kt + 1) & 1) * STAGE_SZ;

        // LDG for kt+1
        if (kt + 1 < nk) {
            const int gk = k0 + (kt + 1) * BKK + lkq * 4;
            pa0 = *(const float4*)(A + (size_t)(bm + lrow) * lda + gk);
            pa1 = *(const float4*)(A + (size_t)(bm + lrow + 32) * lda + gk);
            #pragma unroll
            for (int r = 0; r < 4; r++) {
                const int n = bn + lrow + r * 32;
                const float* Bp = (gk < ksplit)
                    ? (B1 + (size_t)n * ldb1 + gk)
                    : (B2 + (size_t)n * ldb2 + (gk - ksplit));
                pb[r] = *(const float4*)Bp;
            }
        }

        // MMAs on current stage (fragments via ldmatrix.x4)
        #pragma unroll
        for (int ks = 0; ks < 2; ks++) {
            const int ks16 = ks * 16;
            uint32_t ah[2][4], al[2][4], bh[4][2], bl[4][2];
            #pragma unroll
            for (int mt = 0; mt < 2; mt++) {
                const int r = wm * 32 + mt * 16;
                const uint32_t a_addr =
                    cu + 2u * (STAGE_A + (r + rowsel) * LDK + ks16 + kcsel);
                LDSM4(ah[mt][0], ah[mt][1], ah[mt][2], ah[mt][3], a_addr);
                if (NPROD >= 2) {
                    const uint32_t al_addr =
                        cu + 2u * (STAGE_AL + (r + rowsel) * LDK + ks16 + kcsel);
                    LDSM4(al[mt][0], al[mt][1], al[mt][2], al[mt][3], al_addr);
                }
            }
            {
                const uint32_t b_addr =
                    cu + 2u * (STAGE_B + (wn * 32 + lane) * LDK + ks16);
                LDSM4(bh[0][0], bh[1][0], bh[2][0], bh[3][0], b_addr);
                LDSM4(bh[0][1], bh[1][1], bh[2][1], bh[3][1], b_addr + 16);
                if (NPROD == 3) {
                    const uint32_t bl_addr =
                        cu + 2u * (STAGE_BL + (wn * 32 + lane) * LDK + ks16);
                    LDSM4(bl[0][0], bl[1][0], bl[2][0], bl[3][0], bl_addr);
                    LDSM4(bl[0][1], bl[1][1], bl[2][1], bl[3][1], bl_addr + 16);
                }
            }
            #pragma unroll
            for (int mt = 0; mt < 2; mt++)
                #pragma unroll
                for (int nt = 0; nt < 4; nt++) {
                    MMA16816(acc[mt][nt], ah[mt], bh[nt]);
                    if (NPROD == 3) MMA16816(acc[mt][nt], ah[mt], bl[nt]);
                    if (NPROD >= 2) MMA16816(acc[mt][nt], al[mt], bh[nt]);
                }
        }

        // convert + STS into other stage
        if (kt + 1 < nk) {
            uint2 h, l;
            if (NPROD >= 2) {
                split4(pa0, h, l);
                *(uint2*)&nxt[STAGE_A  + lrow * LDK + lkq * 4] = h;
                *(uint2*)&nxt[STAGE_AL + lrow * LDK + lkq * 4] = l;
                split4(pa1, h, l);
                *(uint2*)&nxt[STAGE_A  + (lrow + 32) * LDK + lkq * 4] = h;
                *(uint2*)&nxt[STAGE_AL + (lrow + 32) * LDK + lkq * 4] = l;
            } else {
                hi4(pa0, h);
                *(uint2*)&nxt[STAGE_A  + lrow * LDK + lkq * 4] = h;
                hi4(pa1, h);
                *(uint2*)&nxt[STAGE_A  + (lrow + 32) * LDK + lkq * 4] = h;
            }
            #pragma unroll
            for (int r = 0; r < 4; r++) {
                if (NPROD == 3) {
                    split4(pb[r], h, l);
                    *(uint2*)&nxt[STAGE_B  + (lrow + r * 32) * LDK + lkq * 4] = h;
                    *(uint2*)&nxt[STAGE_BL + (lrow + r * 32) * LDK + lkq * 4] = l;
                } else {
                    hi4(pb[r], h);
                    *(uint2*)&nxt[STAGE_B  + (lrow + r * 32) * LDK + lkq * 4] = h;
                }
            }
        }
        __syncthreads();
    }

    if (EPI == 0) {
        #pragma unroll
        for (int mt = 0; mt < 2; mt++) {
            const int gm = bm + wm * 32 + mt * 16 + g;
            #pragma unroll
            for (int nt = 0; nt < 4; nt++) {
                const int gn = bn + wn * 32 + nt * 8 + tig * 2;
                if (ATOM) {
                    atomicAdd(C + (size_t)gm * N + gn,       acc[mt][nt][0]);
                    atomicAdd(C + (size_t)gm * N + gn + 1,   acc[mt][nt][1]);
                    atomicAdd(C + (size_t)(gm + 8) * N + gn,     acc[mt][nt][2]);
                    atomicAdd(C + (size_t)(gm + 8) * N + gn + 1, acc[mt][nt][3]);
                } else {
                    const float b0 = bias ? bias[gn] : 0.f;
                    const float b1 = bias ? bias[gn + 1] : 0.f;
                    *(float2*)(C + (size_t)gm * N + gn) =
                        make_float2(acc[mt][nt][0] + b0, acc[mt][nt][1] + b1);
                    *(float2*)(C + (size_t)(gm + 8) * N + gn) =
                        make_float2(acc[mt][nt][2] + b0, acc[mt][nt][3] + b1);
                }
            }
        }
    } else {
        // score epilogue: row gm -> (b = gm&63, s = gm>>6); c2/c3 are row gm+8
        #pragma unroll
        for (int mt = 0; mt < 2; mt++) {
            const int gm = bm + wm * 32 + mt * 16 + g;
            const int bA = gm & 63;
            const int bBt = (gm + 8) & 63;
            float p0 = 0.f, p8 = 0.f;
            #pragma unroll
            for (int nt = 0; nt < 4; nt++) {
                const int gn = bn + wn * 32 + nt * 8 + tig * 2;
                const float d0a = decp[bA * ATTN_ + gn],  d1a = decp[bA * ATTN_ + gn + 1];
                const float d0b = decp[bBt * ATTN_ + gn], d1b = decp[bBt * ATTN_ + gn + 1];
                const float v0 = vat[gn], v1 = vat[gn + 1];
                p0 += tanhf(acc[mt][nt][0] + d0a) * v0 + tanhf(acc[mt][nt][1] + d1a) * v1;
                p8 += tanhf(acc[mt][nt][2] + d0b) * v0 + tanhf(acc[mt][nt][3] + d1b) * v1;
            }
            p0 += __shfl_xor_sync(0xffffffffu, p0, 1);
            p0 += __shfl_xor_sync(0xffffffffu, p0, 2);
            p8 += __shfl_xor_sync(0xffffffffu, p8, 1);
            p8 += __shfl_xor_sync(0xffffffffu, p8, 2);
            if (tig == 0) {
                atomicAdd(&g_scores[bA * SS + (gm >> 6)], p0);
                atomicAdd(&g_scores[bBt * SS + ((gm + 8) >> 6)], p8);
            }
        }
    }
}

// ---------------------------------------------------------------- embed etc.
__global__ void __launch_bounds__(256)
embed_copy_k(const int* __restrict__ tok, const float* __restrict__ emb,
             const float* __restrict__ hidden)
{
    int b = blockIdx.x, tid = threadIdx.x;
    int t = tok[b];
    const float* src = emb + (size_t)t * EMB_;
    for (int j = tid; j < EMB_; j += 256) {
        float v = (t == 0) ? 0.f : src[j];
        g_xbuf[b * XKC + j] = v;
        g_obuf[b * OUTK + (DECH_ + ENC2_) + j] = v;
    }
    for (int j = tid; j < DECH_; j += 256) {
        g_xbuf[b * XKC + (EMB_ + ENC2_) + j] = hidden[b * DECH_ + j];
        g_xbuf[b * XKC + EMB_ + j] = 0.f;   // ctx accumulator
    }
    if (tid < SS) g_scores[b * SS + tid] = 0.f;
}

// softmax + partial context; grid (32, 64): x = half*16 + schunk; 128 threads.
// Each CTA accumulates 8 s-rows for its 512-col half via atomicAdd.
__global__ void __launch_bounds__(128)
smctx_k(const int* __restrict__ mask, const float* __restrict__ enc_out,
        float* __restrict__ aw_dst)
{
    int b = blockIdx.y, half = blockIdx.x >> 4, sc = blockIdx.x & 15;
    int tid = threadIdx.x;
    int wid = tid >> 5, lane = tid & 31;
    __shared__ float w[SS];
    __shared__ float red[4];

    float val = (mask[b * SS + tid] == 0) ? -INFINITY : g_scores[b * SS + tid];
    float m = val;
    #pragma unroll
    for (int o = 16; o; o >>= 1) m = fmaxf(m, __shfl_xor_sync(0xffffffffu, m, o));
    if (lane == 0) red[wid] = m;
    __syncthreads();
    if (tid == 0) red[0] = fmaxf(fmaxf(red[0], red[1]), fmaxf(red[2], red[3]));
    __syncthreads();
    float mx = red[0];
    __syncthreads();

    float e = __expf(val - mx);
    float ssum = e;
    #pragma unroll
    for (int o = 16; o; o >>= 1) ssum += __shfl_xor_sync(0xffffffffu, ssum, o);
    if (lane == 0) red[wid] = ssum;
    __syncthreads();
    if (tid == 0) red[0] = red[0] + red[1] + red[2] + red[3];
    __syncthreads();
    float ww = e / red[0];
    w[tid] = ww;
    if (blockIdx.x == 0) aw_dst[b * SS + tid] = ww;
    __syncthreads();

    const int col = half * 512 + tid * 4;
    const float* base = enc_out + (size_t)b * ENC2_ + col;
    float4 a = make_float4(0.f, 0.f, 0.f, 0.f);
    const int s0 = sc * 8;
    #pragma unroll
    for (int s = s0; s < s0 + 8; s++) {
        float ws = w[s];
        float4 v = *(const float4*)(base + (size_t)s * BB * ENC2_);
        a.x = fmaf(ws, v.x, a.x); a.y = fmaf(ws, v.y, a.y);
        a.z = fmaf(ws, v.z, a.z); a.w = fmaf(ws, v.w, a.w);
    }
    float* dst = &g_xbuf[b * XKC + EMB_ + col];
    atomicAdd(dst + 0, a.x);
    atomicAdd(dst + 1, a.y);
    atomicAdd(dst + 2, a.z);
    atomicAdd(dst + 3, a.w);
}

// LSTM pointwise; also copies ctx g_xbuf -> g_obuf
__global__ void __launch_bounds__(1024)
lstm_k(const float* __restrict__ b_ih, const float* __restrict__ b_hh,
       const float* __restrict__ cell,
       float* __restrict__ nh_out, float* __restrict__ nc_out)
{
    int b = blockIdx.x, j = threadIdx.x;
    const float* gg = g_gates + (size_t)b * G4;
    float iv = gg[j]             + b_ih[j]             + b_hh[j];
    float fv = gg[j + DECH_]     + b_ih[j + DECH_]     + b_hh[j + DECH_];
    float gv = gg[j + 2 * DECH_] + b_ih[j + 2 * DECH_] + b_hh[j + 2 * DECH_];
    float ov = gg[j + 3 * DECH_] + b_ih[j + 3 * DECH_] + b_hh[j + 3 * DECH_];
    float i_ = 1.f / (1.f + __expf(-iv));
    float f_ = 1.f / (1.f + __expf(-fv));
    float o_ = 1.f / (1.f + __expf(-ov));
    float gt = tanhf(gv);
    float nc = f_ * cell[b * DECH_ + j] + i_ * gt;
    float nh = o_ * tanhf(nc);
    nc_out[b * DECH_ + j] = nc;
    nh_out[b * DECH_ + j] = nh;
    g_obuf[b * OUTK + j] = nh;
    g_obuf[b * OUTK + DECH_ + j] = g_xbuf[b * XKC + EMB_ + j];  // ctx copy
}

// ---------------------------------------------------------------- launcher
extern "C" void kernel_launch(void* const* d_in, const int* in_sizes, int n_in,
                              void* d_out, int out_size)
{
    const int*   input_token = (const int*)  d_in[0];
    const float* hidden      = (const float*)d_in[1];
    const float* cell        = (const float*)d_in[2];
    const float* enc_out     = (const float*)d_in[3];
    const int*   mask        = (const int*)  d_in[4];
    const float* embedding   = (const float*)d_in[5];
    const float* W_enc       = (const float*)d_in[6];
    const float* W_dec       = (const float*)d_in[7];
    const float* v_attn      = (const float*)d_in[8];
    const float* W_ih        = (const float*)d_in[9];
    const float* W_hh        = (const float*)d_in[10];
    const float* b_ih        = (const float*)d_in[11];
    const float* b_hh        = (const float*)d_in[12];
    const float* W_out       = (const float*)d_in[13];
    const float* b_out       = (const float*)d_in[14];

    float* out = (float*)d_out;

    void *p_decp, *p_xbuf, *p_obuf, *p_gates, *p_aux;
    cudaGetSymbolAddress(&p_decp,  g_decp);
    cudaGetSymbolAddress(&p_xbuf,  g_xbuf);
    cudaGetSymbolAddress(&p_obuf,  g_obuf);
    cudaGetSymbolAddress(&p_gates, g_gates);
    cudaGetSymbolAddress(&p_aux,   g_aux);

    cudaFuncSetAttribute(gemm_k<0,0,2>, cudaFuncAttributeMaxDynamicSharedMemorySize, SMEM_BYTES);
    cudaFuncSetAttribute(gemm_k<0,1,3>, cudaFuncAttributeMaxDynamicSharedMemorySize, SMEM_BYTES);
    cudaFuncSetAttribute(gemm_k<1,0,1>, cudaFuncAttributeMaxDynamicSharedMemorySize, SMEM_BYTES);

    bool full = (out_size >= OUT_TOTAL);
    float* nh_dst = full ? out + OFF_NH : (float*)p_aux;
    float* nc_dst = full ? out + OFF_NC : (float*)p_aux + BB * DECH_;
    float* aw_dst = full ? out + OFF_AW : (float*)p_aux + 2 * BB * DECH_;

    // zero split-K accumulators
    cudaMemsetAsync(p_decp,  0, BB * ATTN_ * sizeof(float));
    cudaMemsetAsync(p_gates, 0, BB * G4 * sizeof(float));

    // 1) embedding + hidden copy + zero scores/ctx
    embed_copy_k<<<BB, 256>>>(input_token, embedding, hidden);

    // 2) dec_proj[64,512] = hidden @ W_dec^T (split-K x8, atomic, 3-product fp16)
    gemm_k<0,1,3><<<dim3(ATTN_ / 128, 1, 8), 256, SMEM_BYTES>>>(
        hidden, DECH_, W_dec, DECH_, DECH_, W_dec, DECH_,
        (float*)p_decp, ATTN_, DECH_ / 8, nullptr, nullptr, nullptr);

    // 3) enc_proj GEMM + fused score reduction (1-product fp16)
    gemm_k<1,0,1><<<dim3(ATTN_ / 128, (SS * BB) / 64, 1), 256, SMEM_BYTES>>>(
        enc_out, ENC2_, W_enc, ENC2_, ENC2_, W_enc, ENC2_,
        nullptr, ATTN_, ENC2_, nullptr, (const float*)p_decp, v_attn);

    // 4) softmax + context (s-split x16, col-half x2)
    smctx_k<<<dim3(32, BB), 128>>>(mask, enc_out, aw_dst);

    // 5) gates = [emb|ctx]@W_ih^T + hidden@W_hh^T (split-K x4, 3-product fp16)
    gemm_k<0,1,3><<<dim3(G4 / 128, 1, 4), 256, SMEM_BYTES>>>(
        (const float*)p_xbuf, XKC, W_ih, EMB_ + ENC2_, EMB_ + ENC2_, W_hh, DECH_,
        (float*)p_gates, G4, XKC / 4, nullptr, nullptr, nullptr);

    // 6) LSTM pointwise + ctx copy
    lstm_k<<<BB, DECH_>>>(b_ih, b_hh, cell, nh_dst, nc_dst);

    // 7) output = [nh|ctx|emb] @ W_out^T + b_out (2-product fp16)
    gemm_k<0,0,2><<<dim3(VOCAB_ / 128, 1, 1), 256, SMEM_BYTES>>>(
        (const float*)p_obuf, OUTK, W_out, OUTK, OUTK, W_out, OUTK,
        out + OFF_OUT, VOCAB_, OUTK, b_out, nullptr, nullptr);
}

// round 10
// speedup vs baseline: 4.2249x; 1.0508x over previous
#include <cuda_runtime.h>
#include <cuda_fp16.h>
#include <math.h>
#include <stdint.h>

// ---------------------------------------------------------------- constants
#define BB    64
#define SS    128
#define EMB_  512
#define ENC2_ 1024
#define ATTN_ 512
#define DECH_ 1024
#define VOCAB_ 32000
#define XKC   2560
#define OUTK  2560
#define G4    (4 * DECH_)

#define OFF_OUT 0
#define OFF_NH  (BB * VOCAB_)
#define OFF_NC  (OFF_NH + BB * DECH_)
#define OFF_AW  (OFF_NC + BB * DECH_)
#define OUT_TOTAL (OFF_AW + BB * SS)

// scratch (no allocations allowed)
__device__ __align__(16) float g_decp[BB * ATTN_];
__device__ __align__(16) float g_scores[BB * SS];
__device__ __align__(16) float g_xbuf[BB * XKC];   // [emb|ctx|hidden]
__device__ __align__(16) float g_obuf[BB * OUTK];  // [nh|ctx|emb]
__device__ __align__(16) float g_gates[BB * G4];
__device__ __align__(16) float g_aux[BB * DECH_ * 2 + BB * SS];

// ---------------------------------------------------------------- helpers
#define MMA16816(c, a, b) \
    asm volatile("mma.sync.aligned.m16n8k16.row.col.f32.f16.f16.f32 " \
        "{%0,%1,%2,%3},{%4,%5,%6,%7},{%8,%9},{%0,%1,%2,%3};" \
        : "+f"(c[0]), "+f"(c[1]), "+f"(c[2]), "+f"(c[3]) \
        : "r"(a[0]), "r"(a[1]), "r"(a[2]), "r"(a[3]), "r"(b[0]), "r"(b[1]))

#define LDSM4(d0, d1, d2, d3, addr) \
    asm volatile("ldmatrix.sync.aligned.m8n8.x4.shared.b16 {%0,%1,%2,%3}, [%4];" \
        : "=r"(d0), "=r"(d1), "=r"(d2), "=r"(d3) : "r"(addr))

__device__ __forceinline__ uint32_t smem_u32(const void* p) {
    uint32_t a;
    asm("{ .reg .u64 t; cvta.to.shared.u64 t, %1; cvt.u32.u64 %0, t; }" : "=r"(a) : "l"(p));
    return a;
}

__device__ __forceinline__ void split4(float4 v, uint2& h, uint2& l)
{
    __half2 h01 = __floats2half2_rn(v.x, v.y);
    __half2 h23 = __floats2half2_rn(v.z, v.w);
    float2 f01 = __half22float2(h01);
    float2 f23 = __half22float2(h23);
    __half2 l01 = __floats2half2_rn(v.x - f01.x, v.y - f01.y);
    __half2 l23 = __floats2half2_rn(v.z - f23.x, v.w - f23.y);
    h.x = *(uint32_t*)&h01; h.y = *(uint32_t*)&h23;
    l.x = *(uint32_t*)&l01; l.y = *(uint32_t*)&l23;
}
__device__ __forceinline__ void hi4(float4 v, uint2& h)
{
    __half2 h01 = __floats2half2_rn(v.x, v.y);
    __half2 h23 = __floats2half2_rn(v.z, v.w);
    h.x = *(uint32_t*)&h01; h.y = *(uint32_t*)&h23;
}

// ---------------------------------------------------------------- GEMM
// C[M,N] = A[M,K] @ concatK(B1,B2)[N,K]^T (+bias), fp16 split, fp32 accum.
// NPROD=3: Ah*Bh + Ah*Bl + Al*Bh.  NPROD=2: (Ah+Al)*Bh.  NPROD=1: Ah*Bh.
// BM=64, BN=128, BK=32, 256 thr, 8 warps 2(m)x4(n), warp tile 32x32.
// Fragments via ldmatrix.x4 (LDK=40 padding -> conflict-free).
// Split-K via blockIdx.z; ATOM=1 -> atomicAdd epilogue.
// EPI=1: Bahdanau score epilogue (atomicAdd partial tanh-dot into g_scores).
#define BKK 32
#define LDK 40
#define STAGE_A  0
#define STAGE_AL 2560
#define STAGE_B  5120
#define STAGE_BL 10240
#define STAGE_SZ 15360          // fp16 elems per stage
#define SMEM_BYTES (2 * STAGE_SZ * 2)  // 61440

template<int EPI, int ATOM, int NPROD>
__global__ void __launch_bounds__(256, 2)
gemm_k(const float* __restrict__ A, int lda,
       const float* __restrict__ B1, int ldb1, int ksplit,
       const float* __restrict__ B2, int ldb2,
       float* __restrict__ C, int N, int kslice,
       const float* __restrict__ bias,
       const float* __restrict__ decp,
       const float* __restrict__ vat)
{
    extern __shared__ __half sm[];
    const uint32_t sb0 = smem_u32(sm);

    const int tid = threadIdx.x;
    const int wid = tid >> 5, lane = tid & 31;
    const int g = lane >> 2, tig = lane & 3;
    const int wm = wid >> 2, wn = wid & 3;
    const int bm = blockIdx.y * 64, bn = blockIdx.x * 128;
    const int k0 = blockIdx.z * kslice;
    const int nk = kslice / BKK;

    const int lrow = tid >> 3;   // 0..31
    const int lkq  = tid & 7;    // float4 slot in BK=32

    const int rowsel = lane & 15;
    const int kcsel  = (lane >> 4) * 8;

    float4 pa0, pa1, pb[4];

    // prefetch kt=0
    {
        const int gk = k0 + lkq * 4;
        pa0 = *(const float4*)(A + (size_t)(bm + lrow) * lda + gk);
        pa1 = *(const float4*)(A + (size_t)(bm + lrow + 32) * lda + gk);
        #pragma unroll
        for (int r = 0; r < 4; r++) {
            const int n = bn + lrow + r * 32;
            const float* Bp = (gk < ksplit)
                ? (B1 + (size_t)n * ldb1 + gk)
                : (B2 + (size_t)n * ldb2 + (gk - ksplit));
            pb[r] = *(const float4*)Bp;
        }
    }
    // store stage 0
    {
        __half* st = sm;
        uint2 h, l;
        if (NPROD >= 2) {
            split4(pa0, h, l);
            *(uint2*)&st[STAGE_A  + lrow * LDK + lkq * 4] = h;
            *(uint2*)&st[STAGE_AL + lrow * LDK + lkq * 4] = l;
            split4(pa1, h, l);
            *(uint2*)&st[STAGE_A  + (lrow + 32) * LDK + lkq * 4] = h;
            *(uint2*)&st[STAGE_AL + (lrow + 32) * LDK + lkq * 4] = l;
        } else {
            hi4(pa0, h);
            *(uint2*)&st[STAGE_A  + lrow * LDK + lkq * 4] = h;
            hi4(pa1, h);
            *(uint2*)&st[STAGE_A  + (lrow + 32) * LDK + lkq * 4] = h;
        }
        #pragma unroll
        for (int r = 0; r < 4; r++) {
            if (NPROD == 3) {
                split4(pb[r], h, l);
                *(uint2*)&st[STAGE_B  + (lrow + r * 32) * LDK + lkq * 4] = h;
                *(uint2*)&st[STAGE_BL + (lrow + r * 32) * LDK + lkq * 4] = l;
            } else {
                hi4(pb[r], h);
                *(uint2*)&st[STAGE_B  + (lrow + r * 32) * LDK + lkq * 4] = h;
            }
        }
    }
    __syncthreads();

    float acc[2][4][4];
    #pragma unroll
    for (int mt = 0; mt < 2; mt++)
        #pragma unroll
        for (int nt = 0; nt < 4; nt++)
            #pragma unroll
            for (int q = 0; q < 4; q++) acc[mt][nt][q] = 0.f;

    for (int kt = 0; kt < nk; kt++) {
        const uint32_t cu = sb0 + (uint32_t)(kt & 1) * (STAGE_SZ * 2);
        __half* nxt = sm + ((kt + 1) & 1) * STAGE_SZ;

        // LDG for kt+1
        if (kt + 1 < nk) {
            const int gk = k0 + (kt + 1) * BKK + lkq * 4;
            pa0 = *(const float4*)(A + (size_t)(bm + lrow) * lda + gk);
            pa1 = *(const float4*)(A + (size_t)(bm + lrow + 32) * lda + gk);
            #pragma unroll
            for (int r = 0; r < 4; r++) {
                const int n = bn + lrow + r * 32;
                const float* Bp = (gk < ksplit)
                    ? (B1 + (size_t)n * ldb1 + gk)
                    : (B2 + (size_t)n * ldb2 + (gk - ksplit));
                pb[r] = *(const float4*)Bp;
            }
        }

        // MMAs on current stage (fragments via ldmatrix.x4)
        #pragma unroll
        for (int ks = 0; ks < 2; ks++) {
            const int ks16 = ks * 16;
            uint32_t ah[2][4], al[2][4], bh[4][2], bl[4][2];
            #pragma unroll
            for (int mt = 0; mt < 2; mt++) {
                const int r = wm * 32 + mt * 16;
                const uint32_t a_addr =
                    cu + 2u * (STAGE_A + (r + rowsel) * LDK + ks16 + kcsel);
                LDSM4(ah[mt][0], ah[mt][1], ah[mt][2], ah[mt][3], a_addr);
                if (NPROD >= 2) {
                    const uint32_t al_addr =
                        cu + 2u * (STAGE_AL + (r + rowsel) * LDK + ks16 + kcsel);
                    LDSM4(al[mt][0], al[mt][1], al[mt][2], al[mt][3], al_addr);
                }
            }
            {
                const uint32_t b_addr =
                    cu + 2u * (STAGE_B + (wn * 32 + lane) * LDK + ks16);
                LDSM4(bh[0][0], bh[1][0], bh[2][0], bh[3][0], b_addr);
                LDSM4(bh[0][1], bh[1][1], bh[2][1], bh[3][1], b_addr + 16);
                if (NPROD == 3) {
                    const uint32_t bl_addr =
                        cu + 2u * (STAGE_BL + (wn * 32 + lane) * LDK + ks16);
                    LDSM4(bl[0][0], bl[1][0], bl[2][0], bl[3][0], bl_addr);
                    LDSM4(bl[0][1], bl[1][1], bl[2][1], bl[3][1], bl_addr + 16);
                }
            }
            #pragma unroll
            for (int mt = 0; mt < 2; mt++)
                #pragma unroll
                for (int nt = 0; nt < 4; nt++) {
                    MMA16816(acc[mt][nt], ah[mt], bh[nt]);
                    if (NPROD == 3) MMA16816(acc[mt][nt], ah[mt], bl[nt]);
                    if (NPROD >= 2) MMA16816(acc[mt][nt], al[mt], bh[nt]);
                }
        }

        // convert + STS into other stage
        if (kt + 1 < nk) {
            uint2 h, l;
            if (NPROD >= 2) {
                split4(pa0, h, l);
                *(uint2*)&nxt[STAGE_A  + lrow * LDK + lkq * 4] = h;
                *(uint2*)&nxt[STAGE_AL + lrow * LDK + lkq * 4] = l;
                split4(pa1, h, l);
                *(uint2*)&nxt[STAGE_A  + (lrow + 32) * LDK + lkq * 4] = h;
                *(uint2*)&nxt[STAGE_AL + (lrow + 32) * LDK + lkq * 4] = l;
            } else {
                hi4(pa0, h);
                *(uint2*)&nxt[STAGE_A  + lrow * LDK + lkq * 4] = h;
                hi4(pa1, h);
                *(uint2*)&nxt[STAGE_A  + (lrow + 32) * LDK + lkq * 4] = h;
            }
            #pragma unroll
            for (int r = 0; r < 4; r++) {
                if (NPROD == 3) {
                    split4(pb[r], h, l);
                    *(uint2*)&nxt[STAGE_B  + (lrow + r * 32) * LDK + lkq * 4] = h;
                    *(uint2*)&nxt[STAGE_BL + (lrow + r * 32) * LDK + lkq * 4] = l;
                } else {
                    hi4(pb[r], h);
                    *(uint2*)&nxt[STAGE_B  + (lrow + r * 32) * LDK + lkq * 4] = h;
                }
            }
        }
        __syncthreads();
    }

    if (EPI == 0) {
        #pragma unroll
        for (int mt = 0; mt < 2; mt++) {
            const int gm = bm + wm * 32 + mt * 16 + g;
            #pragma unroll
            for (int nt = 0; nt < 4; nt++) {
                const int gn = bn + wn * 32 + nt * 8 + tig * 2;
                if (ATOM) {
                    atomicAdd(C + (size_t)gm * N + gn,       acc[mt][nt][0]);
                    atomicAdd(C + (size_t)gm * N + gn + 1,   acc[mt][nt][1]);
                    atomicAdd(C + (size_t)(gm + 8) * N + gn,     acc[mt][nt][2]);
                    atomicAdd(C + (size_t)(gm + 8) * N + gn + 1, acc[mt][nt][3]);
                } else {
                    const float b0 = bias ? bias[gn] : 0.f;
                    const float b1 = bias ? bias[gn + 1] : 0.f;
                    *(float2*)(C + (size_t)gm * N + gn) =
                        make_float2(acc[mt][nt][0] + b0, acc[mt][nt][1] + b1);
                    *(float2*)(C + (size_t)(gm + 8) * N + gn) =
                        make_float2(acc[mt][nt][2] + b0, acc[mt][nt][3] + b1);
                }
            }
        }
    } else {
        // score epilogue: row gm -> (b = gm&63, s = gm>>6); c2/c3 are row gm+8
        #pragma unroll
        for (int mt = 0; mt < 2; mt++) {
            const int gm = bm + wm * 32 + mt * 16 + g;
            const int bA = gm & 63;
            const int bBt = (gm + 8) & 63;
            float p0 = 0.f, p8 = 0.f;
            #pragma unroll
            for (int nt = 0; nt < 4; nt++) {
                const int gn = bn + wn * 32 + nt * 8 + tig * 2;
                const float d0a = decp[bA * ATTN_ + gn],  d1a = decp[bA * ATTN_ + gn + 1];
                const float d0b = decp[bBt * ATTN_ + gn], d1b = decp[bBt * ATTN_ + gn + 1];
                const float v0 = vat[gn], v1 = vat[gn + 1];
                p0 += tanhf(acc[mt][nt][0] + d0a) * v0 + tanhf(acc[mt][nt][1] + d1a) * v1;
                p8 += tanhf(acc[mt][nt][2] + d0b) * v0 + tanhf(acc[mt][nt][3] + d1b) * v1;
            }
            p0 += __shfl_xor_sync(0xffffffffu, p0, 1);
            p0 += __shfl_xor_sync(0xffffffffu, p0, 2);
            p8 += __shfl_xor_sync(0xffffffffu, p8, 1);
            p8 += __shfl_xor_sync(0xffffffffu, p8, 2);
            if (tig == 0) {
                atomicAdd(&g_scores[bA * SS + (gm >> 6)], p0);
                atomicAdd(&g_scores[bBt * SS + ((gm + 8) >> 6)], p8);
            }
        }
    }
}

// ---------------------------------------------------------------- embed etc.
__global__ void __launch_bounds__(256)
embed_copy_k(const int* __restrict__ tok, const float* __restrict__ emb,
             const float* __restrict__ hidden)
{
    int b = blockIdx.x, tid = threadIdx.x;
    int t = tok[b];
    const float* src = emb + (size_t)t * EMB_;
    for (int j = tid; j < EMB_; j += 256) {
        float v = (t == 0) ? 0.f : src[j];
        g_xbuf[b * XKC + j] = v;
        g_obuf[b * OUTK + (DECH_ + ENC2_) + j] = v;
    }
    for (int j = tid; j < DECH_; j += 256) {
        g_xbuf[b * XKC + (EMB_ + ENC2_) + j] = hidden[b * DECH_ + j];
        g_xbuf[b * XKC + EMB_ + j] = 0.f;   // ctx accumulator
    }
    if (tid < SS) g_scores[b * SS + tid] = 0.f;
}

// softmax + partial context; grid (16, 64): x = half*8 + schunk; 128 threads.
// Each CTA accumulates 16 s-rows for its 512-col half via atomicAdd.
__global__ void __launch_bounds__(128)
smctx_k(const int* __restrict__ mask, const float* __restrict__ enc_out,
        float* __restrict__ aw_dst)
{
    int b = blockIdx.y, half = blockIdx.x >> 3, sc = blockIdx.x & 7;
    int tid = threadIdx.x;
    int wid = tid >> 5, lane = tid & 31;
    __shared__ float w[SS];
    __shared__ float red[4];

    float val = (mask[b * SS + tid] == 0) ? -INFINITY : g_scores[b * SS + tid];
    float m = val;
    #pragma unroll
    for (int o = 16; o; o >>= 1) m = fmaxf(m, __shfl_xor_sync(0xffffffffu, m, o));
    if (lane == 0) red[wid] = m;
    __syncthreads();
    if (tid == 0) red[0] = fmaxf(fmaxf(red[0], red[1]), fmaxf(red[2], red[3]));
    __syncthreads();
    float mx = red[0];
    __syncthreads();

    float e = __expf(val - mx);
    float ssum = e;
    #pragma unroll
    for (int o = 16; o; o >>= 1) ssum += __shfl_xor_sync(0xffffffffu, ssum, o);
    if (lane == 0) red[wid] = ssum;
    __syncthreads();
    if (tid == 0) red[0] = red[0] + red[1] + red[2] + red[3];
    __syncthreads();
    float ww = e / red[0];
    w[tid] = ww;
    if (blockIdx.x == 0) aw_dst[b * SS + tid] = ww;
    __syncthreads();

    const int col = half * 512 + tid * 4;
    const float* base = enc_out + (size_t)b * ENC2_ + col;
    float4 a = make_float4(0.f, 0.f, 0.f, 0.f);
    const int s0 = sc * 16;
    #pragma unroll 8
    for (int s = s0; s < s0 + 16; s++) {
        float ws = w[s];
        float4 v = *(const float4*)(base + (size_t)s * BB * ENC2_);
        a.x = fmaf(ws, v.x, a.x); a.y = fmaf(ws, v.y, a.y);
        a.z = fmaf(ws, v.z, a.z); a.w = fmaf(ws, v.w, a.w);
    }
    float* dst = &g_xbuf[b * XKC + EMB_ + col];
    atomicAdd(dst + 0, a.x);
    atomicAdd(dst + 1, a.y);
    atomicAdd(dst + 2, a.z);
    atomicAdd(dst + 3, a.w);
}

// LSTM pointwise; also copies ctx g_xbuf -> g_obuf
__global__ void __launch_bounds__(1024)
lstm_k(const float* __restrict__ b_ih, const float* __restrict__ b_hh,
       const float* __restrict__ cell,
       float* __restrict__ nh_out, float* __restrict__ nc_out)
{
    int b = blockIdx.x, j = threadIdx.x;
    const float* gg = g_gates + (size_t)b * G4;
    float iv = gg[j]             + b_ih[j]             + b_hh[j];
    float fv = gg[j + DECH_]     + b_ih[j + DECH_]     + b_hh[j + DECH_];
    float gv = gg[j + 2 * DECH_] + b_ih[j + 2 * DECH_] + b_hh[j + 2 * DECH_];
    float ov = gg[j + 3 * DECH_] + b_ih[j + 3 * DECH_] + b_hh[j + 3 * DECH_];
    float i_ = 1.f / (1.f + __expf(-iv));
    float f_ = 1.f / (1.f + __expf(-fv));
    float o_ = 1.f / (1.f + __expf(-ov));
    float gt = tanhf(gv);
    float nc = f_ * cell[b * DECH_ + j] + i_ * gt;
    float nh = o_ * tanhf(nc);
    nc_out[b * DECH_ + j] = nc;
    nh_out[b * DECH_ + j] = nh;
    g_obuf[b * OUTK + j] = nh;
    g_obuf[b * OUTK + DECH_ + j] = g_xbuf[b * XKC + EMB_ + j];  // ctx copy
}

// ---------------------------------------------------------------- launcher
extern "C" void kernel_launch(void* const* d_in, const int* in_sizes, int n_in,
                              void* d_out, int out_size)
{
    const int*   input_token = (const int*)  d_in[0];
    const float* hidden      = (const float*)d_in[1];
    const float* cell        = (const float*)d_in[2];
    const float* enc_out     = (const float*)d_in[3];
    const int*   mask        = (const int*)  d_in[4];
    const float* embedding   = (const float*)d_in[5];
    const float* W_enc       = (const float*)d_in[6];
    const float* W_dec       = (const float*)d_in[7];
    const float* v_attn      = (const float*)d_in[8];
    const float* W_ih        = (const float*)d_in[9];
    const float* W_hh        = (const float*)d_in[10];
    const float* b_ih        = (const float*)d_in[11];
    const float* b_hh        = (const float*)d_in[12];
    const float* W_out       = (const float*)d_in[13];
    const float* b_out       = (const float*)d_in[14];

    float* out = (float*)d_out;

    void *p_decp, *p_xbuf, *p_obuf, *p_gates, *p_aux;
    cudaGetSymbolAddress(&p_decp,  g_decp);
    cudaGetSymbolAddress(&p_xbuf,  g_xbuf);
    cudaGetSymbolAddress(&p_obuf,  g_obuf);
    cudaGetSymbolAddress(&p_gates, g_gates);
    cudaGetSymbolAddress(&p_aux,   g_aux);

    cudaFuncSetAttribute(gemm_k<0,0,1>, cudaFuncAttributeMaxDynamicSharedMemorySize, SMEM_BYTES);
    cudaFuncSetAttribute(gemm_k<0,1,2>, cudaFuncAttributeMaxDynamicSharedMemorySize, SMEM_BYTES);
    cudaFuncSetAttribute(gemm_k<1,0,1>, cudaFuncAttributeMaxDynamicSharedMemorySize, SMEM_BYTES);

    bool full = (out_size >= OUT_TOTAL);
    float* nh_dst = full ? out + OFF_NH : (float*)p_aux;
    float* nc_dst = full ? out + OFF_NC : (float*)p_aux + BB * DECH_;
    float* aw_dst = full ? out + OFF_AW : (float*)p_aux + 2 * BB * DECH_;

    // zero split-K accumulators
    cudaMemsetAsync(p_decp,  0, BB * ATTN_ * sizeof(float));
    cudaMemsetAsync(p_gates, 0, BB * G4 * sizeof(float));

    // 1) embedding + hidden copy + zero scores/ctx
    embed_copy_k<<<BB, 256>>>(input_token, embedding, hidden);

    // 2) dec_proj[64,512] = hidden @ W_dec^T (split-K x8, atomic, 2-product)
    gemm_k<0,1,2><<<dim3(ATTN_ / 128, 1, 8), 256, SMEM_BYTES>>>(
        hidden, DECH_, W_dec, DECH_, DECH_, W_dec, DECH_,
        (float*)p_decp, ATTN_, DECH_ / 8, nullptr, nullptr, nullptr);

    // 3) enc_proj GEMM + fused score reduction (1-product)
    gemm_k<1,0,1><<<dim3(ATTN_ / 128, (SS * BB) / 64, 1), 256, SMEM_BYTES>>>(
        enc_out, ENC2_, W_enc, ENC2_, ENC2_, W_enc, ENC2_,
        nullptr, ATTN_, ENC2_, nullptr, (const float*)p_decp, v_attn);

    // 4) softmax + context (s-split x8, col-half x2)
    smctx_k<<<dim3(16, BB), 128>>>(mask, enc_out, aw_dst);

    // 5) gates = [emb|ctx]@W_ih^T + hidden@W_hh^T (split-K x4, 2-product)
    gemm_k<0,1,2><<<dim3(G4 / 128, 1, 4), 256, SMEM_BYTES>>>(
        (const float*)p_xbuf, XKC, W_ih, EMB_ + ENC2_, EMB_ + ENC2_, W_hh, DECH_,
        (float*)p_gates, G4, XKC / 4, nullptr, nullptr, nullptr);

    // 6) LSTM pointwise + ctx copy
    lstm_k<<<BB, DECH_>>>(b_ih, b_hh, cell, nh_dst, nc_dst);

    // 7) output = [nh|ctx|emb] @ W_out^T + b_out (1-product)
    gemm_k<0,0,1><<<dim3(VOCAB_ / 128, 1, 1), 256, SMEM_BYTES>>>(
        (const float*)p_obuf, OUTK, W_out, OUTK, OUTK, W_out, OUTK,
        out + OFF_OUT, VOCAB_, OUTK, b_out, nullptr, nullptr);
}

// round 11
// speedup vs baseline: 4.8234x; 1.1416x over previous
#include <cuda_runtime.h>
#include <cuda_fp16.h>
#include <math.h>
#include <stdint.h>

// ---------------------------------------------------------------- constants
#define BB    64
#define SS    128
#define EMB_  512
#define ENC2_ 1024
#define ATTN_ 512
#define DECH_ 1024
#define VOCAB_ 32000
#define XKC   2560
#define OUTK  2560
#define G4    (4 * DECH_)

#define OFF_OUT 0
#define OFF_NH  (BB * VOCAB_)
#define OFF_NC  (OFF_NH + BB * DECH_)
#define OFF_AW  (OFF_NC + BB * DECH_)
#define OUT_TOTAL (OFF_AW + BB * SS)

// scratch (no allocations allowed)
__device__ __align__(16) float g_decp[BB * ATTN_];
__device__ __align__(16) float g_scores[BB * SS];
__device__ __align__(16) float g_xbuf[BB * XKC];   // [emb|ctx|hidden]
__device__ __align__(16) float g_obuf[BB * OUTK];  // [nh|ctx|emb]
__device__ __align__(16) float g_gates[BB * G4];
__device__ __align__(16) float g_aux[BB * DECH_ * 2 + BB * SS];

// ---------------------------------------------------------------- helpers
#define MMA16816(c, a, b) \
    asm volatile("mma.sync.aligned.m16n8k16.row.col.f32.f16.f16.f32 " \
        "{%0,%1,%2,%3},{%4,%5,%6,%7},{%8,%9},{%0,%1,%2,%3};" \
        : "+f"(c[0]), "+f"(c[1]), "+f"(c[2]), "+f"(c[3]) \
        : "r"(a[0]), "r"(a[1]), "r"(a[2]), "r"(a[3]), "r"(b[0]), "r"(b[1]))

#define LDSM4(d0, d1, d2, d3, addr) \
    asm volatile("ldmatrix.sync.aligned.m8n8.x4.shared.b16 {%0,%1,%2,%3}, [%4];" \
        : "=r"(d0), "=r"(d1), "=r"(d2), "=r"(d3) : "r"(addr))

__device__ __forceinline__ uint32_t smem_u32(const void* p) {
    uint32_t a;
    asm("{ .reg .u64 t; cvta.to.shared.u64 t, %1; cvt.u32.u64 %0, t; }" : "=r"(a) : "l"(p));
    return a;
}

__device__ __forceinline__ void split4(float4 v, uint2& h, uint2& l)
{
    __half2 h01 = __floats2half2_rn(v.x, v.y);
    __half2 h23 = __floats2half2_rn(v.z, v.w);
    float2 f01 = __half22float2(h01);
    float2 f23 = __half22float2(h23);
    __half2 l01 = __floats2half2_rn(v.x - f01.x, v.y - f01.y);
    __half2 l23 = __floats2half2_rn(v.z - f23.x, v.w - f23.y);
    h.x = *(uint32_t*)&h01; h.y = *(uint32_t*)&h23;
    l.x = *(uint32_t*)&l01; l.y = *(uint32_t*)&l23;
}
__device__ __forceinline__ void hi4(float4 v, uint2& h)
{
    __half2 h01 = __floats2half2_rn(v.x, v.y);
    __half2 h23 = __floats2half2_rn(v.z, v.w);
    h.x = *(uint32_t*)&h01; h.y = *(uint32_t*)&h23;
}

// ================================================================ generic GEMM
// (dec_proj / gates / output) — BM=64, BN=128, BK=32, 256 thr.
#define BKK 32
#define LDK 40
#define STAGE_A  0
#define STAGE_AL 2560
#define STAGE_B  5120
#define STAGE_BL 10240
#define STAGE_SZ 15360
#define SMEM_BYTES (2 * STAGE_SZ * 2)  // 61440

template<int EPI, int ATOM, int NPROD>
__global__ void __launch_bounds__(256, 2)
gemm_k(const float* __restrict__ A, int lda,
       const float* __restrict__ B1, int ldb1, int ksplit,
       const float* __restrict__ B2, int ldb2,
       float* __restrict__ C, int N, int kslice,
       const float* __restrict__ bias,
       const float* __restrict__ decp,
       const float* __restrict__ vat)
{
    extern __shared__ __half sm[];
    const uint32_t sb0 = smem_u32(sm);

    const int tid = threadIdx.x;
    const int wid = tid >> 5, lane = tid & 31;
    const int g = lane >> 2, tig = lane & 3;
    const int wm = wid >> 2, wn = wid & 3;
    const int bm = blockIdx.y * 64, bn = blockIdx.x * 128;
    const int k0 = blockIdx.z * kslice;
    const int nk = kslice / BKK;

    const int lrow = tid >> 3;
    const int lkq  = tid & 7;
    const int rowsel = lane & 15;
    const int kcsel  = (lane >> 4) * 8;

    float4 pa0, pa1, pb[4];

    {
        const int gk = k0 + lkq * 4;
        pa0 = *(const float4*)(A + (size_t)(bm + lrow) * lda + gk);
        pa1 = *(const float4*)(A + (size_t)(bm + lrow + 32) * lda + gk);
        #pragma unroll
        for (int r = 0; r < 4; r++) {
            const int n = bn + lrow + r * 32;
            const float* Bp = (gk < ksplit)
                ? (B1 + (size_t)n * ldb1 + gk)
                : (B2 + (size_t)n * ldb2 + (gk - ksplit));
            pb[r] = *(const float4*)Bp;
        }
    }
    {
        __half* st = sm;
        uint2 h, l;
        if (NPROD >= 2) {
            split4(pa0, h, l);
            *(uint2*)&st[STAGE_A  + lrow * LDK + lkq * 4] = h;
            *(uint2*)&st[STAGE_AL + lrow * LDK + lkq * 4] = l;
            split4(pa1, h, l);
            *(uint2*)&st[STAGE_A  + (lrow + 32) * LDK + lkq * 4] = h;
            *(uint2*)&st[STAGE_AL + (lrow + 32) * LDK + lkq * 4] = l;
        } else {
            hi4(pa0, h);
            *(uint2*)&st[STAGE_A  + lrow * LDK + lkq * 4] = h;
            hi4(pa1, h);
            *(uint2*)&st[STAGE_A  + (lrow + 32) * LDK + lkq * 4] = h;
        }
        #pragma unroll
        for (int r = 0; r < 4; r++) {
            if (NPROD == 3) {
                split4(pb[r], h, l);
                *(uint2*)&st[STAGE_B  + (lrow + r * 32) * LDK + lkq * 4] = h;
                *(uint2*)&st[STAGE_BL + (lrow + r * 32) * LDK + lkq * 4] = l;
            } else {
                hi4(pb[r], h);
                *(uint2*)&st[STAGE_B  + (lrow + r * 32) * LDK + lkq * 4] = h;
            }
        }
    }
    __syncthreads();

    float acc[2][4][4];
    #pragma unroll
    for (int mt = 0; mt < 2; mt++)
        #pragma unroll
        for (int nt = 0; nt < 4; nt++)
            #pragma unroll
            for (int q = 0; q < 4; q++) acc[mt][nt][q] = 0.f;

    for (int kt = 0; kt < nk; kt++) {
        const uint32_t cu = sb0 + (uint32_t)(kt & 1) * (STAGE_SZ * 2);
        __half* nxt = sm + ((kt + 1) & 1) * STAGE_SZ;

        if (kt + 1 < nk) {
            const int gk = k0 + (kt + 1) * BKK + lkq * 4;
            pa0 = *(const float4*)(A + (size_t)(bm + lrow) * lda + gk);
            pa1 = *(const float4*)(A + (size_t)(bm + lrow + 32) * lda + gk);
            #pragma unroll
            for (int r = 0; r < 4; r++) {
                const int n = bn + lrow + r * 32;
                const float* Bp = (gk < ksplit)
                    ? (B1 + (size_t)n * ldb1 + gk)
                    : (B2 + (size_t)n * ldb2 + (gk - ksplit));
                pb[r] = *(const float4*)Bp;
            }
        }

        #pragma unroll
        for (int ks = 0; ks < 2; ks++) {
            const int ks16 = ks * 16;
            uint32_t ah[2][4], al[2][4], bh[4][2], bl[4][2];
            #pragma unroll
            for (int mt = 0; mt < 2; mt++) {
                const int r = wm * 32 + mt * 16;
                const uint32_t a_addr =
                    cu + 2u * (STAGE_A + (r + rowsel) * LDK + ks16 + kcsel);
                LDSM4(ah[mt][0], ah[mt][1], ah[mt][2], ah[mt][3], a_addr);
                if (NPROD >= 2) {
                    const uint32_t al_addr =
                        cu + 2u * (STAGE_AL + (r + rowsel) * LDK + ks16 + kcsel);
                    LDSM4(al[mt][0], al[mt][1], al[mt][2], al[mt][3], al_addr);
                }
            }
            {
                const uint32_t b_addr =
                    cu + 2u * (STAGE_B + (wn * 32 + lane) * LDK + ks16);
                LDSM4(bh[0][0], bh[1][0], bh[2][0], bh[3][0], b_addr);
                LDSM4(bh[0][1], bh[1][1], bh[2][1], bh[3][1], b_addr + 16);
                if (NPROD == 3) {
                    const uint32_t bl_addr =
                        cu + 2u * (STAGE_BL + (wn * 32 + lane) * LDK + ks16);
                    LDSM4(bl[0][0], bl[1][0], bl[2][0], bl[3][0], bl_addr);
                    LDSM4(bl[0][1], bl[1][1], bl[2][1], bl[3][1], bl_addr + 16);
                }
            }
            #pragma unroll
            for (int mt = 0; mt < 2; mt++)
                #pragma unroll
                for (int nt = 0; nt < 4; nt++) {
                    MMA16816(acc[mt][nt], ah[mt], bh[nt]);
                    if (NPROD == 3) MMA16816(acc[mt][nt], ah[mt], bl[nt]);
                    if (NPROD >= 2) MMA16816(acc[mt][nt], al[mt], bh[nt]);
                }
        }

        if (kt + 1 < nk) {
            uint2 h, l;
            if (NPROD >= 2) {
                split4(pa0, h, l);
                *(uint2*)&nxt[STAGE_A  + lrow * LDK + lkq * 4] = h;
                *(uint2*)&nxt[STAGE_AL + lrow * LDK + lkq * 4] = l;
                split4(pa1, h, l);
                *(uint2*)&nxt[STAGE_A  + (lrow + 32) * LDK + lkq * 4] = h;
                *(uint2*)&nxt[STAGE_AL + (lrow + 32) * LDK + lkq * 4] = l;
            } else {
                hi4(pa0, h);
                *(uint2*)&nxt[STAGE_A  + lrow * LDK + lkq * 4] = h;
                hi4(pa1, h);
                *(uint2*)&nxt[STAGE_A  + (lrow + 32) * LDK + lkq * 4] = h;
            }
            #pragma unroll
            for (int r = 0; r < 4; r++) {
                if (NPROD == 3) {
                    split4(pb[r], h, l);
                    *(uint2*)&nxt[STAGE_B  + (lrow + r * 32) * LDK + lkq * 4] = h;
                    *(uint2*)&nxt[STAGE_BL + (lrow + r * 32) * LDK + lkq * 4] = l;
                } else {
                    hi4(pb[r], h);
                    *(uint2*)&nxt[STAGE_B  + (lrow + r * 32) * LDK + lkq * 4] = h;
                }
            }
        }
        __syncthreads();
    }

    #pragma unroll
    for (int mt = 0; mt < 2; mt++) {
        const int gm = bm + wm * 32 + mt * 16 + g;
        #pragma unroll
        for (int nt = 0; nt < 4; nt++) {
            const int gn = bn + wn * 32 + nt * 8 + tig * 2;
            if (ATOM) {
                atomicAdd(C + (size_t)gm * N + gn,       acc[mt][nt][0]);
                atomicAdd(C + (size_t)gm * N + gn + 1,   acc[mt][nt][1]);
                atomicAdd(C + (size_t)(gm + 8) * N + gn,     acc[mt][nt][2]);
                atomicAdd(C + (size_t)(gm + 8) * N + gn + 1, acc[mt][nt][3]);
            } else {
                const float b0 = bias ? bias[gn] : 0.f;
                const float b1 = bias ? bias[gn + 1] : 0.f;
                *(float2*)(C + (size_t)gm * N + gn) =
                    make_float2(acc[mt][nt][0] + b0, acc[mt][nt][1] + b1);
                *(float2*)(C + (size_t)(gm + 8) * N + gn) =
                    make_float2(acc[mt][nt][2] + b0, acc[mt][nt][3] + b1);
            }
        }
    }
}

// ================================================================ enc GEMM
// BM=128, BN=256, BK=32, 512 threads, 16 warps 4(m)x4(n), warp tile 32x64.
// 1-product fp16. Fused Bahdanau score epilogue only (no C write).
// Halves L2 traffic vs generic tile (A read 2x instead of 4x, B 64x not 128x).
#define ESTG_A 0
#define ESTG_B 5120                 // A: 128*40
#define ESTG_SZ 15360               // + B: 256*40
#define ESMEM_BYTES (2 * ESTG_SZ * 2)

__global__ void __launch_bounds__(512, 1)
gemm_enc_k(const float* __restrict__ A,      // enc_out [8192, 1024]
           const float* __restrict__ Bm,     // W_enc  [512, 1024]
           const float* __restrict__ decp,
           const float* __restrict__ vat)
{
    extern __shared__ __half sm[];
    const uint32_t sb0 = smem_u32(sm);

    const int tid = threadIdx.x;
    const int wid = tid >> 5, lane = tid & 31;
    const int g = lane >> 2, tig = lane & 3;
    const int wm = wid >> 2, wn = wid & 3;
    const int bm = blockIdx.y * 128, bn = blockIdx.x * 256;

    const int lrow = tid >> 3;   // 0..63
    const int lkq  = tid & 7;
    const int rowsel = lane & 15;
    const int kcsel  = (lane >> 4) * 8;

    const int nk = ENC2_ / BKK;  // 32

    float4 pa0, pa1, pb[4];

    // prefetch kt=0
    {
        const int gk = lkq * 4;
        pa0 = *(const float4*)(A + (size_t)(bm + lrow) * ENC2_ + gk);
        pa1 = *(const float4*)(A + (size_t)(bm + lrow + 64) * ENC2_ + gk);
        #pragma unroll
        for (int r = 0; r < 4; r++)
            pb[r] = *(const float4*)(Bm + (size_t)(bn + lrow + r * 64) * ENC2_ + gk);
    }
    {
        __half* st = sm;
        uint2 h;
        hi4(pa0, h); *(uint2*)&st[ESTG_A + lrow * LDK + lkq * 4] = h;
        hi4(pa1, h); *(uint2*)&st[ESTG_A + (lrow + 64) * LDK + lkq * 4] = h;
        #pragma unroll
        for (int r = 0; r < 4; r++) {
            hi4(pb[r], h);
            *(uint2*)&st[ESTG_B + (lrow + r * 64) * LDK + lkq * 4] = h;
        }
    }
    __syncthreads();

    float acc[2][8][4];
    #pragma unroll
    for (int mt = 0; mt < 2; mt++)
        #pragma unroll
        for (int nt = 0; nt < 8; nt++)
            #pragma unroll
            for (int q = 0; q < 4; q++) acc[mt][nt][q] = 0.f;

    for (int kt = 0; kt < nk; kt++) {
        const uint32_t cu = sb0 + (uint32_t)(kt & 1) * (ESTG_SZ * 2);
        __half* nxt = sm + ((kt + 1) & 1) * ESTG_SZ;

        if (kt + 1 < nk) {
            const int gk = (kt + 1) * BKK + lkq * 4;
            pa0 = *(const float4*)(A + (size_t)(bm + lrow) * ENC2_ + gk);
            pa1 = *(const float4*)(A + (size_t)(bm + lrow + 64) * ENC2_ + gk);
            #pragma unroll
            for (int r = 0; r < 4; r++)
                pb[r] = *(const float4*)(Bm + (size_t)(bn + lrow + r * 64) * ENC2_ + gk);
        }

        #pragma unroll
        for (int ks = 0; ks < 2; ks++) {
            const int ks16 = ks * 16;
            uint32_t ah[2][4], bh[8][2];
            #pragma unroll
            for (int mt = 0; mt < 2; mt++) {
                const int r = wm * 32 + mt * 16;
                const uint32_t a_addr =
                    cu + 2u * (ESTG_A + (r + rowsel) * LDK + ks16 + kcsel);
                LDSM4(ah[mt][0], ah[mt][1], ah[mt][2], ah[mt][3], a_addr);
            }
            {
                const uint32_t b1a =
                    cu + 2u * (ESTG_B + (wn * 64 + lane) * LDK + ks16);
                LDSM4(bh[0][0], bh[1][0], bh[2][0], bh[3][0], b1a);
                LDSM4(bh[0][1], bh[1][1], bh[2][1], bh[3][1], b1a + 16);
                const uint32_t b2a =
                    cu + 2u * (ESTG_B + (wn * 64 + 32 + lane) * LDK + ks16);
                LDSM4(bh[4][0], bh[5][0], bh[6][0], bh[7][0], b2a);
                LDSM4(bh[4][1], bh[5][1], bh[6][1], bh[7][1], b2a + 16);
            }
            #pragma unroll
            for (int mt = 0; mt < 2; mt++)
                #pragma unroll
                for (int nt = 0; nt < 8; nt++)
                    MMA16816(acc[mt][nt], ah[mt], bh[nt]);
        }

        if (kt + 1 < nk) {
            uint2 h;
            hi4(pa0, h); *(uint2*)&nxt[ESTG_A + lrow * LDK + lkq * 4] = h;
            hi4(pa1, h); *(uint2*)&nxt[ESTG_A + (lrow + 64) * LDK + lkq * 4] = h;
            #pragma unroll
            for (int r = 0; r < 4; r++) {
                hi4(pb[r], h);
                *(uint2*)&nxt[ESTG_B + (lrow + r * 64) * LDK + lkq * 4] = h;
            }
        }
        __syncthreads();
    }

    // score epilogue: row gm -> (b = gm&63, s = gm>>6); c2/c3 are row gm+8
    #pragma unroll
    for (int mt = 0; mt < 2; mt++) {
        const int gm = bm + wm * 32 + mt * 16 + g;
        const int bA = gm & 63;
        const int bBt = (gm + 8) & 63;
        float p0 = 0.f, p8 = 0.f;
        #pragma unroll
        for (int nt = 0; nt < 8; nt++) {
            const int gn = bn + wn * 64 + nt * 8 + tig * 2;
            const float d0a = decp[bA * ATTN_ + gn],  d1a = decp[bA * ATTN_ + gn + 1];
            const float d0b = decp[bBt * ATTN_ + gn], d1b = decp[bBt * ATTN_ + gn + 1];
            const float v0 = vat[gn], v1 = vat[gn + 1];
            p0 += tanhf(acc[mt][nt][0] + d0a) * v0 + tanhf(acc[mt][nt][1] + d1a) * v1;
            p8 += tanhf(acc[mt][nt][2] + d0b) * v0 + tanhf(acc[mt][nt][3] + d1b) * v1;
        }
        p0 += __shfl_xor_sync(0xffffffffu, p0, 1);
        p0 += __shfl_xor_sync(0xffffffffu, p0, 2);
        p8 += __shfl_xor_sync(0xffffffffu, p8, 1);
        p8 += __shfl_xor_sync(0xffffffffu, p8, 2);
        if (tig == 0) {
            atomicAdd(&g_scores[bA * SS + (gm >> 6)], p0);
            atomicAdd(&g_scores[bBt * SS + ((gm + 8) >> 6)], p8);
        }
    }
}

// ---------------------------------------------------------------- embed etc.
// Also zeroes scores, ctx accumulator, dec_proj, and gates (split-K targets).
__global__ void __launch_bounds__(256)
embed_copy_k(const int* __restrict__ tok, const float* __restrict__ emb,
             const float* __restrict__ hidden)
{
    int b = blockIdx.x, tid = threadIdx.x;
    int t = tok[b];
    const float* src = emb + (size_t)t * EMB_;
    for (int j = tid; j < EMB_; j += 256) {
        float v = (t == 0) ? 0.f : src[j];
        g_xbuf[b * XKC + j] = v;
        g_obuf[b * OUTK + (DECH_ + ENC2_) + j] = v;
        g_decp[b * ATTN_ + j] = 0.f;   // dec_proj accumulator (ATTN_ == EMB_)
    }
    for (int j = tid; j < DECH_; j += 256) {
        g_xbuf[b * XKC + (EMB_ + ENC2_) + j] = hidden[b * DECH_ + j];
        g_xbuf[b * XKC + EMB_ + j] = 0.f;   // ctx accumulator
    }
    for (int j = tid; j < G4; j += 256)
        g_gates[b * G4 + j] = 0.f;          // gates accumulator
    if (tid < SS) g_scores[b * SS + tid] = 0.f;
}

// softmax + partial context; grid (16, 64): x = half*8 + schunk; 128 threads.
__global__ void __launch_bounds__(128)
smctx_k(const int* __restrict__ mask, const float* __restrict__ enc_out,
        float* __restrict__ aw_dst)
{
    int b = blockIdx.y, half = blockIdx.x >> 3, sc = blockIdx.x & 7;
    int tid = threadIdx.x;
    int wid = tid >> 5, lane = tid & 31;
    __shared__ float w[SS];
    __shared__ float red[4];

    float val = (mask[b * SS + tid] == 0) ? -INFINITY : g_scores[b * SS + tid];
    float m = val;
    #pragma unroll
    for (int o = 16; o; o >>= 1) m = fmaxf(m, __shfl_xor_sync(0xffffffffu, m, o));
    if (lane == 0) red[wid] = m;
    __syncthreads();
    if (tid == 0) red[0] = fmaxf(fmaxf(red[0], red[1]), fmaxf(red[2], red[3]));
    __syncthreads();
    float mx = red[0];
    __syncthreads();

    float e = __expf(val - mx);
    float ssum = e;
    #pragma unroll
    for (int o = 16; o; o >>= 1) ssum += __shfl_xor_sync(0xffffffffu, ssum, o);
    if (lane == 0) red[wid] = ssum;
    __syncthreads();
    if (tid == 0) red[0] = red[0] + red[1] + red[2] + red[3];
    __syncthreads();
    float ww = e / red[0];
    w[tid] = ww;
    if (blockIdx.x == 0) aw_dst[b * SS + tid] = ww;
    __syncthreads();

    const int col = half * 512 + tid * 4;
    const float* base = enc_out + (size_t)b * ENC2_ + col;
    float4 a = make_float4(0.f, 0.f, 0.f, 0.f);
    const int s0 = sc * 16;
    #pragma unroll 8
    for (int s = s0; s < s0 + 16; s++) {
        float ws = w[s];
        float4 v = *(const float4*)(base + (size_t)s * BB * ENC2_);
        a.x = fmaf(ws, v.x, a.x); a.y = fmaf(ws, v.y, a.y);
        a.z = fmaf(ws, v.z, a.z); a.w = fmaf(ws, v.w, a.w);
    }
    float* dst = &g_xbuf[b * XKC + EMB_ + col];
    atomicAdd(dst + 0, a.x);
    atomicAdd(dst + 1, a.y);
    atomicAdd(dst + 2, a.z);
    atomicAdd(dst + 3, a.w);
}

// LSTM pointwise; also copies ctx g_xbuf -> g_obuf
__global__ void __launch_bounds__(1024)
lstm_k(const float* __restrict__ b_ih, const float* __restrict__ b_hh,
       const float* __restrict__ cell,
       float* __restrict__ nh_out, float* __restrict__ nc_out)
{
    int b = blockIdx.x, j = threadIdx.x;
    const float* gg = g_gates + (size_t)b * G4;
    float iv = gg[j]             + b_ih[j]             + b_hh[j];
    float fv = gg[j + DECH_]     + b_ih[j + DECH_]     + b_hh[j + DECH_];
    float gv = gg[j + 2 * DECH_] + b_ih[j + 2 * DECH_] + b_hh[j + 2 * DECH_];
    float ov = gg[j + 3 * DECH_] + b_ih[j + 3 * DECH_] + b_hh[j + 3 * DECH_];
    float i_ = 1.f / (1.f + __expf(-iv));
    float f_ = 1.f / (1.f + __expf(-fv));
    float o_ = 1.f / (1.f + __expf(-ov));
    float gt = tanhf(gv);
    float nc = f_ * cell[b * DECH_ + j] + i_ * gt;
    float nh = o_ * tanhf(nc);
    nc_out[b * DECH_ + j] = nc;
    nh_out[b * DECH_ + j] = nh;
    g_obuf[b * OUTK + j] = nh;
    g_obuf[b * OUTK + DECH_ + j] = g_xbuf[b * XKC + EMB_ + j];  // ctx copy
}

// ---------------------------------------------------------------- launcher
extern "C" void kernel_launch(void* const* d_in, const int* in_sizes, int n_in,
                              void* d_out, int out_size)
{
    const int*   input_token = (const int*)  d_in[0];
    const float* hidden      = (const float*)d_in[1];
    const float* cell        = (const float*)d_in[2];
    const float* enc_out     = (const float*)d_in[3];
    const int*   mask        = (const int*)  d_in[4];
    const float* embedding   = (const float*)d_in[5];
    const float* W_enc       = (const float*)d_in[6];
    const float* W_dec       = (const float*)d_in[7];
    const float* v_attn      = (const float*)d_in[8];
    const float* W_ih        = (const float*)d_in[9];
    const float* W_hh        = (const float*)d_in[10];
    const float* b_ih        = (const float*)d_in[11];
    const float* b_hh        = (const float*)d_in[12];
    const float* W_out       = (const float*)d_in[13];
    const float* b_out       = (const float*)d_in[14];

    float* out = (float*)d_out;

    void *p_decp, *p_xbuf, *p_obuf, *p_gates, *p_aux;
    cudaGetSymbolAddress(&p_decp,  g_decp);
    cudaGetSymbolAddress(&p_xbuf,  g_xbuf);
    cudaGetSymbolAddress(&p_obuf,  g_obuf);
    cudaGetSymbolAddress(&p_gates, g_gates);
    cudaGetSymbolAddress(&p_aux,   g_aux);

    cudaFuncSetAttribute(gemm_k<0,0,1>, cudaFuncAttributeMaxDynamicSharedMemorySize, SMEM_BYTES);
    cudaFuncSetAttribute(gemm_k<0,1,2>, cudaFuncAttributeMaxDynamicSharedMemorySize, SMEM_BYTES);
    cudaFuncSetAttribute(gemm_enc_k, cudaFuncAttributeMaxDynamicSharedMemorySize, ESMEM_BYTES);

    bool full = (out_size >= OUT_TOTAL);
    float* nh_dst = full ? out + OFF_NH : (float*)p_aux;
    float* nc_dst = full ? out + OFF_NC : (float*)p_aux + BB * DECH_;
    float* aw_dst = full ? out + OFF_AW : (float*)p_aux + 2 * BB * DECH_;

    // 1) embedding + hidden copy + zero scores/ctx/decp/gates
    embed_copy_k<<<BB, 256>>>(input_token, embedding, hidden);

    // 2) dec_proj[64,512] = hidden @ W_dec^T (split-K x8, atomic, 2-product)
    gemm_k<0,1,2><<<dim3(ATTN_ / 128, 1, 8), 256, SMEM_BYTES>>>(
        hidden, DECH_, W_dec, DECH_, DECH_, W_dec, DECH_,
        (float*)p_decp, ATTN_, DECH_ / 8, nullptr, nullptr, nullptr);

    // 3) enc_proj GEMM + fused score reduction (big-tile, 1-product)
    gemm_enc_k<<<dim3(ATTN_ / 256, (SS * BB) / 128), 512, ESMEM_BYTES>>>(
        enc_out, W_enc, (const float*)p_decp, v_attn);

    // 4) softmax + context (s-split x8, col-half x2)
    smctx_k<<<dim3(16, BB), 128>>>(mask, enc_out, aw_dst);

    // 5) gates = [emb|ctx]@W_ih^T + hidden@W_hh^T (split-K x4, 2-product)
    gemm_k<0,1,2><<<dim3(G4 / 128, 1, 4), 256, SMEM_BYTES>>>(
        (const float*)p_xbuf, XKC, W_ih, EMB_ + ENC2_, EMB_ + ENC2_, W_hh, DECH_,
        (float*)p_gates, G4, XKC / 4, nullptr, nullptr, nullptr);

    // 6) LSTM pointwise + ctx copy
    lstm_k<<<BB, DECH_>>>(b_ih, b_hh, cell, nh_dst, nc_dst);

    // 7) output = [nh|ctx|emb] @ W_out^T + b_out (1-product)
    gemm_k<0,0,1><<<dim3(VOCAB_ / 128, 1, 1), 256, SMEM_BYTES>>>(
        (const float*)p_obuf, OUTK, W_out, OUTK, OUTK, W_out, OUTK,
        out + OFF_OUT, VOCAB_, OUTK, b_out, nullptr, nullptr);
}

// round 12
// speedup vs baseline: 5.4161x; 1.1229x over previous
#include <cuda_runtime.h>
#include <cuda_fp16.h>
#include <math.h>
#include <stdint.h>

// ---------------------------------------------------------------- constants
#define BB    64
#define SS    128
#define EMB_  512
#define ENC2_ 1024
#define ATTN_ 512
#define DECH_ 1024
#define VOCAB_ 32000
#define XKC   2560
#define OUTK  2560
#define G4    (4 * DECH_)

#define OFF_OUT 0
#define OFF_NH  (BB * VOCAB_)
#define OFF_NC  (OFF_NH + BB * DECH_)
#define OFF_AW  (OFF_NC + BB * DECH_)
#define OUT_TOTAL (OFF_AW + BB * SS)

// scratch (no allocations allowed)
__device__ __align__(16) float g_decp[BB * ATTN_];
__device__ __align__(16) float g_scores[BB * SS];
__device__ __align__(16) float g_xbuf[BB * XKC];   // [emb|ctx|hidden]
__device__ __align__(16) float g_obuf[BB * OUTK];  // [nh|ctx|emb]
__device__ __align__(16) float g_gates[BB * G4];
__device__ __align__(16) float g_aux[BB * DECH_ * 2 + BB * SS];

// ---------------------------------------------------------------- helpers
#define MMA16816(c, a, b) \
    asm volatile("mma.sync.aligned.m16n8k16.row.col.f32.f16.f16.f32 " \
        "{%0,%1,%2,%3},{%4,%5,%6,%7},{%8,%9},{%0,%1,%2,%3};" \
        : "+f"(c[0]), "+f"(c[1]), "+f"(c[2]), "+f"(c[3]) \
        : "r"(a[0]), "r"(a[1]), "r"(a[2]), "r"(a[3]), "r"(b[0]), "r"(b[1]))

#define LDSM4(d0, d1, d2, d3, addr) \
    asm volatile("ldmatrix.sync.aligned.m8n8.x4.shared.b16 {%0,%1,%2,%3}, [%4];" \
        : "=r"(d0), "=r"(d1), "=r"(d2), "=r"(d3) : "r"(addr))

__device__ __forceinline__ uint32_t smem_u32(const void* p) {
    uint32_t a;
    asm("{ .reg .u64 t; cvta.to.shared.u64 t, %1; cvt.u32.u64 %0, t; }" : "=r"(a) : "l"(p));
    return a;
}

__device__ __forceinline__ void split4(float4 v, uint2& h, uint2& l)
{
    __half2 h01 = __floats2half2_rn(v.x, v.y);
    __half2 h23 = __floats2half2_rn(v.z, v.w);
    float2 f01 = __half22float2(h01);
    float2 f23 = __half22float2(h23);
    __half2 l01 = __floats2half2_rn(v.x - f01.x, v.y - f01.y);
    __half2 l23 = __floats2half2_rn(v.z - f23.x, v.w - f23.y);
    h.x = *(uint32_t*)&h01; h.y = *(uint32_t*)&h23;
    l.x = *(uint32_t*)&l01; l.y = *(uint32_t*)&l23;
}
__device__ __forceinline__ void hi4(float4 v, uint2& h)
{
    __half2 h01 = __floats2half2_rn(v.x, v.y);
    __half2 h23 = __floats2half2_rn(v.z, v.w);
    h.x = *(uint32_t*)&h01; h.y = *(uint32_t*)&h23;
}

// ================================================================ generic GEMM
// (dec_proj / gates) — BM=64, BN=128, BK=32, 256 thr.
#define BKK 32
#define LDK 40
#define STAGE_A  0
#define STAGE_AL 2560
#define STAGE_B  5120
#define STAGE_BL 10240
#define STAGE_SZ 15360
#define SMEM_BYTES (2 * STAGE_SZ * 2)  // 61440

template<int EPI, int ATOM, int NPROD>
__global__ void __launch_bounds__(256, 2)
gemm_k(const float* __restrict__ A, int lda,
       const float* __restrict__ B1, int ldb1, int ksplit,
       const float* __restrict__ B2, int ldb2,
       float* __restrict__ C, int N, int kslice,
       const float* __restrict__ bias,
       const float* __restrict__ decp,
       const float* __restrict__ vat)
{
    extern __shared__ __half sm[];
    const uint32_t sb0 = smem_u32(sm);

    const int tid = threadIdx.x;
    const int wid = tid >> 5, lane = tid & 31;
    const int g = lane >> 2, tig = lane & 3;
    const int wm = wid >> 2, wn = wid & 3;
    const int bm = blockIdx.y * 64, bn = blockIdx.x * 128;
    const int k0 = blockIdx.z * kslice;
    const int nk = kslice / BKK;

    const int lrow = tid >> 3;
    const int lkq  = tid & 7;
    const int rowsel = lane & 15;
    const int kcsel  = (lane >> 4) * 8;

    float4 pa0, pa1, pb[4];

    {
        const int gk = k0 + lkq * 4;
        pa0 = *(const float4*)(A + (size_t)(bm + lrow) * lda + gk);
        pa1 = *(const float4*)(A + (size_t)(bm + lrow + 32) * lda + gk);
        #pragma unroll
        for (int r = 0; r < 4; r++) {
            const int n = bn + lrow + r * 32;
            const float* Bp = (gk < ksplit)
                ? (B1 + (size_t)n * ldb1 + gk)
                : (B2 + (size_t)n * ldb2 + (gk - ksplit));
            pb[r] = *(const float4*)Bp;
        }
    }
    {
        __half* st = sm;
        uint2 h, l;
        if (NPROD >= 2) {
            split4(pa0, h, l);
            *(uint2*)&st[STAGE_A  + lrow * LDK + lkq * 4] = h;
            *(uint2*)&st[STAGE_AL + lrow * LDK + lkq * 4] = l;
            split4(pa1, h, l);
            *(uint2*)&st[STAGE_A  + (lrow + 32) * LDK + lkq * 4] = h;
            *(uint2*)&st[STAGE_AL + (lrow + 32) * LDK + lkq * 4] = l;
        } else {
            hi4(pa0, h);
            *(uint2*)&st[STAGE_A  + lrow * LDK + lkq * 4] = h;
            hi4(pa1, h);
            *(uint2*)&st[STAGE_A  + (lrow + 32) * LDK + lkq * 4] = h;
        }
        #pragma unroll
        for (int r = 0; r < 4; r++) {
            if (NPROD == 3) {
                split4(pb[r], h, l);
                *(uint2*)&st[STAGE_B  + (lrow + r * 32) * LDK + lkq * 4] = h;
                *(uint2*)&st[STAGE_BL + (lrow + r * 32) * LDK + lkq * 4] = l;
            } else {
                hi4(pb[r], h);
                *(uint2*)&st[STAGE_B  + (lrow + r * 32) * LDK + lkq * 4] = h;
            }
        }
    }
    __syncthreads();

    float acc[2][4][4];
    #pragma unroll
    for (int mt = 0; mt < 2; mt++)
        #pragma unroll
        for (int nt = 0; nt < 4; nt++)
            #pragma unroll
            for (int q = 0; q < 4; q++) acc[mt][nt][q] = 0.f;

    for (int kt = 0; kt < nk; kt++) {
        const uint32_t cu = sb0 + (uint32_t)(kt & 1) * (STAGE_SZ * 2);
        __half* nxt = sm + ((kt + 1) & 1) * STAGE_SZ;

        if (kt + 1 < nk) {
            const int gk = k0 + (kt + 1) * BKK + lkq * 4;
            pa0 = *(const float4*)(A + (size_t)(bm + lrow) * lda + gk);
            pa1 = *(const float4*)(A + (size_t)(bm + lrow + 32) * lda + gk);
            #pragma unroll
            for (int r = 0; r < 4; r++) {
                const int n = bn + lrow + r * 32;
                const float* Bp = (gk < ksplit)
                    ? (B1 + (size_t)n * ldb1 + gk)
                    : (B2 + (size_t)n * ldb2 + (gk - ksplit));
                pb[r] = *(const float4*)Bp;
            }
        }

        #pragma unroll
        for (int ks = 0; ks < 2; ks++) {
            const int ks16 = ks * 16;
            uint32_t ah[2][4], al[2][4], bh[4][2], bl[4][2];
            #pragma unroll
            for (int mt = 0; mt < 2; mt++) {
                const int r = wm * 32 + mt * 16;
                const uint32_t a_addr =
                    cu + 2u * (STAGE_A + (r + rowsel) * LDK + ks16 + kcsel);
                LDSM4(ah[mt][0], ah[mt][1], ah[mt][2], ah[mt][3], a_addr);
                if (NPROD >= 2) {
                    const uint32_t al_addr =
                        cu + 2u * (STAGE_AL + (r + rowsel) * LDK + ks16 + kcsel);
                    LDSM4(al[mt][0], al[mt][1], al[mt][2], al[mt][3], al_addr);
                }
            }
            {
                const uint32_t b_addr =
                    cu + 2u * (STAGE_B + (wn * 32 + lane) * LDK + ks16);
                LDSM4(bh[0][0], bh[1][0], bh[2][0], bh[3][0], b_addr);
                LDSM4(bh[0][1], bh[1][1], bh[2][1], bh[3][1], b_addr + 16);
                if (NPROD == 3) {
                    const uint32_t bl_addr =
                        cu + 2u * (STAGE_BL + (wn * 32 + lane) * LDK + ks16);
                    LDSM4(bl[0][0], bl[1][0], bl[2][0], bl[3][0], bl_addr);
                    LDSM4(bl[0][1], bl[1][1], bl[2][1], bl[3][1], bl_addr + 16);
                }
            }
            #pragma unroll
            for (int mt = 0; mt < 2; mt++)
                #pragma unroll
                for (int nt = 0; nt < 4; nt++) {
                    MMA16816(acc[mt][nt], ah[mt], bh[nt]);
                    if (NPROD == 3) MMA16816(acc[mt][nt], ah[mt], bl[nt]);
                    if (NPROD >= 2) MMA16816(acc[mt][nt], al[mt], bh[nt]);
                }
        }

        if (kt + 1 < nk) {
            uint2 h, l;
            if (NPROD >= 2) {
                split4(pa0, h, l);
                *(uint2*)&nxt[STAGE_A  + lrow * LDK + lkq * 4] = h;
                *(uint2*)&nxt[STAGE_AL + lrow * LDK + lkq * 4] = l;
                split4(pa1, h, l);
                *(uint2*)&nxt[STAGE_A  + (lrow + 32) * LDK + lkq * 4] = h;
                *(uint2*)&nxt[STAGE_AL + (lrow + 32) * LDK + lkq * 4] = l;
            } else {
                hi4(pa0, h);
                *(uint2*)&nxt[STAGE_A  + lrow * LDK + lkq * 4] = h;
                hi4(pa1, h);
                *(uint2*)&nxt[STAGE_A  + (lrow + 32) * LDK + lkq * 4] = h;
            }
            #pragma unroll
            for (int r = 0; r < 4; r++) {
                if (NPROD == 3) {
                    split4(pb[r], h, l);
                    *(uint2*)&nxt[STAGE_B  + (lrow + r * 32) * LDK + lkq * 4] = h;
                    *(uint2*)&nxt[STAGE_BL + (lrow + r * 32) * LDK + lkq * 4] = l;
                } else {
                    hi4(pb[r], h);
                    *(uint2*)&nxt[STAGE_B  + (lrow + r * 32) * LDK + lkq * 4] = h;
                }
            }
        }
        __syncthreads();
    }

    #pragma unroll
    for (int mt = 0; mt < 2; mt++) {
        const int gm = bm + wm * 32 + mt * 16 + g;
        #pragma unroll
        for (int nt = 0; nt < 4; nt++) {
            const int gn = bn + wn * 32 + nt * 8 + tig * 2;
            if (ATOM) {
                atomicAdd(C + (size_t)gm * N + gn,       acc[mt][nt][0]);
                atomicAdd(C + (size_t)gm * N + gn + 1,   acc[mt][nt][1]);
                atomicAdd(C + (size_t)(gm + 8) * N + gn,     acc[mt][nt][2]);
                atomicAdd(C + (size_t)(gm + 8) * N + gn + 1, acc[mt][nt][3]);
            } else {
                const float b0 = bias ? bias[gn] : 0.f;
                const float b1 = bias ? bias[gn + 1] : 0.f;
                *(float2*)(C + (size_t)gm * N + gn) =
                    make_float2(acc[mt][nt][0] + b0, acc[mt][nt][1] + b1);
                *(float2*)(C + (size_t)(gm + 8) * N + gn) =
                    make_float2(acc[mt][nt][2] + b0, acc[mt][nt][3] + b1);
            }
        }
    }
}

// ================================================================ out GEMM
// M=64 (fixed), BN=128, BK=32, nk=80, 1-product fp16, fp32 accum.
// 2-deep register prefetch: STS of iter j consumes LDGs issued at iter j-2,
// hiding the full DRAM latency (W_out streams at ~327MB once).
#define OSTG_A 0
#define OSTG_B 2560                // A: 64*40 halfs
#define OSTG_SZ 7680               // + B: 128*40 halfs
#define OSMEM_BYTES (2 * OSTG_SZ * 2)   // 30720

#define OUT_LDG(it, s) do { \
    const int gk = (it) * BKK + lkq * 4; \
    a0[s] = *(const float4*)(A + (size_t)lrow * OUTK + gk); \
    a1[s] = *(const float4*)(A + (size_t)(lrow + 32) * OUTK + gk); \
    b4[s][0] = *(const float4*)(Bm + (size_t)(bn + lrow)      * OUTK + gk); \
    b4[s][1] = *(const float4*)(Bm + (size_t)(bn + lrow + 32) * OUTK + gk); \
    b4[s][2] = *(const float4*)(Bm + (size_t)(bn + lrow + 64) * OUTK + gk); \
    b4[s][3] = *(const float4*)(Bm + (size_t)(bn + lrow + 96) * OUTK + gk); \
} while (0)

#define OUT_STS(s, stg) do { \
    __half* st = sm + (stg) * OSTG_SZ; \
    uint2 h; \
    hi4(a0[s], h); *(uint2*)&st[OSTG_A + lrow * LDK + lkq * 4] = h; \
    hi4(a1[s], h); *(uint2*)&st[OSTG_A + (lrow + 32) * LDK + lkq * 4] = h; \
    hi4(b4[s][0], h); *(uint2*)&st[OSTG_B + lrow * LDK + lkq * 4] = h; \
    hi4(b4[s][1], h); *(uint2*)&st[OSTG_B + (lrow + 32) * LDK + lkq * 4] = h; \
    hi4(b4[s][2], h); *(uint2*)&st[OSTG_B + (lrow + 64) * LDK + lkq * 4] = h; \
    hi4(b4[s][3], h); *(uint2*)&st[OSTG_B + (lrow + 96) * LDK + lkq * 4] = h; \
} while (0)

#define OUT_MMA(stg) do { \
    const uint32_t cu = sb0 + (uint32_t)(stg) * (OSTG_SZ * 2); \
    _Pragma("unroll") \
    for (int ks = 0; ks < 2; ks++) { \
        const int ks16 = ks * 16; \
        uint32_t ah[2][4], bh[4][2]; \
        _Pragma("unroll") \
        for (int mt = 0; mt < 2; mt++) { \
            const int r = wm * 32 + mt * 16; \
            const uint32_t a_addr = \
                cu + 2u * (OSTG_A + (r + rowsel) * LDK + ks16 + kcsel); \
            LDSM4(ah[mt][0], ah[mt][1], ah[mt][2], ah[mt][3], a_addr); \
        } \
        { \
            const uint32_t b_addr = \
                cu + 2u * (OSTG_B + (wn * 32 + lane) * LDK + ks16); \
            LDSM4(bh[0][0], bh[1][0], bh[2][0], bh[3][0], b_addr); \
            LDSM4(bh[0][1], bh[1][1], bh[2][1], bh[3][1], b_addr + 16); \
        } \
        _Pragma("unroll") \
        for (int mt = 0; mt < 2; mt++) \
            _Pragma("unroll") \
            for (int nt = 0; nt < 4; nt++) \
                MMA16816(acc[mt][nt], ah[mt], bh[nt]); \
    } \
} while (0)

__global__ void __launch_bounds__(256, 2)
gemm_out_k(const float* __restrict__ A,      // obuf [64, 2560]
           const float* __restrict__ Bm,     // W_out [32000, 2560]
           float* __restrict__ C,            // out [64, 32000]
           const float* __restrict__ bias)
{
    extern __shared__ __half sm[];
    const uint32_t sb0 = smem_u32(sm);

    const int tid = threadIdx.x;
    const int wid = tid >> 5, lane = tid & 31;
    const int g = lane >> 2, tig = lane & 3;
    const int wm = wid >> 2, wn = wid & 3;
    const int bn = blockIdx.x * 128;
    const int nk = OUTK / BKK;   // 80 (even)

    const int lrow = tid >> 3, lkq = tid & 7;
    const int rowsel = lane & 15, kcsel = (lane >> 4) * 8;

    float4 a0[2], a1[2], b4[2][4];

    // prologue: stage0 = iter0; set1 = iter1; set0 = iter2 (in flight)
    OUT_LDG(0, 0);
    OUT_STS(0, 0);
    OUT_LDG(1, 1);
    OUT_LDG(2, 0);
    __syncthreads();

    float acc[2][4][4];
    #pragma unroll
    for (int mt = 0; mt < 2; mt++)
        #pragma unroll
        for (int nt = 0; nt < 4; nt++)
            #pragma unroll
            for (int q = 0; q < 4; q++) acc[mt][nt][q] = 0.f;

    // invariant at top (kt even): stage0 = iter kt, set1 = iter kt+1,
    //                             set0 = iter kt+2 (in flight)
    for (int kt = 0; kt < nk; kt += 2) {
        OUT_MMA(0);                      // iter kt
        OUT_STS(1, 1);                   // iter kt+1 -> stage1
        if (kt + 3 < nk) OUT_LDG(kt + 3, 1);
        __syncthreads();

        OUT_MMA(1);                      // iter kt+1
        if (kt + 2 < nk) {
            OUT_STS(0, 0);               // iter kt+2 -> stage0
            if (kt + 4 < nk) OUT_LDG(kt + 4, 0);
        }
        __syncthreads();
    }

    #pragma unroll
    for (int mt = 0; mt < 2; mt++) {
        const int gm = wm * 32 + mt * 16 + g;
        #pragma unroll
        for (int nt = 0; nt < 4; nt++) {
            const int gn = bn + wn * 32 + nt * 8 + tig * 2;
            const float b0 = bias[gn];
            const float b1 = bias[gn + 1];
            *(float2*)(C + (size_t)gm * VOCAB_ + gn) =
                make_float2(acc[mt][nt][0] + b0, acc[mt][nt][1] + b1);
            *(float2*)(C + (size_t)(gm + 8) * VOCAB_ + gn) =
                make_float2(acc[mt][nt][2] + b0, acc[mt][nt][3] + b1);
        }
    }
}

// ================================================================ enc GEMM
// BM=128, BN=256, BK=32, 512 threads, 16 warps 4(m)x4(n), warp tile 32x64.
// 1-product fp16. Fused Bahdanau score epilogue only (no C write).
#define ESTG_A 0
#define ESTG_B 5120
#define ESTG_SZ 15360
#define ESMEM_BYTES (2 * ESTG_SZ * 2)

__global__ void __launch_bounds__(512, 1)
gemm_enc_k(const float* __restrict__ A,      // enc_out [8192, 1024]
           const float* __restrict__ Bm,     // W_enc  [512, 1024]
           const float* __restrict__ decp,
           const float* __restrict__ vat)
{
    extern __shared__ __half sm[];
    const uint32_t sb0 = smem_u32(sm);

    const int tid = threadIdx.x;
    const int wid = tid >> 5, lane = tid & 31;
    const int g = lane >> 2, tig = lane & 3;
    const int wm = wid >> 2, wn = wid & 3;
    const int bm = blockIdx.y * 128, bn = blockIdx.x * 256;

    const int lrow = tid >> 3;   // 0..63
    const int lkq  = tid & 7;
    const int rowsel = lane & 15;
    const int kcsel  = (lane >> 4) * 8;

    const int nk = ENC2_ / BKK;  // 32

    float4 pa0, pa1, pb[4];

    {
        const int gk = lkq * 4;
        pa0 = *(const float4*)(A + (size_t)(bm + lrow) * ENC2_ + gk);
        pa1 = *(const float4*)(A + (size_t)(bm + lrow + 64) * ENC2_ + gk);
        #pragma unroll
        for (int r = 0; r < 4; r++)
            pb[r] = *(const float4*)(Bm + (size_t)(bn + lrow + r * 64) * ENC2_ + gk);
    }
    {
        __half* st = sm;
        uint2 h;
        hi4(pa0, h); *(uint2*)&st[ESTG_A + lrow * LDK + lkq * 4] = h;
        hi4(pa1, h); *(uint2*)&st[ESTG_A + (lrow + 64) * LDK + lkq * 4] = h;
        #pragma unroll
        for (int r = 0; r < 4; r++) {
            hi4(pb[r], h);
            *(uint2*)&st[ESTG_B + (lrow + r * 64) * LDK + lkq * 4] = h;
        }
    }
    __syncthreads();

    float acc[2][8][4];
    #pragma unroll
    for (int mt = 0; mt < 2; mt++)
        #pragma unroll
        for (int nt = 0; nt < 8; nt++)
            #pragma unroll
            for (int q = 0; q < 4; q++) acc[mt][nt][q] = 0.f;

    for (int kt = 0; kt < nk; kt++) {
        const uint32_t cu = sb0 + (uint32_t)(kt & 1) * (ESTG_SZ * 2);
        __half* nxt = sm + ((kt + 1) & 1) * ESTG_SZ;

        if (kt + 1 < nk) {
            const int gk = (kt + 1) * BKK + lkq * 4;
            pa0 = *(const float4*)(A + (size_t)(bm + lrow) * ENC2_ + gk);
            pa1 = *(const float4*)(A + (size_t)(bm + lrow + 64) * ENC2_ + gk);
            #pragma unroll
            for (int r = 0; r < 4; r++)
                pb[r] = *(const float4*)(Bm + (size_t)(bn + lrow + r * 64) * ENC2_ + gk);
        }

        #pragma unroll
        for (int ks = 0; ks < 2; ks++) {
            const int ks16 = ks * 16;
            uint32_t ah[2][4], bh[8][2];
            #pragma unroll
            for (int mt = 0; mt < 2; mt++) {
                const int r = wm * 32 + mt * 16;
                const uint32_t a_addr =
                    cu + 2u * (ESTG_A + (r + rowsel) * LDK + ks16 + kcsel);
                LDSM4(ah[mt][0], ah[mt][1], ah[mt][2], ah[mt][3], a_addr);
            }
            {
                const uint32_t b1a =
                    cu + 2u * (ESTG_B + (wn * 64 + lane) * LDK + ks16);
                LDSM4(bh[0][0], bh[1][0], bh[2][0], bh[3][0], b1a);
                LDSM4(bh[0][1], bh[1][1], bh[2][1], bh[3][1], b1a + 16);
                const uint32_t b2a =
                    cu + 2u * (ESTG_B + (wn * 64 + 32 + lane) * LDK + ks16);
                LDSM4(bh[4][0], bh[5][0], bh[6][0], bh[7][0], b2a);
                LDSM4(bh[4][1], bh[5][1], bh[6][1], bh[7][1], b2a + 16);
            }
            #pragma unroll
            for (int mt = 0; mt < 2; mt++)
                #pragma unroll
                for (int nt = 0; nt < 8; nt++)
                    MMA16816(acc[mt][nt], ah[mt], bh[nt]);
        }

        if (kt + 1 < nk) {
            uint2 h;
            hi4(pa0, h); *(uint2*)&nxt[ESTG_A + lrow * LDK + lkq * 4] = h;
            hi4(pa1, h); *(uint2*)&nxt[ESTG_A + (lrow + 64) * LDK + lkq * 4] = h;
            #pragma unroll
            for (int r = 0; r < 4; r++) {
                hi4(pb[r], h);
                *(uint2*)&nxt[ESTG_B + (lrow + r * 64) * LDK + lkq * 4] = h;
            }
        }
        __syncthreads();
    }

    // score epilogue: row gm -> (b = gm&63, s = gm>>6); c2/c3 are row gm+8
    #pragma unroll
    for (int mt = 0; mt < 2; mt++) {
        const int gm = bm + wm * 32 + mt * 16 + g;
        const int bA = gm & 63;
        const int bBt = (gm + 8) & 63;
        float p0 = 0.f, p8 = 0.f;
        #pragma unroll
        for (int nt = 0; nt < 8; nt++) {
            const int gn = bn + wn * 64 + nt * 8 + tig * 2;
            const float d0a = decp[bA * ATTN_ + gn],  d1a = decp[bA * ATTN_ + gn + 1];
            const float d0b = decp[bBt * ATTN_ + gn], d1b = decp[bBt * ATTN_ + gn + 1];
            const float v0 = vat[gn], v1 = vat[gn + 1];
            p0 += tanhf(acc[mt][nt][0] + d0a) * v0 + tanhf(acc[mt][nt][1] + d1a) * v1;
            p8 += tanhf(acc[mt][nt][2] + d0b) * v0 + tanhf(acc[mt][nt][3] + d1b) * v1;
        }
        p0 += __shfl_xor_sync(0xffffffffu, p0, 1);
        p0 += __shfl_xor_sync(0xffffffffu, p0, 2);
        p8 += __shfl_xor_sync(0xffffffffu, p8, 1);
        p8 += __shfl_xor_sync(0xffffffffu, p8, 2);
        if (tig == 0) {
            atomicAdd(&g_scores[bA * SS + (gm >> 6)], p0);
            atomicAdd(&g_scores[bBt * SS + ((gm + 8) >> 6)], p8);
        }
    }
}

// ---------------------------------------------------------------- embed etc.
__global__ void __launch_bounds__(256)
embed_copy_k(const int* __restrict__ tok, const float* __restrict__ emb,
             const float* __restrict__ hidden)
{
    int b = blockIdx.x, tid = threadIdx.x;
    int t = tok[b];
    const float* src = emb + (size_t)t * EMB_;
    for (int j = tid; j < EMB_; j += 256) {
        float v = (t == 0) ? 0.f : src[j];
        g_xbuf[b * XKC + j] = v;
        g_obuf[b * OUTK + (DECH_ + ENC2_) + j] = v;
        g_decp[b * ATTN_ + j] = 0.f;
    }
    for (int j = tid; j < DECH_; j += 256) {
        g_xbuf[b * XKC + (EMB_ + ENC2_) + j] = hidden[b * DECH_ + j];
        g_xbuf[b * XKC + EMB_ + j] = 0.f;
    }
    for (int j = tid; j < G4; j += 256)
        g_gates[b * G4 + j] = 0.f;
    if (tid < SS) g_scores[b * SS + tid] = 0.f;
}

// softmax + partial context; grid (16, 64): x = half*8 + schunk; 128 threads.
__global__ void __launch_bounds__(128)
smctx_k(const int* __restrict__ mask, const float* __restrict__ enc_out,
        float* __restrict__ aw_dst)
{
    int b = blockIdx.y, half = blockIdx.x >> 3, sc = blockIdx.x & 7;
    int tid = threadIdx.x;
    int wid = tid >> 5, lane = tid & 31;
    __shared__ float w[SS];
    __shared__ float red[4];

    float val = (mask[b * SS + tid] == 0) ? -INFINITY : g_scores[b * SS + tid];
    float m = val;
    #pragma unroll
    for (int o = 16; o; o >>= 1) m = fmaxf(m, __shfl_xor_sync(0xffffffffu, m, o));
    if (lane == 0) red[wid] = m;
    __syncthreads();
    if (tid == 0) red[0] = fmaxf(fmaxf(red[0], red[1]), fmaxf(red[2], red[3]));
    __syncthreads();
    float mx = red[0];
    __syncthreads();

    float e = __expf(val - mx);
    float ssum = e;
    #pragma unroll
    for (int o = 16; o; o >>= 1) ssum += __shfl_xor_sync(0xffffffffu, ssum, o);
    if (lane == 0) red[wid] = ssum;
    __syncthreads();
    if (tid == 0) red[0] = red[0] + red[1] + red[2] + red[3];
    __syncthreads();
    float ww = e / red[0];
    w[tid] = ww;
    if (blockIdx.x == 0) aw_dst[b * SS + tid] = ww;
    __syncthreads();

    const int col = half * 512 + tid * 4;
    const float* base = enc_out + (size_t)b * ENC2_ + col;
    float4 a = make_float4(0.f, 0.f, 0.f, 0.f);
    const int s0 = sc * 16;
    #pragma unroll 8
    for (int s = s0; s < s0 + 16; s++) {
        float ws = w[s];
        float4 v = *(const float4*)(base + (size_t)s * BB * ENC2_);
        a.x = fmaf(ws, v.x, a.x); a.y = fmaf(ws, v.y, a.y);
        a.z = fmaf(ws, v.z, a.z); a.w = fmaf(ws, v.w, a.w);
    }
    float* dst = &g_xbuf[b * XKC + EMB_ + col];
    atomicAdd(dst + 0, a.x);
    atomicAdd(dst + 1, a.y);
    atomicAdd(dst + 2, a.z);
    atomicAdd(dst + 3, a.w);
}

// LSTM pointwise; also copies ctx g_xbuf -> g_obuf
__global__ void __launch_bounds__(1024)
lstm_k(const float* __restrict__ b_ih, const float* __restrict__ b_hh,
       const float* __restrict__ cell,
       float* __restrict__ nh_out, float* __restrict__ nc_out)
{
    int b = blockIdx.x, j = threadIdx.x;
    const float* gg = g_gates + (size_t)b * G4;
    float iv = gg[j]             + b_ih[j]             + b_hh[j];
    float fv = gg[j + DECH_]     + b_ih[j + DECH_]     + b_hh[j + DECH_];
    float gv = gg[j + 2 * DECH_] + b_ih[j + 2 * DECH_] + b_hh[j + 2 * DECH_];
    float ov = gg[j + 3 * DECH_] + b_ih[j + 3 * DECH_] + b_hh[j + 3 * DECH_];
    float i_ = 1.f / (1.f + __expf(-iv));
    float f_ = 1.f / (1.f + __expf(-fv));
    float o_ = 1.f / (1.f + __expf(-ov));
    float gt = tanhf(gv);
    float nc = f_ * cell[b * DECH_ + j] + i_ * gt;
    float nh = o_ * tanhf(nc);
    nc_out[b * DECH_ + j] = nc;
    nh_out[b * DECH_ + j] = nh;
    g_obuf[b * OUTK + j] = nh;
    g_obuf[b * OUTK + DECH_ + j] = g_xbuf[b * XKC + EMB_ + j];
}

// ---------------------------------------------------------------- launcher
extern "C" void kernel_launch(void* const* d_in, const int* in_sizes, int n_in,
                              void* d_out, int out_size)
{
    const int*   input_token = (const int*)  d_in[0];
    const float* hidden      = (const float*)d_in[1];
    const float* cell        = (const float*)d_in[2];
    const float* enc_out     = (const float*)d_in[3];
    const int*   mask        = (const int*)  d_in[4];
    const float* embedding   = (const float*)d_in[5];
    const float* W_enc       = (const float*)d_in[6];
    const float* W_dec       = (const float*)d_in[7];
    const float* v_attn      = (const float*)d_in[8];
    const float* W_ih        = (const float*)d_in[9];
    const float* W_hh        = (const float*)d_in[10];
    const float* b_ih        = (const float*)d_in[11];
    const float* b_hh        = (const float*)d_in[12];
    const float* W_out       = (const float*)d_in[13];
    const float* b_out       = (const float*)d_in[14];

    float* out = (float*)d_out;

    void *p_decp, *p_xbuf, *p_obuf, *p_gates, *p_aux;
    cudaGetSymbolAddress(&p_decp,  g_decp);
    cudaGetSymbolAddress(&p_xbuf,  g_xbuf);
    cudaGetSymbolAddress(&p_obuf,  g_obuf);
    cudaGetSymbolAddress(&p_gates, g_gates);
    cudaGetSymbolAddress(&p_aux,   g_aux);

    cudaFuncSetAttribute(gemm_k<0,1,2>, cudaFuncAttributeMaxDynamicSharedMemorySize, SMEM_BYTES);
    cudaFuncSetAttribute(gemm_enc_k, cudaFuncAttributeMaxDynamicSharedMemorySize, ESMEM_BYTES);
    cudaFuncSetAttribute(gemm_out_k, cudaFuncAttributeMaxDynamicSharedMemorySize, OSMEM_BYTES);

    bool full = (out_size >= OUT_TOTAL);
    float* nh_dst = full ? out + OFF_NH : (float*)p_aux;
    float* nc_dst = full ? out + OFF_NC : (float*)p_aux + BB * DECH_;
    float* aw_dst = full ? out + OFF_AW : (float*)p_aux + 2 * BB * DECH_;

    // 1) embedding + hidden copy + zero scores/ctx/decp/gates
    embed_copy_k<<<BB, 256>>>(input_token, embedding, hidden);

    // 2) dec_proj[64,512] = hidden @ W_dec^T (split-K x8, atomic, 2-product)
    gemm_k<0,1,2><<<dim3(ATTN_ / 128, 1, 8), 256, SMEM_BYTES>>>(
        hidden, DECH_, W_dec, DECH_, DECH_, W_dec, DECH_,
        (float*)p_decp, ATTN_, DECH_ / 8, nullptr, nullptr, nullptr);

    // 3) enc_proj GEMM + fused score reduction (big-tile, 1-product)
    gemm_enc_k<<<dim3(ATTN_ / 256, (SS * BB) / 128), 512, ESMEM_BYTES>>>(
        enc_out, W_enc, (const float*)p_decp, v_attn);

    // 4) softmax + context (s-split x8, col-half x2)
    smctx_k<<<dim3(16, BB), 128>>>(mask, enc_out, aw_dst);

    // 5) gates = [emb|ctx]@W_ih^T + hidden@W_hh^T (split-K x4, 2-product)
    gemm_k<0,1,2><<<dim3(G4 / 128, 1, 4), 256, SMEM_BYTES>>>(
        (const float*)p_xbuf, XKC, W_ih, EMB_ + ENC2_, EMB_ + ENC2_, W_hh, DECH_,
        (float*)p_gates, G4, XKC / 4, nullptr, nullptr, nullptr);

    // 6) LSTM pointwise + ctx copy
    lstm_k<<<BB, DECH_>>>(b_ih, b_hh, cell, nh_dst, nc_dst);

    // 7) output = [nh|ctx|emb] @ W_out^T + b_out (1-product, 2-deep prefetch)
    gemm_out_k<<<dim3(VOCAB_ / 128), 256, OSMEM_BYTES>>>(
        (const float*)p_obuf, W_out, out + OFF_OUT, b_out);
}

// round 13
// speedup vs baseline: 5.4394x; 1.0043x over previous
#include <cuda_runtime.h>
#include <cuda_fp16.h>
#include <math.h>
#include <stdint.h>

// ---------------------------------------------------------------- constants
#define BB    64
#define SS    128
#define EMB_  512
#define ENC2_ 1024
#define ATTN_ 512
#define DECH_ 1024
#define VOCAB_ 32000
#define XKC   2560
#define OUTK  2560
#define G4    (4 * DECH_)

#define OFF_OUT 0
#define OFF_NH  (BB * VOCAB_)
#define OFF_NC  (OFF_NH + BB * DECH_)
#define OFF_AW  (OFF_NC + BB * DECH_)
#define OUT_TOTAL (OFF_AW + BB * SS)

// scratch (no allocations allowed)
__device__ __align__(16) float g_decp[BB * ATTN_];
__device__ __align__(16) float g_scores[BB * SS];
__device__ __align__(16) float g_xbuf[BB * XKC];   // [emb|ctx|hidden]
__device__ __align__(16) float g_obuf[BB * OUTK];  // [nh|ctx|emb]
__device__ __align__(16) float g_gates[BB * G4];
__device__ __align__(16) __half g_wenc_h[ATTN_ * ENC2_];  // fp16 W_enc (1 MB)
__device__ __align__(16) float g_aux[BB * DECH_ * 2 + BB * SS];

// ---------------------------------------------------------------- helpers
#define MMA16816(c, a, b) \
    asm volatile("mma.sync.aligned.m16n8k16.row.col.f32.f16.f16.f32 " \
        "{%0,%1,%2,%3},{%4,%5,%6,%7},{%8,%9},{%0,%1,%2,%3};" \
        : "+f"(c[0]), "+f"(c[1]), "+f"(c[2]), "+f"(c[3]) \
        : "r"(a[0]), "r"(a[1]), "r"(a[2]), "r"(a[3]), "r"(b[0]), "r"(b[1]))

#define LDSM4(d0, d1, d2, d3, addr) \
    asm volatile("ldmatrix.sync.aligned.m8n8.x4.shared.b16 {%0,%1,%2,%3}, [%4];" \
        : "=r"(d0), "=r"(d1), "=r"(d2), "=r"(d3) : "r"(addr))

__device__ __forceinline__ uint32_t smem_u32(const void* p) {
    uint32_t a;
    asm("{ .reg .u64 t; cvta.to.shared.u64 t, %1; cvt.u32.u64 %0, t; }" : "=r"(a) : "l"(p));
    return a;
}

__device__ __forceinline__ void split4(float4 v, uint2& h, uint2& l)
{
    __half2 h01 = __floats2half2_rn(v.x, v.y);
    __half2 h23 = __floats2half2_rn(v.z, v.w);
    float2 f01 = __half22float2(h01);
    float2 f23 = __half22float2(h23);
    __half2 l01 = __floats2half2_rn(v.x - f01.x, v.y - f01.y);
    __half2 l23 = __floats2half2_rn(v.z - f23.x, v.w - f23.y);
    h.x = *(uint32_t*)&h01; h.y = *(uint32_t*)&h23;
    l.x = *(uint32_t*)&l01; l.y = *(uint32_t*)&l23;
}
__device__ __forceinline__ void hi4(float4 v, uint2& h)
{
    __half2 h01 = __floats2half2_rn(v.x, v.y);
    __half2 h23 = __floats2half2_rn(v.z, v.w);
    h.x = *(uint32_t*)&h01; h.y = *(uint32_t*)&h23;
}

// ================================================================ W_enc fp32->fp16
__global__ void __launch_bounds__(256)
cvt_wenc_k(const float* __restrict__ W)
{
    const int i = (blockIdx.x * 256 + threadIdx.x) * 4;   // grid covers 512*1024
    float4 v = *(const float4*)(W + i);
    uint2 h;
    hi4(v, h);
    *(uint2*)&g_wenc_h[i] = h;
}

// ================================================================ generic GEMM
// (dec_proj / gates) — BM=64, BN=128, BK=32, 256 thr.
#define BKK 32
#define LDK 40
#define STAGE_A  0
#define STAGE_AL 2560
#define STAGE_B  5120
#define STAGE_BL 10240
#define STAGE_SZ 15360
#define SMEM_BYTES (2 * STAGE_SZ * 2)  // 61440

template<int EPI, int ATOM, int NPROD>
__global__ void __launch_bounds__(256, 2)
gemm_k(const float* __restrict__ A, int lda,
       const float* __restrict__ B1, int ldb1, int ksplit,
       const float* __restrict__ B2, int ldb2,
       float* __restrict__ C, int N, int kslice,
       const float* __restrict__ bias,
       const float* __restrict__ decp,
       const float* __restrict__ vat)
{
    extern __shared__ __half sm[];
    const uint32_t sb0 = smem_u32(sm);

    const int tid = threadIdx.x;
    const int wid = tid >> 5, lane = tid & 31;
    const int g = lane >> 2, tig = lane & 3;
    const int wm = wid >> 2, wn = wid & 3;
    const int bm = blockIdx.y * 64, bn = blockIdx.x * 128;
    const int k0 = blockIdx.z * kslice;
    const int nk = kslice / BKK;

    const int lrow = tid >> 3;
    const int lkq  = tid & 7;
    const int rowsel = lane & 15;
    const int kcsel  = (lane >> 4) * 8;

    float4 pa0, pa1, pb[4];

    {
        const int gk = k0 + lkq * 4;
        pa0 = *(const float4*)(A + (size_t)(bm + lrow) * lda + gk);
        pa1 = *(const float4*)(A + (size_t)(bm + lrow + 32) * lda + gk);
        #pragma unroll
        for (int r = 0; r < 4; r++) {
            const int n = bn + lrow + r * 32;
            const float* Bp = (gk < ksplit)
                ? (B1 + (size_t)n * ldb1 + gk)
                : (B2 + (size_t)n * ldb2 + (gk - ksplit));
            pb[r] = *(const float4*)Bp;
        }
    }
    {
        __half* st = sm;
        uint2 h, l;
        if (NPROD >= 2) {
            split4(pa0, h, l);
            *(uint2*)&st[STAGE_A  + lrow * LDK + lkq * 4] = h;
            *(uint2*)&st[STAGE_AL + lrow * LDK + lkq * 4] = l;
            split4(pa1, h, l);
            *(uint2*)&st[STAGE_A  + (lrow + 32) * LDK + lkq * 4] = h;
            *(uint2*)&st[STAGE_AL + (lrow + 32) * LDK + lkq * 4] = l;
        } else {
            hi4(pa0, h);
            *(uint2*)&st[STAGE_A  + lrow * LDK + lkq * 4] = h;
            hi4(pa1, h);
            *(uint2*)&st[STAGE_A  + (lrow + 32) * LDK + lkq * 4] = h;
        }
        #pragma unroll
        for (int r = 0; r < 4; r++) {
            if (NPROD == 3) {
                split4(pb[r], h, l);
                *(uint2*)&st[STAGE_B  + (lrow + r * 32) * LDK + lkq * 4] = h;
                *(uint2*)&st[STAGE_BL + (lrow + r * 32) * LDK + lkq * 4] = l;
            } else {
                hi4(pb[r], h);
                *(uint2*)&st[STAGE_B  + (lrow + r * 32) * LDK + lkq * 4] = h;
            }
        }
    }
    __syncthreads();

    float acc[2][4][4];
    #pragma unroll
    for (int mt = 0; mt < 2; mt++)
        #pragma unroll
        for (int nt = 0; nt < 4; nt++)
            #pragma unroll
            for (int q = 0; q < 4; q++) acc[mt][nt][q] = 0.f;

    for (int kt = 0; kt < nk; kt++) {
        const uint32_t cu = sb0 + (uint32_t)(kt & 1) * (STAGE_SZ * 2);
        __half* nxt = sm + ((kt + 1) & 1) * STAGE_SZ;

        if (kt + 1 < nk) {
            const int gk = k0 + (kt + 1) * BKK + lkq * 4;
            pa0 = *(const float4*)(A + (size_t)(bm + lrow) * lda + gk);
            pa1 = *(const float4*)(A + (size_t)(bm + lrow + 32) * lda + gk);
            #pragma unroll
            for (int r = 0; r < 4; r++) {
                const int n = bn + lrow + r * 32;
                const float* Bp = (gk < ksplit)
                    ? (B1 + (size_t)n * ldb1 + gk)
                    : (B2 + (size_t)n * ldb2 + (gk - ksplit));
                pb[r] = *(const float4*)Bp;
            }
        }

        #pragma unroll
        for (int ks = 0; ks < 2; ks++) {
            const int ks16 = ks * 16;
            uint32_t ah[2][4], al[2][4], bh[4][2], bl[4][2];
            #pragma unroll
            for (int mt = 0; mt < 2; mt++) {
                const int r = wm * 32 + mt * 16;
                const uint32_t a_addr =
                    cu + 2u * (STAGE_A + (r + rowsel) * LDK + ks16 + kcsel);
                LDSM4(ah[mt][0], ah[mt][1], ah[mt][2], ah[mt][3], a_addr);
                if (NPROD >= 2) {
                    const uint32_t al_addr =
                        cu + 2u * (STAGE_AL + (r + rowsel) * LDK + ks16 + kcsel);
                    LDSM4(al[mt][0], al[mt][1], al[mt][2], al[mt][3], al_addr);
                }
            }
            {
                const uint32_t b_addr =
                    cu + 2u * (STAGE_B + (wn * 32 + lane) * LDK + ks16);
                LDSM4(bh[0][0], bh[1][0], bh[2][0], bh[3][0], b_addr);
                LDSM4(bh[0][1], bh[1][1], bh[2][1], bh[3][1], b_addr + 16);
                if (NPROD == 3) {
                    const uint32_t bl_addr =
                        cu + 2u * (STAGE_BL + (wn * 32 + lane) * LDK + ks16);
                    LDSM4(bl[0][0], bl[1][0], bl[2][0], bl[3][0], bl_addr);
                    LDSM4(bl[0][1], bl[1][1], bl[2][1], bl[3][1], bl_addr + 16);
                }
            }
            #pragma unroll
            for (int mt = 0; mt < 2; mt++)
                #pragma unroll
                for (int nt = 0; nt < 4; nt++) {
                    MMA16816(acc[mt][nt], ah[mt], bh[nt]);
                    if (NPROD == 3) MMA16816(acc[mt][nt], ah[mt], bl[nt]);
                    if (NPROD >= 2) MMA16816(acc[mt][nt], al[mt], bh[nt]);
                }
        }

        if (kt + 1 < nk) {
            uint2 h, l;
            if (NPROD >= 2) {
                split4(pa0, h, l);
                *(uint2*)&nxt[STAGE_A  + lrow * LDK + lkq * 4] = h;
                *(uint2*)&nxt[STAGE_AL + lrow * LDK + lkq * 4] = l;
                split4(pa1, h, l);
                *(uint2*)&nxt[STAGE_A  + (lrow + 32) * LDK + lkq * 4] = h;
                *(uint2*)&nxt[STAGE_AL + (lrow + 32) * LDK + lkq * 4] = l;
            } else {
                hi4(pa0, h);
                *(uint2*)&nxt[STAGE_A  + lrow * LDK + lkq * 4] = h;
                hi4(pa1, h);
                *(uint2*)&nxt[STAGE_A  + (lrow + 32) * LDK + lkq * 4] = h;
            }
            #pragma unroll
            for (int r = 0; r < 4; r++) {
                if (NPROD == 3) {
                    split4(pb[r], h, l);
                    *(uint2*)&nxt[STAGE_B  + (lrow + r * 32) * LDK + lkq * 4] = h;
                    *(uint2*)&nxt[STAGE_BL + (lrow + r * 32) * LDK + lkq * 4] = l;
                } else {
                    hi4(pb[r], h);
                    *(uint2*)&nxt[STAGE_B  + (lrow + r * 32) * LDK + lkq * 4] = h;
                }
            }
        }
        __syncthreads();
    }

    #pragma unroll
    for (int mt = 0; mt < 2; mt++) {
        const int gm = bm + wm * 32 + mt * 16 + g;
        #pragma unroll
        for (int nt = 0; nt < 4; nt++) {
            const int gn = bn + wn * 32 + nt * 8 + tig * 2;
            if (ATOM) {
                atomicAdd(C + (size_t)gm * N + gn,       acc[mt][nt][0]);
                atomicAdd(C + (size_t)gm * N + gn + 1,   acc[mt][nt][1]);
                atomicAdd(C + (size_t)(gm + 8) * N + gn,     acc[mt][nt][2]);
                atomicAdd(C + (size_t)(gm + 8) * N + gn + 1, acc[mt][nt][3]);
            } else {
                const float b0 = bias ? bias[gn] : 0.f;
                const float b1 = bias ? bias[gn + 1] : 0.f;
                *(float2*)(C + (size_t)gm * N + gn) =
                    make_float2(acc[mt][nt][0] + b0, acc[mt][nt][1] + b1);
                *(float2*)(C + (size_t)(gm + 8) * N + gn) =
                    make_float2(acc[mt][nt][2] + b0, acc[mt][nt][3] + b1);
            }
        }
    }
}

// ================================================================ out GEMM
// M=64 (fixed), BN=128, BK=32, nk=80, 1-product fp16, 2-deep register prefetch.
#define OSTG_A 0
#define OSTG_B 2560
#define OSTG_SZ 7680
#define OSMEM_BYTES (2 * OSTG_SZ * 2)   // 30720

#define OUT_LDG(it, s) do { \
    const int gk = (it) * BKK + lkq * 4; \
    a0[s] = *(const float4*)(A + (size_t)lrow * OUTK + gk); \
    a1[s] = *(const float4*)(A + (size_t)(lrow + 32) * OUTK + gk); \
    b4[s][0] = *(const float4*)(Bm + (size_t)(bn + lrow)      * OUTK + gk); \
    b4[s][1] = *(const float4*)(Bm + (size_t)(bn + lrow + 32) * OUTK + gk); \
    b4[s][2] = *(const float4*)(Bm + (size_t)(bn + lrow + 64) * OUTK + gk); \
    b4[s][3] = *(const float4*)(Bm + (size_t)(bn + lrow + 96) * OUTK + gk); \
} while (0)

#define OUT_STS(s, stg) do { \
    __half* st = sm + (stg) * OSTG_SZ; \
    uint2 h; \
    hi4(a0[s], h); *(uint2*)&st[OSTG_A + lrow * LDK + lkq * 4] = h; \
    hi4(a1[s], h); *(uint2*)&st[OSTG_A + (lrow + 32) * LDK + lkq * 4] = h; \
    hi4(b4[s][0], h); *(uint2*)&st[OSTG_B + lrow * LDK + lkq * 4] = h; \
    hi4(b4[s][1], h); *(uint2*)&st[OSTG_B + (lrow + 32) * LDK + lkq * 4] = h; \
    hi4(b4[s][2], h); *(uint2*)&st[OSTG_B + (lrow + 64) * LDK + lkq * 4] = h; \
    hi4(b4[s][3], h); *(uint2*)&st[OSTG_B + (lrow + 96) * LDK + lkq * 4] = h; \
} while (0)

#define OUT_MMA(stg) do { \
    const uint32_t cu = sb0 + (uint32_t)(stg) * (OSTG_SZ * 2); \
    _Pragma("unroll") \
    for (int ks = 0; ks < 2; ks++) { \
        const int ks16 = ks * 16; \
        uint32_t ah[2][4], bh[4][2]; \
        _Pragma("unroll") \
        for (int mt = 0; mt < 2; mt++) { \
            const int r = wm * 32 + mt * 16; \
            const uint32_t a_addr = \
                cu + 2u * (OSTG_A + (r + rowsel) * LDK + ks16 + kcsel); \
            LDSM4(ah[mt][0], ah[mt][1], ah[mt][2], ah[mt][3], a_addr); \
        } \
        { \
            const uint32_t b_addr = \
                cu + 2u * (OSTG_B + (wn * 32 + lane) * LDK + ks16); \
            LDSM4(bh[0][0], bh[1][0], bh[2][0], bh[3][0], b_addr); \
            LDSM4(bh[0][1], bh[1][1], bh[2][1], bh[3][1], b_addr + 16); \
        } \
        _Pragma("unroll") \
        for (int mt = 0; mt < 2; mt++) \
            _Pragma("unroll") \
            for (int nt = 0; nt < 4; nt++) \
                MMA16816(acc[mt][nt], ah[mt], bh[nt]); \
    } \
} while (0)

__global__ void __launch_bounds__(256, 2)
gemm_out_k(const float* __restrict__ A,      // obuf [64, 2560]
           const float* __restrict__ Bm,     // W_out [32000, 2560]
           float* __restrict__ C,            // out [64, 32000]
           const float* __restrict__ bias)
{
    extern __shared__ __half sm[];
    const uint32_t sb0 = smem_u32(sm);

    const int tid = threadIdx.x;
    const int wid = tid >> 5, lane = tid & 31;
    const int g = lane >> 2, tig = lane & 3;
    const int wm = wid >> 2, wn = wid & 3;
    const int bn = blockIdx.x * 128;
    const int nk = OUTK / BKK;   // 80

    const int lrow = tid >> 3, lkq = tid & 7;
    const int rowsel = lane & 15, kcsel = (lane >> 4) * 8;

    float4 a0[2], a1[2], b4[2][4];

    OUT_LDG(0, 0);
    OUT_STS(0, 0);
    OUT_LDG(1, 1);
    OUT_LDG(2, 0);
    __syncthreads();

    float acc[2][4][4];
    #pragma unroll
    for (int mt = 0; mt < 2; mt++)
        #pragma unroll
        for (int nt = 0; nt < 4; nt++)
            #pragma unroll
            for (int q = 0; q < 4; q++) acc[mt][nt][q] = 0.f;

    for (int kt = 0; kt < nk; kt += 2) {
        OUT_MMA(0);
        OUT_STS(1, 1);
        if (kt + 3 < nk) OUT_LDG(kt + 3, 1);
        __syncthreads();

        OUT_MMA(1);
        if (kt + 2 < nk) {
            OUT_STS(0, 0);
            if (kt + 4 < nk) OUT_LDG(kt + 4, 0);
        }
        __syncthreads();
    }

    #pragma unroll
    for (int mt = 0; mt < 2; mt++) {
        const int gm = wm * 32 + mt * 16 + g;
        #pragma unroll
        for (int nt = 0; nt < 4; nt++) {
            const int gn = bn + wn * 32 + nt * 8 + tig * 2;
            const float b0 = bias[gn];
            const float b1 = bias[gn + 1];
            *(float2*)(C + (size_t)gm * VOCAB_ + gn) =
                make_float2(acc[mt][nt][0] + b0, acc[mt][nt][1] + b1);
            *(float2*)(C + (size_t)(gm + 8) * VOCAB_ + gn) =
                make_float2(acc[mt][nt][2] + b0, acc[mt][nt][3] + b1);
        }
    }
}

// ================================================================ enc GEMM
// BM=128, BN=256, BK=32, 512 threads. B = pre-converted fp16 W_enc (direct copy).
#define ESTG_A 0
#define ESTG_B 5120
#define ESTG_SZ 15360
#define ESMEM_BYTES (2 * ESTG_SZ * 2)

__global__ void __launch_bounds__(512, 1)
gemm_enc_k(const float* __restrict__ A,        // enc_out [8192, 1024] fp32
           const __half* __restrict__ Bh16,    // W_enc fp16 [512, 1024]
           const float* __restrict__ decp,
           const float* __restrict__ vat)
{
    extern __shared__ __half sm[];
    const uint32_t sb0 = smem_u32(sm);

    const int tid = threadIdx.x;
    const int wid = tid >> 5, lane = tid & 31;
    const int g = lane >> 2, tig = lane & 3;
    const int wm = wid >> 2, wn = wid & 3;
    const int bm = blockIdx.y * 128, bn = blockIdx.x * 256;

    const int lrow = tid >> 3;   // 0..63
    const int lkq  = tid & 7;
    const int rowsel = lane & 15;
    const int kcsel  = (lane >> 4) * 8;

    const int nk = ENC2_ / BKK;  // 32

    float4 pa0, pa1;
    uint2 pbh[4];

    {
        const int gk = lkq * 4;
        pa0 = *(const float4*)(A + (size_t)(bm + lrow) * ENC2_ + gk);
        pa1 = *(const float4*)(A + (size_t)(bm + lrow + 64) * ENC2_ + gk);
        #pragma unroll
        for (int r = 0; r < 4; r++)
            pbh[r] = *(const uint2*)(Bh16 + (size_t)(bn + lrow + r * 64) * ENC2_ + gk);
    }
    {
        __half* st = sm;
        uint2 h;
        hi4(pa0, h); *(uint2*)&st[ESTG_A + lrow * LDK + lkq * 4] = h;
        hi4(pa1, h); *(uint2*)&st[ESTG_A + (lrow + 64) * LDK + lkq * 4] = h;
        #pragma unroll
        for (int r = 0; r < 4; r++)
            *(uint2*)&st[ESTG_B + (lrow + r * 64) * LDK + lkq * 4] = pbh[r];
    }
    __syncthreads();

    float acc[2][8][4];
    #pragma unroll
    for (int mt = 0; mt < 2; mt++)
        #pragma unroll
        for (int nt = 0; nt < 8; nt++)
            #pragma unroll
            for (int q = 0; q < 4; q++) acc[mt][nt][q] = 0.f;

    for (int kt = 0; kt < nk; kt++) {
        const uint32_t cu = sb0 + (uint32_t)(kt & 1) * (ESTG_SZ * 2);
        __half* nxt = sm + ((kt + 1) & 1) * ESTG_SZ;

        if (kt + 1 < nk) {
            const int gk = (kt + 1) * BKK + lkq * 4;
            pa0 = *(const float4*)(A + (size_t)(bm + lrow) * ENC2_ + gk);
            pa1 = *(const float4*)(A + (size_t)(bm + lrow + 64) * ENC2_ + gk);
            #pragma unroll
            for (int r = 0; r < 4; r++)
                pbh[r] = *(const uint2*)(Bh16 + (size_t)(bn + lrow + r * 64) * ENC2_ + gk);
        }

        #pragma unroll
        for (int ks = 0; ks < 2; ks++) {
            const int ks16 = ks * 16;
            uint32_t ah[2][4], bh[8][2];
            #pragma unroll
            for (int mt = 0; mt < 2; mt++) {
                const int r = wm * 32 + mt * 16;
                const uint32_t a_addr =
                    cu + 2u * (ESTG_A + (r + rowsel) * LDK + ks16 + kcsel);
                LDSM4(ah[mt][0], ah[mt][1], ah[mt][2], ah[mt][3], a_addr);
            }
            {
                const uint32_t b1a =
                    cu + 2u * (ESTG_B + (wn * 64 + lane) * LDK + ks16);
                LDSM4(bh[0][0], bh[1][0], bh[2][0], bh[3][0], b1a);
                LDSM4(bh[0][1], bh[1][1], bh[2][1], bh[3][1], b1a + 16);
                const uint32_t b2a =
                    cu + 2u * (ESTG_B + (wn * 64 + 32 + lane) * LDK + ks16);
                LDSM4(bh[4][0], bh[5][0], bh[6][0], bh[7][0], b2a);
                LDSM4(bh[4][1], bh[5][1], bh[6][1], bh[7][1], b2a + 16);
            }
            #pragma unroll
            for (int mt = 0; mt < 2; mt++)
                #pragma unroll
                for (int nt = 0; nt < 8; nt++)
                    MMA16816(acc[mt][nt], ah[mt], bh[nt]);
        }

        if (kt + 1 < nk) {
            uint2 h;
            hi4(pa0, h); *(uint2*)&nxt[ESTG_A + lrow * LDK + lkq * 4] = h;
            hi4(pa1, h); *(uint2*)&nxt[ESTG_A + (lrow + 64) * LDK + lkq * 4] = h;
            #pragma unroll
            for (int r = 0; r < 4; r++)
                *(uint2*)&nxt[ESTG_B + (lrow + r * 64) * LDK + lkq * 4] = pbh[r];
        }
        __syncthreads();
    }

    // score epilogue: row gm -> (b = gm&63, s = gm>>6); c2/c3 are row gm+8
    #pragma unroll
    for (int mt = 0; mt < 2; mt++) {
        const int gm = bm + wm * 32 + mt * 16 + g;
        const int bA = gm & 63;
        const int bBt = (gm + 8) & 63;
        float p0 = 0.f, p8 = 0.f;
        #pragma unroll
        for (int nt = 0; nt < 8; nt++) {
            const int gn = bn + wn * 64 + nt * 8 + tig * 2;
            const float d0a = decp[bA * ATTN_ + gn],  d1a = decp[bA * ATTN_ + gn + 1];
            const float d0b = decp[bBt * ATTN_ + gn], d1b = decp[bBt * ATTN_ + gn + 1];
            const float v0 = vat[gn], v1 = vat[gn + 1];
            p0 += tanhf(acc[mt][nt][0] + d0a) * v0 + tanhf(acc[mt][nt][1] + d1a) * v1;
            p8 += tanhf(acc[mt][nt][2] + d0b) * v0 + tanhf(acc[mt][nt][3] + d1b) * v1;
        }
        p0 += __shfl_xor_sync(0xffffffffu, p0, 1);
        p0 += __shfl_xor_sync(0xffffffffu, p0, 2);
        p8 += __shfl_xor_sync(0xffffffffu, p8, 1);
        p8 += __shfl_xor_sync(0xffffffffu, p8, 2);
        if (tig == 0) {
            atomicAdd(&g_scores[bA * SS + (gm >> 6)], p0);
            atomicAdd(&g_scores[bBt * SS + ((gm + 8) >> 6)], p8);
        }
    }
}

// ---------------------------------------------------------------- embed etc.
__global__ void __launch_bounds__(256)
embed_copy_k(const int* __restrict__ tok, const float* __restrict__ emb,
             const float* __restrict__ hidden)
{
    int b = blockIdx.x, tid = threadIdx.x;
    int t = tok[b];
    const float* src = emb + (size_t)t * EMB_;
    for (int j = tid; j < EMB_; j += 256) {
        float v = (t == 0) ? 0.f : src[j];
        g_xbuf[b * XKC + j] = v;
        g_obuf[b * OUTK + (DECH_ + ENC2_) + j] = v;
        g_decp[b * ATTN_ + j] = 0.f;
    }
    for (int j = tid; j < DECH_; j += 256) {
        g_xbuf[b * XKC + (EMB_ + ENC2_) + j] = hidden[b * DECH_ + j];
        g_xbuf[b * XKC + EMB_ + j] = 0.f;
    }
    for (int j = tid; j < G4; j += 256)
        g_gates[b * G4 + j] = 0.f;
    if (tid < SS) g_scores[b * SS + tid] = 0.f;
}

// softmax + partial context; grid (16, 64): x = half*8 + schunk; 128 threads.
__global__ void __launch_bounds__(128)
smctx_k(const int* __restrict__ mask, const float* __restrict__ enc_out,
        float* __restrict__ aw_dst)
{
    int b = blockIdx.y, half = blockIdx.x >> 3, sc = blockIdx.x & 7;
    int tid = threadIdx.x;
    int wid = tid >> 5, lane = tid & 31;
    __shared__ float w[SS];
    __shared__ float red[4];

    float val = (mask[b * SS + tid] == 0) ? -INFINITY : g_scores[b * SS + tid];
    float m = val;
    #pragma unroll
    for (int o = 16; o; o >>= 1) m = fmaxf(m, __shfl_xor_sync(0xffffffffu, m, o));
    if (lane == 0) red[wid] = m;
    __syncthreads();
    if (tid == 0) red[0] = fmaxf(fmaxf(red[0], red[1]), fmaxf(red[2], red[3]));
    __syncthreads();
    float mx = red[0];
    __syncthreads();

    float e = __expf(val - mx);
    float ssum = e;
    #pragma unroll
    for (int o = 16; o; o >>= 1) ssum += __shfl_xor_sync(0xffffffffu, ssum, o);
    if (lane == 0) red[wid] = ssum;
    __syncthreads();
    if (tid == 0) red[0] = red[0] + red[1] + red[2] + red[3];
    __syncthreads();
    float ww = e / red[0];
    w[tid] = ww;
    if (blockIdx.x == 0) aw_dst[b * SS + tid] = ww;
    __syncthreads();

    const int col = half * 512 + tid * 4;
    const float* base = enc_out + (size_t)b * ENC2_ + col;
    float4 a = make_float4(0.f, 0.f, 0.f, 0.f);
    const int s0 = sc * 16;
    #pragma unroll 8
    for (int s = s0; s < s0 + 16; s++) {
        float ws = w[s];
        float4 v = *(const float4*)(base + (size_t)s * BB * ENC2_);
        a.x = fmaf(ws, v.x, a.x); a.y = fmaf(ws, v.y, a.y);
        a.z = fmaf(ws, v.z, a.z); a.w = fmaf(ws, v.w, a.w);
    }
    float* dst = &g_xbuf[b * XKC + EMB_ + col];
    atomicAdd(dst + 0, a.x);
    atomicAdd(dst + 1, a.y);
    atomicAdd(dst + 2, a.z);
    atomicAdd(dst + 3, a.w);
}

// LSTM pointwise; also copies ctx g_xbuf -> g_obuf
__global__ void __launch_bounds__(1024)
lstm_k(const float* __restrict__ b_ih, const float* __restrict__ b_hh,
       const float* __restrict__ cell,
       float* __restrict__ nh_out, float* __restrict__ nc_out)
{
    int b = blockIdx.x, j = threadIdx.x;
    const float* gg = g_gates + (size_t)b * G4;
    float iv = gg[j]             + b_ih[j]             + b_hh[j];
    float fv = gg[j + DECH_]     + b_ih[j + DECH_]     + b_hh[j + DECH_];
    float gv = gg[j + 2 * DECH_] + b_ih[j + 2 * DECH_] + b_hh[j + 2 * DECH_];
    float ov = gg[j + 3 * DECH_] + b_ih[j + 3 * DECH_] + b_hh[j + 3 * DECH_];
    float i_ = 1.f / (1.f + __expf(-iv));
    float f_ = 1.f / (1.f + __expf(-fv));
    float o_ = 1.f / (1.f + __expf(-ov));
    float gt = tanhf(gv);
    float nc = f_ * cell[b * DECH_ + j] + i_ * gt;
    float nh = o_ * tanhf(nc);
    nc_out[b * DECH_ + j] = nc;
    nh_out[b * DECH_ + j] = nh;
    g_obuf[b * OUTK + j] = nh;
    g_obuf[b * OUTK + DECH_ + j] = g_xbuf[b * XKC + EMB_ + j];
}

// ---------------------------------------------------------------- launcher
extern "C" void kernel_launch(void* const* d_in, const int* in_sizes, int n_in,
                              void* d_out, int out_size)
{
    const int*   input_token = (const int*)  d_in[0];
    const float* hidden      = (const float*)d_in[1];
    const float* cell        = (const float*)d_in[2];
    const float* enc_out     = (const float*)d_in[3];
    const int*   mask        = (const int*)  d_in[4];
    const float* embedding   = (const float*)d_in[5];
    const float* W_enc       = (const float*)d_in[6];
    const float* W_dec       = (const float*)d_in[7];
    const float* v_attn      = (const float*)d_in[8];
    const float* W_ih        = (const float*)d_in[9];
    const float* W_hh        = (const float*)d_in[10];
    const float* b_ih        = (const float*)d_in[11];
    const float* b_hh        = (const float*)d_in[12];
    const float* W_out       = (const float*)d_in[13];
    const float* b_out       = (const float*)d_in[14];

    float* out = (float*)d_out;

    void *p_decp, *p_xbuf, *p_obuf, *p_gates, *p_wench, *p_aux;
    cudaGetSymbolAddress(&p_decp,  g_decp);
    cudaGetSymbolAddress(&p_xbuf,  g_xbuf);
    cudaGetSymbolAddress(&p_obuf,  g_obuf);
    cudaGetSymbolAddress(&p_gates, g_gates);
    cudaGetSymbolAddress(&p_wench, g_wenc_h);
    cudaGetSymbolAddress(&p_aux,   g_aux);

    cudaFuncSetAttribute(gemm_k<0,1,2>, cudaFuncAttributeMaxDynamicSharedMemorySize, SMEM_BYTES);
    cudaFuncSetAttribute(gemm_enc_k, cudaFuncAttributeMaxDynamicSharedMemorySize, ESMEM_BYTES);
    cudaFuncSetAttribute(gemm_out_k, cudaFuncAttributeMaxDynamicSharedMemorySize, OSMEM_BYTES);

    bool full = (out_size >= OUT_TOTAL);
    float* nh_dst = full ? out + OFF_NH : (float*)p_aux;
    float* nc_dst = full ? out + OFF_NC : (float*)p_aux + BB * DECH_;
    float* aw_dst = full ? out + OFF_AW : (float*)p_aux + 2 * BB * DECH_;

    // 0) W_enc fp32 -> fp16 (bit-identical to in-GEMM truncation)
    cvt_wenc_k<<<(ATTN_ * ENC2_) / 1024, 256>>>(W_enc);

    // 1) embedding + hidden copy + zero scores/ctx/decp/gates
    embed_copy_k<<<BB, 256>>>(input_token, embedding, hidden);

    // 2) dec_proj[64,512] = hidden @ W_dec^T (split-K x8, atomic, 2-product)
    gemm_k<0,1,2><<<dim3(ATTN_ / 128, 1, 8), 256, SMEM_BYTES>>>(
        hidden, DECH_, W_dec, DECH_, DECH_, W_dec, DECH_,
        (float*)p_decp, ATTN_, DECH_ / 8, nullptr, nullptr, nullptr);

    // 3) enc_proj GEMM + fused score reduction (big-tile, fp16 B)
    gemm_enc_k<<<dim3(ATTN_ / 256, (SS * BB) / 128), 512, ESMEM_BYTES>>>(
        enc_out, (const __half*)p_wench, (const float*)p_decp, v_attn);

    // 4) softmax + context (s-split x8, col-half x2)
    smctx_k<<<dim3(16, BB), 128>>>(mask, enc_out, aw_dst);

    // 5) gates = [emb|ctx]@W_ih^T + hidden@W_hh^T (split-K x4, 2-product)
    gemm_k<0,1,2><<<dim3(G4 / 128, 1, 4), 256, SMEM_BYTES>>>(
        (const float*)p_xbuf, XKC, W_ih, EMB_ + ENC2_, EMB_ + ENC2_, W_hh, DECH_,
        (float*)p_gates, G4, XKC / 4, nullptr, nullptr, nullptr);

    // 6) LSTM pointwise + ctx copy
    lstm_k<<<BB, DECH_>>>(b_ih, b_hh, cell, nh_dst, nc_dst);

    // 7) output = [nh|ctx|emb] @ W_out^T + b_out (1-product, 2-deep prefetch)
    gemm_out_k<<<dim3(VOCAB_ / 128), 256, OSMEM_BYTES>>>(
        (const float*)p_obuf, W_out, out + OFF_OUT, b_out);
}